// round 1
// baseline (speedup 1.0000x reference)
#include <cuda_runtime.h>
#include <math.h>

#define NN 50000
#define EE 800000
#define HH 256
#define FF 128
#define RR 32
#define KTOT 288   // 128 (xf[i]) + 128 (xf[j]) + 32 (rbf, rtm folded)

// ---------------- persistent device scratch (no runtime alloc allowed) ----------
__device__ float g_xf[NN * FF];      // LN(node_to_message(x))
__device__ float g_agg[NN * FF];     // segment-sum accumulator
__device__ float g_Wc[KTOT * FF];    // combined GEMM1 weight, [k][f]
__device__ float g_b1f[FF];          // folded GEMM1 bias
__device__ float g_l2t[FF * FF];     // l2_w transposed, [k][f]

// ---------------- prep: fold rtm into l1, transpose l2 --------------------------
__global__ void prep_kernel(const float* __restrict__ l1_w, const float* __restrict__ l1_b,
                            const float* __restrict__ rtm_w, const float* __restrict__ rtm_b,
                            const float* __restrict__ l2_w) {
    int f = blockIdx.x;      // 128 blocks
    int t = threadIdx.x;     // 128 threads
    // rows 0..255 of Wc: plain transpose of l1_w[:, 0:256]
    for (int k = t; k < 256; k += 128)
        g_Wc[k * FF + f] = l1_w[f * 384 + k];
    // rows 256..287: Wr[f][r] = sum_c l1_w[f][256+c] * rtm_w[c][r]
    if (t < RR) {
        float s = 0.f;
        for (int c = 0; c < FF; ++c)
            s += l1_w[f * 384 + 256 + c] * rtm_w[c * RR + t];
        g_Wc[(256 + t) * FF + f] = s;
    } else if (t == RR) {
        float s = l1_b[f];
        for (int c = 0; c < FF; ++c)
            s += l1_w[f * 384 + 256 + c] * rtm_b[c];
        g_b1f[f] = s;
    }
    // l2t[k][f] = l2_w[f][k]
    g_l2t[t * FF + f] = l2_w[f * FF + t];
}

// ---------------- zero the aggregation buffer ------------------------------------
__global__ void zero_agg_kernel() {
    float4 z = make_float4(0.f, 0.f, 0.f, 0.f);
    float4* p = (float4*)g_agg;
    int total = NN * FF / 4;
    for (int i = blockIdx.x * blockDim.x + threadIdx.x; i < total; i += gridDim.x * blockDim.x)
        p[i] = z;
}

// ---------------- node kernel: xf = LN(x @ ntm_w^T + ntm_b) ----------------------
#define A_TN 64
#define A_PX 260
#define A_PW 132

__global__ __launch_bounds__(256, 1)
void node_kernel(const float* __restrict__ x,
                 const float* __restrict__ ntm_w, const float* __restrict__ ntm_b,
                 const float* __restrict__ norm_g, const float* __restrict__ norm_b) {
    extern __shared__ float sm[];
    float* xs = sm;                      // 64 x 260
    float* Ws = sm + A_TN * A_PX;        // 256 x 132 (transposed weight [h][f])
    int tid = threadIdx.x;
    int tx = tid & 15, ty = tid >> 4;    // tx: f-groups, ty: node-groups
    int n0 = blockIdx.x * A_TN;

    float4* xs4 = (float4*)xs;
    const float4* x4 = (const float4*)x;
    for (int idx = tid; idx < A_TN * 64; idx += 256) {
        int nl = idx >> 6, q = idx & 63;
        int n = n0 + nl;
        xs4[nl * 65 + q] = (n < NN) ? x4[n * 64 + q] : make_float4(0.f, 0.f, 0.f, 0.f);
    }
    for (int idx = tid; idx < FF * HH; idx += 256) {
        int f = idx >> 8, h = idx & 255;
        Ws[h * A_PW + f] = ntm_w[idx];
    }
    float bb[8], gg[8], be[8];
#pragma unroll
    for (int c = 0; c < 8; ++c) {
        int f = tx * 8 + c;
        bb[c] = ntm_b[f]; gg[c] = norm_g[f]; be[c] = norm_b[f];
    }
    __syncthreads();

    float acc[4][8];
#pragma unroll
    for (int r = 0; r < 4; ++r)
#pragma unroll
        for (int c = 0; c < 8; ++c) acc[r][c] = bb[c];

    const float4* Ws4 = (const float4*)Ws;
    for (int k = 0; k < HH; ++k) {
        float a[4];
#pragma unroll
        for (int r = 0; r < 4; ++r) a[r] = xs[(ty * 4 + r) * A_PX + k];
        float4 w0 = Ws4[k * 33 + tx * 2];
        float4 w1 = Ws4[k * 33 + tx * 2 + 1];
        float w[8] = {w0.x, w0.y, w0.z, w0.w, w1.x, w1.y, w1.z, w1.w};
#pragma unroll
        for (int r = 0; r < 4; ++r)
#pragma unroll
            for (int c = 0; c < 8; ++c) acc[r][c] = fmaf(a[r], w[c], acc[r][c]);
    }

#pragma unroll
    for (int r = 0; r < 4; ++r) {
        float s = 0.f;
#pragma unroll
        for (int c = 0; c < 8; ++c) s += acc[r][c];
#pragma unroll
        for (int m = 1; m < 16; m <<= 1) s += __shfl_xor_sync(0xffffffffu, s, m);
        float mu = s * (1.f / FF);
        float v = 0.f;
#pragma unroll
        for (int c = 0; c < 8; ++c) { float d = acc[r][c] - mu; v += d * d; }
#pragma unroll
        for (int m = 1; m < 16; m <<= 1) v += __shfl_xor_sync(0xffffffffu, v, m);
        float inv = rsqrtf(v * (1.f / FF) + 1e-5f);
        int n = n0 + ty * 4 + r;
        if (n < NN) {
            float o[8];
#pragma unroll
            for (int c = 0; c < 8; ++c) o[c] = (acc[r][c] - mu) * inv * gg[c] + be[c];
            float4* dst = (float4*)&g_xf[n * FF + tx * 8];
            dst[0] = make_float4(o[0], o[1], o[2], o[3]);
            dst[1] = make_float4(o[4], o[5], o[6], o[7]);
        }
    }
}

// ---------------- fused edge kernel ----------------------------------------------
#define E_TE 128
#define E_PA 292
#define E_PG 132
#define E_KC 32

__global__ __launch_bounds__(256, 1)
void edge_kernel(const float* __restrict__ rbf, const int* __restrict__ edge_index,
                 const float* __restrict__ ln_g, const float* __restrict__ ln_b,
                 const float* __restrict__ l2_b) {
    extern __shared__ float sm[];
    float* As = sm;                      // 128 x 292 (A tile, then reused for G)
    float* Wb = sm + E_TE * E_PA;        // 32 x 128 streamed weight chunk
    __shared__ int ii[E_TE], jj[E_TE];
    int tid = threadIdx.x;
    int tx = tid & 15, ty = tid >> 4;
    int e0 = blockIdx.x * E_TE;          // E divisible by 128

    if (tid < E_TE) ii[tid] = edge_index[e0 + tid];
    else            jj[tid - E_TE] = edge_index[EE + e0 + (tid - E_TE)];
    __syncthreads();

    // gather A = [xf[i] | xf[j] | rbf]
    float4* As4 = (float4*)As;
    const float4* xf4 = (const float4*)g_xf;
    const float4* rbf4 = (const float4*)rbf;
    for (int idx = tid; idx < E_TE * 32; idx += 256) {
        int e = idx >> 5, q = idx & 31;
        As4[e * 73 + q] = xf4[ii[e] * 32 + q];
    }
    for (int idx = tid; idx < E_TE * 32; idx += 256) {
        int e = idx >> 5, q = idx & 31;
        As4[e * 73 + 32 + q] = xf4[jj[e] * 32 + q];
    }
    for (int idx = tid; idx < E_TE * 8; idx += 256) {
        int e = idx >> 3, q = idx & 7;
        As4[e * 73 + 64 + q] = rbf4[(e0 + e) * 8 + q];
    }

    float b1r[8], lg[8], lb[8], l2br[8];
#pragma unroll
    for (int c = 0; c < 8; ++c) {
        int f = tx * 8 + c;
        b1r[c] = g_b1f[f]; lg[c] = ln_g[f]; lb[c] = ln_b[f]; l2br[c] = l2_b[f];
    }

    float acc[8][8];
#pragma unroll
    for (int r = 0; r < 8; ++r)
#pragma unroll
        for (int c = 0; c < 8; ++c) acc[r][c] = b1r[c];

    // GEMM1: [128e x 288] @ [288 x 128f], weight streamed in 32-k chunks
    float4* Wb4 = (float4*)Wb;
    for (int kc = 0; kc < KTOT; kc += E_KC) {
        __syncthreads();
        for (int idx = tid; idx < E_KC * 32; idx += 256)
            Wb4[idx] = ((const float4*)g_Wc)[kc * 32 + idx];
        __syncthreads();
        for (int kk = 0; kk < E_KC; ++kk) {
            int k = kc + kk;
            float a[8];
#pragma unroll
            for (int r = 0; r < 8; ++r) a[r] = As[(ty * 8 + r) * E_PA + k];
            float4 w0 = Wb4[kk * 32 + tx * 2];
            float4 w1 = Wb4[kk * 32 + tx * 2 + 1];
            float w[8] = {w0.x, w0.y, w0.z, w0.w, w1.x, w1.y, w1.z, w1.w};
#pragma unroll
            for (int r = 0; r < 8; ++r)
#pragma unroll
                for (int c = 0; c < 8; ++c) acc[r][c] = fmaf(a[r], w[c], acc[r][c]);
        }
    }

    // LayerNorm (per edge over 128 features) + exact GELU
#pragma unroll
    for (int r = 0; r < 8; ++r) {
        float s = 0.f;
#pragma unroll
        for (int c = 0; c < 8; ++c) s += acc[r][c];
#pragma unroll
        for (int m = 1; m < 16; m <<= 1) s += __shfl_xor_sync(0xffffffffu, s, m);
        float mu = s * (1.f / FF);
        float v = 0.f;
#pragma unroll
        for (int c = 0; c < 8; ++c) { float d = acc[r][c] - mu; v += d * d; }
#pragma unroll
        for (int m = 1; m < 16; m <<= 1) v += __shfl_xor_sync(0xffffffffu, v, m);
        float inv = rsqrtf(v * (1.f / FF) + 1e-5f);
#pragma unroll
        for (int c = 0; c < 8; ++c) {
            float h = (acc[r][c] - mu) * inv * lg[c] + lb[c];
            acc[r][c] = h * normcdff(h);       // exact gelu: x * Phi(x)
        }
    }

    __syncthreads();     // all threads finished reading As
    float* Gs = As;      // reuse As region for GELU output [128 x 132]
#pragma unroll
    for (int r = 0; r < 8; ++r) {
        float4* dst = (float4*)&Gs[(ty * 8 + r) * E_PG + tx * 8];
        dst[0] = make_float4(acc[r][0], acc[r][1], acc[r][2], acc[r][3]);
        dst[1] = make_float4(acc[r][4], acc[r][5], acc[r][6], acc[r][7]);
    }

    // GEMM2: [128e x 128] @ [128 x 128f]
    float acc2[8][8];
#pragma unroll
    for (int r = 0; r < 8; ++r)
#pragma unroll
        for (int c = 0; c < 8; ++c) acc2[r][c] = 0.f;

    for (int kc = 0; kc < FF; kc += E_KC) {
        __syncthreads();
        for (int idx = tid; idx < E_KC * 32; idx += 256)
            Wb4[idx] = ((const float4*)g_l2t)[kc * 32 + idx];
        __syncthreads();
        for (int kk = 0; kk < E_KC; ++kk) {
            int k = kc + kk;
            float a[8];
#pragma unroll
            for (int r = 0; r < 8; ++r) a[r] = Gs[(ty * 8 + r) * E_PG + k];
            float4 w0 = Wb4[kk * 32 + tx * 2];
            float4 w1 = Wb4[kk * 32 + tx * 2 + 1];
            float w[8] = {w0.x, w0.y, w0.z, w0.w, w1.x, w1.y, w1.z, w1.w};
#pragma unroll
            for (int r = 0; r < 8; ++r)
#pragma unroll
                for (int c = 0; c < 8; ++c) acc2[r][c] = fmaf(a[r], w[c], acc2[r][c]);
        }
    }

    // scatter-add into agg[j] with vector atomics (sm_90+)
#pragma unroll
    for (int r = 0; r < 8; ++r) {
        int node = jj[ty * 8 + r];
        float4 v0 = make_float4(acc2[r][0] + l2br[0], acc2[r][1] + l2br[1],
                                acc2[r][2] + l2br[2], acc2[r][3] + l2br[3]);
        float4 v1 = make_float4(acc2[r][4] + l2br[4], acc2[r][5] + l2br[5],
                                acc2[r][6] + l2br[6], acc2[r][7] + l2br[7]);
        atomicAdd((float4*)&g_agg[node * FF + tx * 8], v0);
        atomicAdd((float4*)&g_agg[node * FF + tx * 8 + 4], v1);
    }
}

// ---------------- output kernel: out = agg @ mtn_w^T ------------------------------
#define C_TN 64
#define C_PA 132
#define C_PW 260

__global__ __launch_bounds__(256, 1)
void out_kernel(const float* __restrict__ mtn_w, float* __restrict__ out) {
    extern __shared__ float sm[];
    float* aggs = sm;                    // 64 x 132
    float* Wt = sm + C_TN * C_PA;        // 128 x 260 (transposed [f][h])
    int tid = threadIdx.x;
    int tx = tid & 31, ty = tid >> 5;
    int n0 = blockIdx.x * C_TN;

    float4* ag4 = (float4*)aggs;
    const float4* g4 = (const float4*)g_agg;
    for (int idx = tid; idx < C_TN * 32; idx += 256) {
        int nl = idx >> 5, q = idx & 31;
        int n = n0 + nl;
        ag4[nl * 33 + q] = (n < NN) ? g4[n * 32 + q] : make_float4(0.f, 0.f, 0.f, 0.f);
    }
    for (int idx = tid; idx < HH * FF; idx += 256) {
        int h = idx >> 7, f = idx & 127;
        Wt[f * C_PW + h] = mtn_w[idx];
    }
    __syncthreads();

    float acc[8][8];
#pragma unroll
    for (int r = 0; r < 8; ++r)
#pragma unroll
        for (int c = 0; c < 8; ++c) acc[r][c] = 0.f;

    const float4* Wt4 = (const float4*)Wt;
    for (int k = 0; k < FF; ++k) {
        float a[8];
#pragma unroll
        for (int r = 0; r < 8; ++r) a[r] = aggs[(ty * 8 + r) * C_PA + k];
        float4 w0 = Wt4[k * 65 + tx * 2];
        float4 w1 = Wt4[k * 65 + tx * 2 + 1];
        float w[8] = {w0.x, w0.y, w0.z, w0.w, w1.x, w1.y, w1.z, w1.w};
#pragma unroll
        for (int r = 0; r < 8; ++r)
#pragma unroll
            for (int c = 0; c < 8; ++c) acc[r][c] = fmaf(a[r], w[c], acc[r][c]);
    }

#pragma unroll
    for (int r = 0; r < 8; ++r) {
        int n = n0 + ty * 8 + r;
        if (n < NN) {
            float4* dst = (float4*)&out[n * HH + tx * 8];
            dst[0] = make_float4(acc[r][0], acc[r][1], acc[r][2], acc[r][3]);
            dst[1] = make_float4(acc[r][4], acc[r][5], acc[r][6], acc[r][7]);
        }
    }
}

// ---------------- launch ----------------------------------------------------------
extern "C" void kernel_launch(void* const* d_in, const int* in_sizes, int n_in,
                              void* d_out, int out_size) {
    const float* x      = (const float*)d_in[0];
    const float* rbf    = (const float*)d_in[1];
    const int*   eidx   = (const int*)d_in[2];
    const float* ntm_w  = (const float*)d_in[3];
    const float* ntm_b  = (const float*)d_in[4];
    const float* rtm_w  = (const float*)d_in[5];
    const float* rtm_b  = (const float*)d_in[6];
    const float* norm_g = (const float*)d_in[7];
    const float* norm_b = (const float*)d_in[8];
    const float* l1_w   = (const float*)d_in[9];
    const float* l1_b   = (const float*)d_in[10];
    const float* ln_g   = (const float*)d_in[11];
    const float* ln_b   = (const float*)d_in[12];
    const float* l2_w   = (const float*)d_in[13];
    const float* l2_b   = (const float*)d_in[14];
    const float* mtn_w  = (const float*)d_in[15];
    float* out = (float*)d_out;

    cudaFuncSetAttribute(node_kernel, cudaFuncAttributeMaxDynamicSharedMemorySize, 201728);
    cudaFuncSetAttribute(edge_kernel, cudaFuncAttributeMaxDynamicSharedMemorySize, 165888);
    cudaFuncSetAttribute(out_kernel,  cudaFuncAttributeMaxDynamicSharedMemorySize, 166912);

    zero_agg_kernel<<<2048, 256>>>();
    prep_kernel<<<FF, 128>>>(l1_w, l1_b, rtm_w, rtm_b, l2_w);
    node_kernel<<<(NN + A_TN - 1) / A_TN, 256, 201728>>>(x, ntm_w, ntm_b, norm_g, norm_b);
    edge_kernel<<<EE / E_TE, 256, 165888>>>(rbf, eidx, ln_g, ln_b, l2_b);
    out_kernel<<<(NN + C_TN - 1) / C_TN, 256, 166912>>>(mtn_w, out);
}

// round 3
// speedup vs baseline: 1.8246x; 1.8246x over previous
#include <cuda_runtime.h>
#include <math.h>

#define NN 50000
#define EE 800000
#define HH 256
#define FF 128
#define RR 32

// ---------------- persistent device scratch ----------------
__device__ float g_xf[NN * FF];        // LN(node_to_message(x))
__device__ float g_PQ[NN * 256];       // per-node P (0:128) and Q (128:256)
__device__ float g_agg[NN * FF];       // segment-sum accumulator
__device__ float g_Wpq[FF * 256];      // [k][f'] f'<128: l1a, f'>=128: l1b   (k=0..127)
__device__ float g_Wr[RR * FF];        // folded rbf weight [r][f]
__device__ float g_b1f[FF];            // folded GEMM1 bias
__device__ float g_l2t[FF * FF];       // l2_w transposed [k][f]

// ---------------- prep: fold rtm into l1, build transposed weights ----------------
__global__ void prep_kernel(const float* __restrict__ l1_w, const float* __restrict__ l1_b,
                            const float* __restrict__ rtm_w, const float* __restrict__ rtm_b,
                            const float* __restrict__ l2_w) {
    int f = blockIdx.x;      // 128
    int t = threadIdx.x;     // 128 (k index)
    g_Wpq[t * 256 + f]       = l1_w[f * 384 + t];
    g_Wpq[t * 256 + 128 + f] = l1_w[f * 384 + 128 + t];
    if (t < RR) {
        float s = 0.f;
        for (int c = 0; c < FF; ++c)
            s += l1_w[f * 384 + 256 + c] * rtm_w[c * RR + t];
        g_Wr[t * FF + f] = s;
    } else if (t == RR) {
        float s = l1_b[f];
        for (int c = 0; c < FF; ++c)
            s += l1_w[f * 384 + 256 + c] * rtm_b[c];
        g_b1f[f] = s;
    }
    g_l2t[t * FF + f] = l2_w[f * FF + t];
}

// ---------------- zero the aggregation buffer ----------------
__global__ void zero_agg_kernel() {
    float4 z = make_float4(0.f, 0.f, 0.f, 0.f);
    float4* p = (float4*)g_agg;
    int total = NN * FF / 4;
    for (int i = blockIdx.x * blockDim.x + threadIdx.x; i < total; i += gridDim.x * blockDim.x)
        p[i] = z;
}

// ---------------- node kernel: xf = LN(x @ ntm_w^T + ntm_b) ----------------
#define A_TN 64
#define A_PX 260
#define A_PW 132

__global__ __launch_bounds__(256, 1)
void node_kernel(const float* __restrict__ x,
                 const float* __restrict__ ntm_w, const float* __restrict__ ntm_b,
                 const float* __restrict__ norm_g, const float* __restrict__ norm_b) {
    extern __shared__ float sm[];
    float* xs = sm;                      // 64 x 260
    float* Ws = sm + A_TN * A_PX;        // 256 x 132
    int tid = threadIdx.x;
    int tx = tid & 15, ty = tid >> 4;
    int n0 = blockIdx.x * A_TN;

    float4* xs4 = (float4*)xs;
    const float4* x4 = (const float4*)x;
    for (int idx = tid; idx < A_TN * 64; idx += 256) {
        int nl = idx >> 6, q = idx & 63;
        int n = n0 + nl;
        xs4[nl * 65 + q] = (n < NN) ? x4[n * 64 + q] : make_float4(0.f, 0.f, 0.f, 0.f);
    }
    for (int idx = tid; idx < FF * HH; idx += 256) {
        int f = idx >> 8, h = idx & 255;
        Ws[h * A_PW + f] = ntm_w[idx];
    }
    float bb[8], gg[8], be[8];
#pragma unroll
    for (int c = 0; c < 8; ++c) {
        int f = tx * 8 + c;
        bb[c] = ntm_b[f]; gg[c] = norm_g[f]; be[c] = norm_b[f];
    }
    __syncthreads();

    float acc[4][8];
#pragma unroll
    for (int r = 0; r < 4; ++r)
#pragma unroll
        for (int c = 0; c < 8; ++c) acc[r][c] = bb[c];

    const float4* Ws4 = (const float4*)Ws;
    for (int k = 0; k < HH; ++k) {
        float a[4];
#pragma unroll
        for (int r = 0; r < 4; ++r) a[r] = xs[(ty * 4 + r) * A_PX + k];
        float4 w0 = Ws4[k * 33 + tx * 2];
        float4 w1 = Ws4[k * 33 + tx * 2 + 1];
        float w[8] = {w0.x, w0.y, w0.z, w0.w, w1.x, w1.y, w1.z, w1.w};
#pragma unroll
        for (int r = 0; r < 4; ++r)
#pragma unroll
            for (int c = 0; c < 8; ++c) acc[r][c] = fmaf(a[r], w[c], acc[r][c]);
    }

#pragma unroll
    for (int r = 0; r < 4; ++r) {
        float s = 0.f;
#pragma unroll
        for (int c = 0; c < 8; ++c) s += acc[r][c];
#pragma unroll
        for (int m = 1; m < 16; m <<= 1) s += __shfl_xor_sync(0xffffffffu, s, m);
        float mu = s * (1.f / FF);
        float v = 0.f;
#pragma unroll
        for (int c = 0; c < 8; ++c) { float d = acc[r][c] - mu; v += d * d; }
#pragma unroll
        for (int m = 1; m < 16; m <<= 1) v += __shfl_xor_sync(0xffffffffu, v, m);
        float inv = rsqrtf(v * (1.f / FF) + 1e-5f);
        int n = n0 + ty * 4 + r;
        if (n < NN) {
            float o[8];
#pragma unroll
            for (int c = 0; c < 8; ++c) o[c] = (acc[r][c] - mu) * inv * gg[c] + be[c];
            float4* dst = (float4*)&g_xf[n * FF + tx * 8];
            dst[0] = make_float4(o[0], o[1], o[2], o[3]);
            dst[1] = make_float4(o[4], o[5], o[6], o[7]);
        }
    }
}

// ---------------- pq kernel: PQ = xf @ [W1a | W1b] (per-node halves of GEMM1) -----
#define P_TN 128
#define P_PX 132

__global__ __launch_bounds__(512, 1)
void pq_kernel() {
    extern __shared__ float sm[];
    float* ts = sm;                      // 128 x 132
    float* Wp = sm + P_TN * P_PX;        // 128 x 256  (K=FF rows)
    int tid = threadIdx.x;
    int tx = tid & 31, ty = tid >> 5;    // tx: 32 f'-groups of 8, ty: 16 node-groups of 8
    int n0 = blockIdx.x * P_TN;

    float4* ts4 = (float4*)ts;
    const float4* xf4 = (const float4*)g_xf;
    for (int idx = tid; idx < P_TN * 32; idx += 512) {
        int nl = idx >> 5, q = idx & 31;
        int n = n0 + nl;
        ts4[nl * 33 + q] = (n < NN) ? xf4[n * 32 + q] : make_float4(0.f, 0.f, 0.f, 0.f);
    }
    float4* Wp4 = (float4*)Wp;
    const float4* gW4 = (const float4*)g_Wpq;
    for (int idx = tid; idx < FF * 256 / 4; idx += 512)   // FIXED: FF rows, not HH
        Wp4[idx] = gW4[idx];
    __syncthreads();

    float acc[8][8];
#pragma unroll
    for (int r = 0; r < 8; ++r)
#pragma unroll
        for (int c = 0; c < 8; ++c) acc[r][c] = 0.f;

    for (int k = 0; k < FF; ++k) {
        float a[8];
#pragma unroll
        for (int r = 0; r < 8; ++r) a[r] = ts[(ty * 8 + r) * P_PX + k];
        float4 w0 = Wp4[k * 64 + tx * 2];
        float4 w1 = Wp4[k * 64 + tx * 2 + 1];
        float w[8] = {w0.x, w0.y, w0.z, w0.w, w1.x, w1.y, w1.z, w1.w};
#pragma unroll
        for (int r = 0; r < 8; ++r)
#pragma unroll
            for (int c = 0; c < 8; ++c) acc[r][c] = fmaf(a[r], w[c], acc[r][c]);
    }

#pragma unroll
    for (int r = 0; r < 8; ++r) {
        int n = n0 + ty * 8 + r;
        if (n < NN) {
            float4* dst = (float4*)&g_PQ[n * 256 + tx * 8];
            dst[0] = make_float4(acc[r][0], acc[r][1], acc[r][2], acc[r][3]);
            dst[1] = make_float4(acc[r][4], acc[r][5], acc[r][6], acc[r][7]);
        }
    }
}

// ---------------- fused edge kernel ----------------
// h = P[i] + Q[j] + rbf@Wr^T + b1f ; LN ; GELU ; GEMM2 ; atomic scatter to agg[j]
#define E_TE 128
#define E_PA 132
#define E_PR 36
#define E_KC 32

__global__ __launch_bounds__(512, 1)
void edge_kernel(const float* __restrict__ rbf, const int* __restrict__ edge_index,
                 const float* __restrict__ ln_g, const float* __restrict__ ln_b,
                 const float* __restrict__ l2_b) {
    extern __shared__ float sm[];
    float* As   = sm;                              // 128 x 132 (P+Q staging, reused as G)
    float* rbfs = As + E_TE * E_PA;                // 128 x 36
    float* Wr   = rbfs + E_TE * E_PR;              // 32 x 128
    float* Wb   = Wr + RR * FF;                    // 32 x 128 streamed l2 chunk
    __shared__ int ii[E_TE], jj[E_TE];
    int tid = threadIdx.x;
    int tx = tid & 15, ty = tid >> 4;              // tx: 16 f-groups of 8, ty: 32 e-groups of 4
    int e0 = blockIdx.x * E_TE;

    if (tid < E_TE) ii[tid] = edge_index[e0 + tid];
    else if (tid < 2 * E_TE) jj[tid - E_TE] = edge_index[EE + e0 + (tid - E_TE)];
    __syncthreads();

    // gather As[e][f] = P[i[e]][f] + Q[j[e]][f]
    float4* As4 = (float4*)As;
    const float4* pq4 = (const float4*)g_PQ;
    for (int idx = tid; idx < E_TE * 32; idx += 512) {
        int e = idx >> 5, q = idx & 31;
        float4 p = pq4[ii[e] * 64 + q];
        float4 qv = pq4[jj[e] * 64 + 32 + q];
        As4[e * 33 + q] = make_float4(p.x + qv.x, p.y + qv.y, p.z + qv.z, p.w + qv.w);
    }
    // rbf tile
    float4* rbfs4 = (float4*)rbfs;
    const float4* rbf4 = (const float4*)rbf;
    for (int idx = tid; idx < E_TE * 8; idx += 512) {
        int e = idx >> 3, q = idx & 7;
        rbfs4[e * 9 + q] = rbf4[(e0 + e) * 8 + q];
    }
    // Wr resident
    float4* Wr4 = (float4*)Wr;
    const float4* gWr4 = (const float4*)g_Wr;
    for (int idx = tid; idx < RR * FF / 4; idx += 512)
        Wr4[idx] = gWr4[idx];

    float b1r[8], lg[8], lb[8], l2br[8];
#pragma unroll
    for (int c = 0; c < 8; ++c) {
        int f = tx * 8 + c;
        b1r[c] = g_b1f[f]; lg[c] = ln_g[f]; lb[c] = ln_b[f]; l2br[c] = l2_b[f];
    }
    __syncthreads();

    // h = b1 + rbf@Wr (K=32)
    float acc[4][8];
#pragma unroll
    for (int r = 0; r < 4; ++r)
#pragma unroll
        for (int c = 0; c < 8; ++c) acc[r][c] = b1r[c];

#pragma unroll 4
    for (int k = 0; k < RR; ++k) {
        float a[4];
#pragma unroll
        for (int r = 0; r < 4; ++r) a[r] = rbfs[(ty * 4 + r) * E_PR + k];
        float4 w0 = Wr4[k * 32 + tx * 2];
        float4 w1 = Wr4[k * 32 + tx * 2 + 1];
        float w[8] = {w0.x, w0.y, w0.z, w0.w, w1.x, w1.y, w1.z, w1.w};
#pragma unroll
        for (int r = 0; r < 4; ++r)
#pragma unroll
            for (int c = 0; c < 8; ++c) acc[r][c] = fmaf(a[r], w[c], acc[r][c]);
    }

    // += gathered P+Q ; LN ; GELU ; write back in place (same slots owned by thread)
#pragma unroll
    for (int r = 0; r < 4; ++r) {
        const float4* src = (const float4*)&As[(ty * 4 + r) * E_PA + tx * 8];
        float4 v0 = src[0], v1 = src[1];
        acc[r][0] += v0.x; acc[r][1] += v0.y; acc[r][2] += v0.z; acc[r][3] += v0.w;
        acc[r][4] += v1.x; acc[r][5] += v1.y; acc[r][6] += v1.z; acc[r][7] += v1.w;

        float s = 0.f;
#pragma unroll
        for (int c = 0; c < 8; ++c) s += acc[r][c];
#pragma unroll
        for (int m = 1; m < 16; m <<= 1) s += __shfl_xor_sync(0xffffffffu, s, m);
        float mu = s * (1.f / FF);
        float v = 0.f;
#pragma unroll
        for (int c = 0; c < 8; ++c) { float d = acc[r][c] - mu; v += d * d; }
#pragma unroll
        for (int m = 1; m < 16; m <<= 1) v += __shfl_xor_sync(0xffffffffu, v, m);
        float inv = rsqrtf(v * (1.f / FF) + 1e-5f);
        float o[8];
#pragma unroll
        for (int c = 0; c < 8; ++c) {
            float h = (acc[r][c] - mu) * inv * lg[c] + lb[c];
            o[c] = h * normcdff(h);          // exact gelu
        }
        float4* dst = (float4*)&As[(ty * 4 + r) * E_PA + tx * 8];
        dst[0] = make_float4(o[0], o[1], o[2], o[3]);
        dst[1] = make_float4(o[4], o[5], o[6], o[7]);
    }
    __syncthreads();

    // GEMM2: [128e x 128] @ l2t, weight streamed in 32-k chunks
    float acc2[4][8];
#pragma unroll
    for (int r = 0; r < 4; ++r)
#pragma unroll
        for (int c = 0; c < 8; ++c) acc2[r][c] = l2br[c];

    float4* Wb4 = (float4*)Wb;
    for (int kc = 0; kc < FF; kc += E_KC) {
        __syncthreads();
        for (int idx = tid; idx < E_KC * 32; idx += 512)
            Wb4[idx] = ((const float4*)g_l2t)[kc * 32 + idx];
        __syncthreads();
#pragma unroll 4
        for (int kk = 0; kk < E_KC; ++kk) {
            int k = kc + kk;
            float a[4];
#pragma unroll
            for (int r = 0; r < 4; ++r) a[r] = As[(ty * 4 + r) * E_PA + k];
            float4 w0 = Wb4[kk * 32 + tx * 2];
            float4 w1 = Wb4[kk * 32 + tx * 2 + 1];
            float w[8] = {w0.x, w0.y, w0.z, w0.w, w1.x, w1.y, w1.z, w1.w};
#pragma unroll
            for (int r = 0; r < 4; ++r)
#pragma unroll
                for (int c = 0; c < 8; ++c) acc2[r][c] = fmaf(a[r], w[c], acc2[r][c]);
        }
    }

    // scatter-add into agg[j] with vector atomics
#pragma unroll
    for (int r = 0; r < 4; ++r) {
        int node = jj[ty * 4 + r];
        float4 v0 = make_float4(acc2[r][0], acc2[r][1], acc2[r][2], acc2[r][3]);
        float4 v1 = make_float4(acc2[r][4], acc2[r][5], acc2[r][6], acc2[r][7]);
        atomicAdd((float4*)&g_agg[node * FF + tx * 8], v0);
        atomicAdd((float4*)&g_agg[node * FF + tx * 8 + 4], v1);
    }
}

// ---------------- output kernel: out = agg @ mtn_w^T ----------------
#define C_TN 64
#define C_PA 132
#define C_PW 260

__global__ __launch_bounds__(256, 1)
void out_kernel(const float* __restrict__ mtn_w, float* __restrict__ out) {
    extern __shared__ float sm[];
    float* aggs = sm;                    // 64 x 132
    float* Wt = sm + C_TN * C_PA;        // 128 x 260
    int tid = threadIdx.x;
    int tx = tid & 31, ty = tid >> 5;
    int n0 = blockIdx.x * C_TN;

    float4* ag4 = (float4*)aggs;
    const float4* g4 = (const float4*)g_agg;
    for (int idx = tid; idx < C_TN * 32; idx += 256) {
        int nl = idx >> 5, q = idx & 31;
        int n = n0 + nl;
        ag4[nl * 33 + q] = (n < NN) ? g4[n * 32 + q] : make_float4(0.f, 0.f, 0.f, 0.f);
    }
    for (int idx = tid; idx < HH * FF; idx += 256) {
        int h = idx >> 7, f = idx & 127;
        Wt[f * C_PW + h] = mtn_w[idx];
    }
    __syncthreads();

    float acc[8][8];
#pragma unroll
    for (int r = 0; r < 8; ++r)
#pragma unroll
        for (int c = 0; c < 8; ++c) acc[r][c] = 0.f;

    const float4* Wt4 = (const float4*)Wt;
    for (int k = 0; k < FF; ++k) {
        float a[8];
#pragma unroll
        for (int r = 0; r < 8; ++r) a[r] = aggs[(ty * 8 + r) * C_PA + k];
        float4 w0 = Wt4[k * 65 + tx * 2];
        float4 w1 = Wt4[k * 65 + tx * 2 + 1];
        float w[8] = {w0.x, w0.y, w0.z, w0.w, w1.x, w1.y, w1.z, w1.w};
#pragma unroll
        for (int r = 0; r < 8; ++r)
#pragma unroll
            for (int c = 0; c < 8; ++c) acc[r][c] = fmaf(a[r], w[c], acc[r][c]);
    }

#pragma unroll
    for (int r = 0; r < 8; ++r) {
        int n = n0 + ty * 8 + r;
        if (n < NN) {
            float4* dst = (float4*)&out[n * HH + tx * 8];
            dst[0] = make_float4(acc[r][0], acc[r][1], acc[r][2], acc[r][3]);
            dst[1] = make_float4(acc[r][4], acc[r][5], acc[r][6], acc[r][7]);
        }
    }
}

// ---------------- launch ----------------
extern "C" void kernel_launch(void* const* d_in, const int* in_sizes, int n_in,
                              void* d_out, int out_size) {
    const float* x      = (const float*)d_in[0];
    const float* rbf    = (const float*)d_in[1];
    const int*   eidx   = (const int*)d_in[2];
    const float* ntm_w  = (const float*)d_in[3];
    const float* ntm_b  = (const float*)d_in[4];
    const float* rtm_w  = (const float*)d_in[5];
    const float* rtm_b  = (const float*)d_in[6];
    const float* norm_g = (const float*)d_in[7];
    const float* norm_b = (const float*)d_in[8];
    const float* l1_w   = (const float*)d_in[9];
    const float* l1_b   = (const float*)d_in[10];
    const float* ln_g   = (const float*)d_in[11];
    const float* ln_b   = (const float*)d_in[12];
    const float* l2_w   = (const float*)d_in[13];
    const float* l2_b   = (const float*)d_in[14];
    const float* mtn_w  = (const float*)d_in[15];
    float* out = (float*)d_out;

    const int smem_node = (A_TN * A_PX + HH * A_PW) * 4;           // 201728
    const int smem_pq   = (P_TN * P_PX + FF * 256) * 4;            // 198656
    const int smem_edge = (E_TE * E_PA + E_TE * E_PR + RR * FF + E_KC * FF) * 4; // 118784
    const int smem_out  = (C_TN * C_PA + FF * C_PW) * 4;           // 166912

    cudaFuncSetAttribute(node_kernel, cudaFuncAttributeMaxDynamicSharedMemorySize, smem_node);
    cudaFuncSetAttribute(pq_kernel,   cudaFuncAttributeMaxDynamicSharedMemorySize, smem_pq);
    cudaFuncSetAttribute(edge_kernel, cudaFuncAttributeMaxDynamicSharedMemorySize, smem_edge);
    cudaFuncSetAttribute(out_kernel,  cudaFuncAttributeMaxDynamicSharedMemorySize, smem_out);

    zero_agg_kernel<<<2048, 256>>>();
    prep_kernel<<<FF, 128>>>(l1_w, l1_b, rtm_w, rtm_b, l2_w);
    node_kernel<<<(NN + A_TN - 1) / A_TN, 256, smem_node>>>(x, ntm_w, ntm_b, norm_g, norm_b);
    pq_kernel<<<(NN + P_TN - 1) / P_TN, 512, smem_pq>>>();
    edge_kernel<<<EE / E_TE, 512, smem_edge>>>(rbf, eidx, ln_g, ln_b, l2_b);
    out_kernel<<<(NN + C_TN - 1) / C_TN, 256, smem_out>>>(mtn_w, out);
}

// round 6
// speedup vs baseline: 2.6470x; 1.4507x over previous
#include <cuda_runtime.h>
#include <cuda_bf16.h>
#include <math.h>
#include <stdint.h>

#define NN 50000
#define EE 800000
#define HH 256
#define FF 128
#define RR 32

// ---------------- persistent device scratch ----------------
__device__ float g_xf[NN * FF];        // LN(node_to_message(x))
__device__ float g_PQ[NN * 256];       // per-node P (0:128) and Q (128:256)
__device__ float g_agg[NN * FF];       // segment-sum accumulator
__device__ float g_Wpq[FF * 256];      // [k][f'] f'<128: l1a, f'>=128: l1b
__device__ float g_Wr[RR * FF];        // folded rbf weight [r][f]
__device__ float g_b1f[FF];            // folded GEMM1 bias
__device__ __nv_bfloat16 g_Bhi[FF * FF];  // l2_w hi  [f][k] row-major
__device__ __nv_bfloat16 g_Blo[FF * FF];  // l2_w lo  [f][k] row-major

// ---------------- ptx helpers (plain sm_103-legal) ----------------
__device__ __forceinline__ uint32_t smem_u32(const void* p) {
    uint32_t a;
    asm("{ .reg .u64 t; cvta.to.shared.u64 t, %1; cvt.u32.u64 %0, t; }" : "=r"(a) : "l"(p));
    return a;
}
__device__ __forceinline__ void ldsm_x4(uint32_t& r0, uint32_t& r1, uint32_t& r2, uint32_t& r3,
                                        uint32_t addr) {
    asm volatile("ldmatrix.sync.aligned.m8n8.x4.shared.b16 {%0,%1,%2,%3}, [%4];"
                 : "=r"(r0), "=r"(r1), "=r"(r2), "=r"(r3) : "r"(addr));
}
__device__ __forceinline__ void mma16816(float* c, const uint32_t* a, const uint32_t* b) {
    asm volatile(
        "mma.sync.aligned.m16n8k16.row.col.f32.bf16.bf16.f32 "
        "{%0,%1,%2,%3}, {%4,%5,%6,%7}, {%8,%9}, {%0,%1,%2,%3};"
        : "+f"(c[0]), "+f"(c[1]), "+f"(c[2]), "+f"(c[3])
        : "r"(a[0]), "r"(a[1]), "r"(a[2]), "r"(a[3]), "r"(b[0]), "r"(b[1]));
}

// ---------------- prep: fold rtm into l1, build weights, split l2 to bf16 --------
__global__ void prep_kernel(const float* __restrict__ l1_w, const float* __restrict__ l1_b,
                            const float* __restrict__ rtm_w, const float* __restrict__ rtm_b,
                            const float* __restrict__ l2_w) {
    int f = blockIdx.x;      // 128
    int t = threadIdx.x;     // 128
    g_Wpq[t * 256 + f]       = l1_w[f * 384 + t];
    g_Wpq[t * 256 + 128 + f] = l1_w[f * 384 + 128 + t];
    if (t < RR) {
        float s = 0.f;
        for (int c = 0; c < FF; ++c)
            s += l1_w[f * 384 + 256 + c] * rtm_w[c * RR + t];
        g_Wr[t * FF + f] = s;
    } else if (t == RR) {
        float s = l1_b[f];
        for (int c = 0; c < FF; ++c)
            s += l1_w[f * 384 + 256 + c] * rtm_b[c];
        g_b1f[f] = s;
    }
    float w = l2_w[f * FF + t];
    __nv_bfloat16 bh = __float2bfloat16_rn(w);
    __nv_bfloat16 bl = __float2bfloat16_rn(w - __bfloat162float(bh));
    g_Bhi[f * FF + t] = bh;
    g_Blo[f * FF + t] = bl;
}

// ---------------- zero the aggregation buffer ----------------
__global__ void zero_agg_kernel() {
    float4 z = make_float4(0.f, 0.f, 0.f, 0.f);
    float4* p = (float4*)g_agg;
    int total = NN * FF / 4;
    for (int i = blockIdx.x * blockDim.x + threadIdx.x; i < total; i += gridDim.x * blockDim.x)
        p[i] = z;
}

// ---------------- node kernel: xf = LN(x @ ntm_w^T + ntm_b) ----------------
#define A_TN 64
#define A_PX 260
#define A_PW 132

__global__ __launch_bounds__(256, 1)
void node_kernel(const float* __restrict__ x,
                 const float* __restrict__ ntm_w, const float* __restrict__ ntm_b,
                 const float* __restrict__ norm_g, const float* __restrict__ norm_b) {
    extern __shared__ float sm[];
    float* xs = sm;
    float* Ws = sm + A_TN * A_PX;
    int tid = threadIdx.x;
    int tx = tid & 15, ty = tid >> 4;
    int n0 = blockIdx.x * A_TN;

    float4* xs4 = (float4*)xs;
    const float4* x4 = (const float4*)x;
    for (int idx = tid; idx < A_TN * 64; idx += 256) {
        int nl = idx >> 6, q = idx & 63;
        int n = n0 + nl;
        xs4[nl * 65 + q] = (n < NN) ? x4[n * 64 + q] : make_float4(0.f, 0.f, 0.f, 0.f);
    }
    for (int idx = tid; idx < FF * HH; idx += 256) {
        int f = idx >> 8, h = idx & 255;
        Ws[h * A_PW + f] = ntm_w[idx];
    }
    float bb[8], gg[8], be[8];
#pragma unroll
    for (int c = 0; c < 8; ++c) {
        int f = tx * 8 + c;
        bb[c] = ntm_b[f]; gg[c] = norm_g[f]; be[c] = norm_b[f];
    }
    __syncthreads();

    float acc[4][8];
#pragma unroll
    for (int r = 0; r < 4; ++r)
#pragma unroll
        for (int c = 0; c < 8; ++c) acc[r][c] = bb[c];

    const float4* Ws4 = (const float4*)Ws;
    for (int k = 0; k < HH; ++k) {
        float a[4];
#pragma unroll
        for (int r = 0; r < 4; ++r) a[r] = xs[(ty * 4 + r) * A_PX + k];
        float4 w0 = Ws4[k * 33 + tx * 2];
        float4 w1 = Ws4[k * 33 + tx * 2 + 1];
        float w[8] = {w0.x, w0.y, w0.z, w0.w, w1.x, w1.y, w1.z, w1.w};
#pragma unroll
        for (int r = 0; r < 4; ++r)
#pragma unroll
            for (int c = 0; c < 8; ++c) acc[r][c] = fmaf(a[r], w[c], acc[r][c]);
    }

#pragma unroll
    for (int r = 0; r < 4; ++r) {
        float s = 0.f;
#pragma unroll
        for (int c = 0; c < 8; ++c) s += acc[r][c];
#pragma unroll
        for (int m = 1; m < 16; m <<= 1) s += __shfl_xor_sync(0xffffffffu, s, m);
        float mu = s * (1.f / FF);
        float v = 0.f;
#pragma unroll
        for (int c = 0; c < 8; ++c) { float d = acc[r][c] - mu; v += d * d; }
#pragma unroll
        for (int m = 1; m < 16; m <<= 1) v += __shfl_xor_sync(0xffffffffu, v, m);
        float inv = rsqrtf(v * (1.f / FF) + 1e-5f);
        int n = n0 + ty * 4 + r;
        if (n < NN) {
            float o[8];
#pragma unroll
            for (int c = 0; c < 8; ++c) o[c] = (acc[r][c] - mu) * inv * gg[c] + be[c];
            float4* dst = (float4*)&g_xf[n * FF + tx * 8];
            dst[0] = make_float4(o[0], o[1], o[2], o[3]);
            dst[1] = make_float4(o[4], o[5], o[6], o[7]);
        }
    }
}

// ---------------- pq kernel: PQ = xf @ [W1a | W1b] ----------------
#define P_TN 128
#define P_PX 132

__global__ __launch_bounds__(512, 1)
void pq_kernel() {
    extern __shared__ float sm[];
    float* ts = sm;
    float* Wp = sm + P_TN * P_PX;
    int tid = threadIdx.x;
    int tx = tid & 31, ty = tid >> 5;
    int n0 = blockIdx.x * P_TN;

    float4* ts4 = (float4*)ts;
    const float4* xf4 = (const float4*)g_xf;
    for (int idx = tid; idx < P_TN * 32; idx += 512) {
        int nl = idx >> 5, q = idx & 31;
        int n = n0 + nl;
        ts4[nl * 33 + q] = (n < NN) ? xf4[n * 32 + q] : make_float4(0.f, 0.f, 0.f, 0.f);
    }
    float4* Wp4 = (float4*)Wp;
    const float4* gW4 = (const float4*)g_Wpq;
    for (int idx = tid; idx < FF * 256 / 4; idx += 512)
        Wp4[idx] = gW4[idx];
    __syncthreads();

    float acc[8][8];
#pragma unroll
    for (int r = 0; r < 8; ++r)
#pragma unroll
        for (int c = 0; c < 8; ++c) acc[r][c] = 0.f;

    for (int k = 0; k < FF; ++k) {
        float a[8];
#pragma unroll
        for (int r = 0; r < 8; ++r) a[r] = ts[(ty * 8 + r) * P_PX + k];
        float4 w0 = Wp4[k * 64 + tx * 2];
        float4 w1 = Wp4[k * 64 + tx * 2 + 1];
        float w[8] = {w0.x, w0.y, w0.z, w0.w, w1.x, w1.y, w1.z, w1.w};
#pragma unroll
        for (int r = 0; r < 8; ++r)
#pragma unroll
            for (int c = 0; c < 8; ++c) acc[r][c] = fmaf(a[r], w[c], acc[r][c]);
    }

#pragma unroll
    for (int r = 0; r < 8; ++r) {
        int n = n0 + ty * 8 + r;
        if (n < NN) {
            float4* dst = (float4*)&g_PQ[n * 256 + tx * 8];
            dst[0] = make_float4(acc[r][0], acc[r][1], acc[r][2], acc[r][3]);
            dst[1] = make_float4(acc[r][4], acc[r][5], acc[r][6], acc[r][7]);
        }
    }
}

// ---------------- fused edge kernel (warp-MMA GEMM2) ----------------
// smem byte offsets; A/B tiles are bf16 [128 rows][128 cols] with row pitch 136 elem (272 B)
#define E_PITCH 136
#define EO_AHI   0
#define EO_ALO   34816
#define EO_BHI   69632
#define EO_BLO   104448
#define EO_RBF   139264    // 128 x 36 floats
#define EO_WR    157696    // 32 x 128 floats
#define EO_BIAS  174080    // 128 floats
#define EO_II    174592    // 128 ints
#define EO_JJ    175104    // 128 ints
#define E_SMEM   175616

__global__ __launch_bounds__(512, 1)
void edge_kernel(const float* __restrict__ rbf, const int* __restrict__ edge_index,
                 const float* __restrict__ ln_g, const float* __restrict__ ln_b,
                 const float* __restrict__ l2_b) {
    extern __shared__ char sma[];
    uint32_t sbase = smem_u32(sma);

    int tid = threadIdx.x;
    int wid = tid >> 5, lane = tid & 31;
    int tx = tid & 15, ty = tid >> 4;          // phase-1 mapping: tx f-groups, ty e-groups of 4
    int e0 = blockIdx.x * 128;

    int*   ii_s  = (int*)(sma + EO_II);
    int*   jj_s  = (int*)(sma + EO_JJ);
    float* rbfs  = (float*)(sma + EO_RBF);
    float* Wr    = (float*)(sma + EO_WR);
    float* sBias = (float*)(sma + EO_BIAS);

    if (tid < 128) ii_s[tid] = edge_index[e0 + tid];
    else if (tid < 256) jj_s[tid - 128] = edge_index[EE + e0 + (tid - 128)];
    else if (tid < 384) sBias[tid - 256] = l2_b[tid - 256];

    // rbf tile [128 x 32] -> pitch 36
    float4* rbfs4 = (float4*)rbfs;
    const float4* rbf4 = (const float4*)rbf;
    for (int idx = tid; idx < 128 * 8; idx += 512) {
        int e = idx >> 3, q = idx & 7;
        rbfs4[e * 9 + q] = rbf4[(e0 + e) * 8 + q];
    }
    // Wr
    float4* Wr4 = (float4*)Wr;
    const float4* gWr4 = (const float4*)g_Wr;
    for (int idx = tid; idx < RR * FF / 4; idx += 512)
        Wr4[idx] = gWr4[idx];
    // B tiles: row-major [f][k] -> pitch 136 elems (16 uint4 per row of 128 bf16)
    {
        const uint4* gbh = (const uint4*)g_Bhi;
        const uint4* gbl = (const uint4*)g_Blo;
        for (int idx = tid; idx < 128 * 16; idx += 512) {
            int rowi = idx >> 4, q = idx & 15;
            *(uint4*)(sma + EO_BHI + rowi * (E_PITCH * 2) + q * 16) = gbh[idx];
            *(uint4*)(sma + EO_BLO + rowi * (E_PITCH * 2) + q * 16) = gbl[idx];
        }
    }

    float b1r[8], lg[8], lb[8];
#pragma unroll
    for (int c = 0; c < 8; ++c) {
        int f = tx * 8 + c;
        b1r[c] = g_b1f[f]; lg[c] = ln_g[f]; lb[c] = ln_b[f];
    }
    __syncthreads();

    // ---- phase 1: h = b1 + rbf @ Wr (K=32) ----
    float acc[4][8];
#pragma unroll
    for (int r = 0; r < 4; ++r)
#pragma unroll
        for (int c = 0; c < 8; ++c) acc[r][c] = b1r[c];

#pragma unroll 4
    for (int k = 0; k < RR; ++k) {
        float a[4];
#pragma unroll
        for (int r = 0; r < 4; ++r) a[r] = rbfs[(ty * 4 + r) * 36 + k];
        float4 w0 = Wr4[k * 32 + tx * 2];
        float4 w1 = Wr4[k * 32 + tx * 2 + 1];
        float w[8] = {w0.x, w0.y, w0.z, w0.w, w1.x, w1.y, w1.z, w1.w};
#pragma unroll
        for (int r = 0; r < 4; ++r)
#pragma unroll
            for (int c = 0; c < 8; ++c) acc[r][c] = fmaf(a[r], w[c], acc[r][c]);
    }

    // + P[i] + Q[j] gather, LN, GELU, bf16 hi/lo split into A tiles (row-major p136)
    const float4* pq4 = (const float4*)g_PQ;
#pragma unroll
    for (int r = 0; r < 4; ++r) {
        int e = ty * 4 + r;
        int i = ii_s[e], j = jj_s[e];
        float4 p0 = pq4[i * 64 + tx * 2];
        float4 p1 = pq4[i * 64 + tx * 2 + 1];
        float4 q0 = pq4[j * 64 + 32 + tx * 2];
        float4 q1 = pq4[j * 64 + 32 + tx * 2 + 1];
        acc[r][0] += p0.x + q0.x; acc[r][1] += p0.y + q0.y;
        acc[r][2] += p0.z + q0.z; acc[r][3] += p0.w + q0.w;
        acc[r][4] += p1.x + q1.x; acc[r][5] += p1.y + q1.y;
        acc[r][6] += p1.z + q1.z; acc[r][7] += p1.w + q1.w;

        float s = 0.f;
#pragma unroll
        for (int c = 0; c < 8; ++c) s += acc[r][c];
#pragma unroll
        for (int m = 1; m < 16; m <<= 1) s += __shfl_xor_sync(0xffffffffu, s, m);
        float mu = s * (1.f / FF);
        float v = 0.f;
#pragma unroll
        for (int c = 0; c < 8; ++c) { float d = acc[r][c] - mu; v += d * d; }
#pragma unroll
        for (int m = 1; m < 16; m <<= 1) v += __shfl_xor_sync(0xffffffffu, v, m);
        float inv = rsqrtf(v * (1.f / FF) + 1e-5f);

        uint32_t hw[4], lw[4];
#pragma unroll
        for (int c2 = 0; c2 < 4; ++c2) {
            float h0 = (acc[r][c2 * 2]     - mu) * inv * lg[c2 * 2]     + lb[c2 * 2];
            float h1 = (acc[r][c2 * 2 + 1] - mu) * inv * lg[c2 * 2 + 1] + lb[c2 * 2 + 1];
            float o0 = h0 * normcdff(h0);
            float o1 = h1 * normcdff(h1);
            __nv_bfloat16 b0 = __float2bfloat16_rn(o0);
            __nv_bfloat16 b1 = __float2bfloat16_rn(o1);
            __nv_bfloat162 hh = __halves2bfloat162(b0, b1);
            __nv_bfloat162 ll = __halves2bfloat162(
                __float2bfloat16_rn(o0 - __bfloat162float(b0)),
                __float2bfloat16_rn(o1 - __bfloat162float(b1)));
            hw[c2] = *(uint32_t*)&hh;
            lw[c2] = *(uint32_t*)&ll;
        }
        uint32_t off = (uint32_t)e * (E_PITCH * 2) + (uint32_t)tx * 16;
        *(uint4*)(sma + EO_AHI + off) = make_uint4(hw[0], hw[1], hw[2], hw[3]);
        *(uint4*)(sma + EO_ALO + off) = make_uint4(lw[0], lw[1], lw[2], lw[3]);
    }
    __syncthreads();

    // ---- phase 2: GEMM2 via mma.sync m16n8k16 bf16, 3 products hi/lo ----
    int warp_m = wid & 3, warp_n = wid >> 2;   // 4x4 warp grid, 32x32 tile each
    float C[2][4][4];
#pragma unroll
    for (int mi = 0; mi < 2; ++mi)
#pragma unroll
        for (int ni = 0; ni < 4; ++ni)
#pragma unroll
            for (int c = 0; c < 4; ++c) C[mi][ni][c] = 0.f;

    // ldmatrix address offsets (element -> byte via *2)
    int a_row = warp_m * 32 + (lane & 15);
    int a_colh = (lane >> 4) * 8;
    int b_row = warp_n * 32 + ((lane & 7) | ((lane & 16) >> 1));
    int b_colh = ((lane >> 3) & 1) * 8;

#pragma unroll
    for (int p = 0; p < 3; ++p) {
        uint32_t Ab = sbase + ((p == 2) ? EO_ALO : EO_AHI);
        uint32_t Bb = sbase + ((p == 1) ? EO_BLO : EO_BHI);
#pragma unroll
        for (int ks = 0; ks < 8; ++ks) {
            int kb = ks * 16;
            uint32_t bf[8];
            ldsm_x4(bf[0], bf[1], bf[2], bf[3],
                    Bb + (uint32_t)(b_row * E_PITCH + kb + b_colh) * 2);
            ldsm_x4(bf[4], bf[5], bf[6], bf[7],
                    Bb + (uint32_t)((b_row + 16) * E_PITCH + kb + b_colh) * 2);
            uint32_t af[8];
            ldsm_x4(af[0], af[1], af[2], af[3],
                    Ab + (uint32_t)(a_row * E_PITCH + kb + a_colh) * 2);
            ldsm_x4(af[4], af[5], af[6], af[7],
                    Ab + (uint32_t)((a_row + 16) * E_PITCH + kb + a_colh) * 2);
#pragma unroll
            for (int mi = 0; mi < 2; ++mi)
#pragma unroll
                for (int ni = 0; ni < 4; ++ni)
                    mma16816(C[mi][ni], af + 4 * mi, bf + 2 * ni);
        }
    }

    // ---- scatter: C fragments + bias -> atomic float2 into g_agg[j] ----
    int lr = lane >> 2;            // 0..7
    int lc = (lane & 3) * 2;       // 0,2,4,6
#pragma unroll
    for (int mi = 0; mi < 2; ++mi) {
#pragma unroll
        for (int rr = 0; rr < 2; ++rr) {
            int erow = warp_m * 32 + mi * 16 + rr * 8 + lr;
            int node = jj_s[erow];
            float* dst = &g_agg[node * FF];
#pragma unroll
            for (int ni = 0; ni < 4; ++ni) {
                int col = warp_n * 32 + ni * 8 + lc;
                float2 bv = *(float2*)&sBias[col];
                float2 v = make_float2(C[mi][ni][rr * 2]     + bv.x,
                                       C[mi][ni][rr * 2 + 1] + bv.y);
                atomicAdd((float2*)&dst[col], v);
            }
        }
    }
}

// ---------------- output kernel: out = agg @ mtn_w^T ----------------
#define C_TN 64
#define C_PA 132
#define C_PW 260

__global__ __launch_bounds__(256, 1)
void out_kernel(const float* __restrict__ mtn_w, float* __restrict__ out) {
    extern __shared__ float sm[];
    float* aggs = sm;
    float* Wt = sm + C_TN * C_PA;
    int tid = threadIdx.x;
    int tx = tid & 31, ty = tid >> 5;
    int n0 = blockIdx.x * C_TN;

    float4* ag4 = (float4*)aggs;
    const float4* g4 = (const float4*)g_agg;
    for (int idx = tid; idx < C_TN * 32; idx += 256) {
        int nl = idx >> 5, q = idx & 31;
        int n = n0 + nl;
        ag4[nl * 33 + q] = (n < NN) ? g4[n * 32 + q] : make_float4(0.f, 0.f, 0.f, 0.f);
    }
    for (int idx = tid; idx < HH * FF; idx += 256) {
        int h = idx >> 7, f = idx & 127;
        Wt[f * C_PW + h] = mtn_w[idx];
    }
    __syncthreads();

    float acc[8][8];
#pragma unroll
    for (int r = 0; r < 8; ++r)
#pragma unroll
        for (int c = 0; c < 8; ++c) acc[r][c] = 0.f;

    const float4* Wt4 = (const float4*)Wt;
    for (int k = 0; k < FF; ++k) {
        float a[8];
#pragma unroll
        for (int r = 0; r < 8; ++r) a[r] = aggs[(ty * 8 + r) * C_PA + k];
        float4 w0 = Wt4[k * 65 + tx * 2];
        float4 w1 = Wt4[k * 65 + tx * 2 + 1];
        float w[8] = {w0.x, w0.y, w0.z, w0.w, w1.x, w1.y, w1.z, w1.w};
#pragma unroll
        for (int r = 0; r < 8; ++r)
#pragma unroll
            for (int c = 0; c < 8; ++c) acc[r][c] = fmaf(a[r], w[c], acc[r][c]);
    }

#pragma unroll
    for (int r = 0; r < 8; ++r) {
        int n = n0 + ty * 8 + r;
        if (n < NN) {
            float4* dst = (float4*)&out[n * HH + tx * 8];
            dst[0] = make_float4(acc[r][0], acc[r][1], acc[r][2], acc[r][3]);
            dst[1] = make_float4(acc[r][4], acc[r][5], acc[r][6], acc[r][7]);
        }
    }
}

// ---------------- launch ----------------
extern "C" void kernel_launch(void* const* d_in, const int* in_sizes, int n_in,
                              void* d_out, int out_size) {
    const float* x      = (const float*)d_in[0];
    const float* rbf    = (const float*)d_in[1];
    const int*   eidx   = (const int*)d_in[2];
    const float* ntm_w  = (const float*)d_in[3];
    const float* ntm_b  = (const float*)d_in[4];
    const float* rtm_w  = (const float*)d_in[5];
    const float* rtm_b  = (const float*)d_in[6];
    const float* norm_g = (const float*)d_in[7];
    const float* norm_b = (const float*)d_in[8];
    const float* l1_w   = (const float*)d_in[9];
    const float* l1_b   = (const float*)d_in[10];
    const float* ln_g   = (const float*)d_in[11];
    const float* ln_b   = (const float*)d_in[12];
    const float* l2_w   = (const float*)d_in[13];
    const float* l2_b   = (const float*)d_in[14];
    const float* mtn_w  = (const float*)d_in[15];
    float* out = (float*)d_out;

    const int smem_node = (A_TN * A_PX + HH * A_PW) * 4;
    const int smem_pq   = (P_TN * P_PX + FF * 256) * 4;
    const int smem_out  = (C_TN * C_PA + FF * C_PW) * 4;

    cudaFuncSetAttribute(node_kernel, cudaFuncAttributeMaxDynamicSharedMemorySize, smem_node);
    cudaFuncSetAttribute(pq_kernel,   cudaFuncAttributeMaxDynamicSharedMemorySize, smem_pq);
    cudaFuncSetAttribute(edge_kernel, cudaFuncAttributeMaxDynamicSharedMemorySize, E_SMEM);
    cudaFuncSetAttribute(out_kernel,  cudaFuncAttributeMaxDynamicSharedMemorySize, smem_out);

    zero_agg_kernel<<<2048, 256>>>();
    prep_kernel<<<FF, 128>>>(l1_w, l1_b, rtm_w, rtm_b, l2_w);
    node_kernel<<<(NN + A_TN - 1) / A_TN, 256, smem_node>>>(x, ntm_w, ntm_b, norm_g, norm_b);
    pq_kernel<<<(NN + P_TN - 1) / P_TN, 512, smem_pq>>>();
    edge_kernel<<<EE / 128, 512, E_SMEM>>>(rbf, eidx, ln_g, ln_b, l2_b);
    out_kernel<<<(NN + C_TN - 1) / C_TN, 256, smem_out>>>(mtn_w, out);
}

// round 7
// speedup vs baseline: 4.1214x; 1.5570x over previous
#include <cuda_runtime.h>
#include <math.h>
#include <stdint.h>

#define NN 50000
#define EE 800000
#define HH 256
#define FF 128
#define RR 32

// ---------------- persistent device scratch ----------------
__device__ float g_xf[NN * FF];        // LN(node_to_message(x))
__device__ float g_PQ[NN * 256];       // per-node P (0:128) and Q (128:256)
__device__ float g_G[NN * FF];         // segment-sum of GELU outputs
__device__ float g_deg[NN];            // in-degree (count of edges with target j)
__device__ float g_Wpq[FF * 256];      // [k][f'] f'<128: l1a, f'>=128: l1b
__device__ float g_Wr[RR * FF];        // folded rbf weight [r][f]
__device__ float g_b1f[FF];            // folded GEMM1 bias
__device__ float g_Mt[FF * HH];        // (mtn_w @ l2_w) stored [k][h]
__device__ float g_bm[HH];             // mtn_w @ l2_b

// ---------------- prep: fold rtm into l1, build transposed weights ----------------
__global__ void prep_kernel(const float* __restrict__ l1_w, const float* __restrict__ l1_b,
                            const float* __restrict__ rtm_w, const float* __restrict__ rtm_b) {
    int f = blockIdx.x;      // 128
    int t = threadIdx.x;     // 128
    g_Wpq[t * 256 + f]       = l1_w[f * 384 + t];
    g_Wpq[t * 256 + 128 + f] = l1_w[f * 384 + 128 + t];
    if (t < RR) {
        float s = 0.f;
        for (int c = 0; c < FF; ++c)
            s += l1_w[f * 384 + 256 + c] * rtm_w[c * RR + t];
        g_Wr[t * FF + f] = s;
    } else if (t == RR) {
        float s = l1_b[f];
        for (int c = 0; c < FF; ++c)
            s += l1_w[f * 384 + 256 + c] * rtm_b[c];
        g_b1f[f] = s;
    }
}

// ---------------- prep2: M = mtn_w @ l2_w (stored [k][h]), bm = mtn_w @ l2_b ------
__global__ void prep2_kernel(const float* __restrict__ mtn_w, const float* __restrict__ l2_w,
                             const float* __restrict__ l2_b) {
    __shared__ float mrow[FF];
    int h = blockIdx.x;      // 256
    int k = threadIdx.x;     // 128
    mrow[k] = mtn_w[h * FF + k];
    __syncthreads();
    float s = 0.f;
    for (int f = 0; f < FF; ++f)
        s = fmaf(mrow[f], l2_w[f * FF + k], s);
    g_Mt[k * HH + h] = s;
    if (k == 0) {
        float b = 0.f;
        for (int f = 0; f < FF; ++f)
            b = fmaf(mrow[f], l2_b[f], b);
        g_bm[h] = b;
    }
}

// ---------------- zero G and deg ----------------
__global__ void zero_kernel() {
    float4 z = make_float4(0.f, 0.f, 0.f, 0.f);
    float4* p = (float4*)g_G;
    int total = NN * FF / 4;
    for (int i = blockIdx.x * blockDim.x + threadIdx.x; i < total; i += gridDim.x * blockDim.x)
        p[i] = z;
    for (int i = blockIdx.x * blockDim.x + threadIdx.x; i < NN; i += gridDim.x * blockDim.x)
        g_deg[i] = 0.f;
}

// ---------------- node kernel: xf = LN(x @ ntm_w^T + ntm_b) ----------------
#define A_TN 64
#define A_PX 260
#define A_PW 132

__global__ __launch_bounds__(256, 1)
void node_kernel(const float* __restrict__ x,
                 const float* __restrict__ ntm_w, const float* __restrict__ ntm_b,
                 const float* __restrict__ norm_g, const float* __restrict__ norm_b) {
    extern __shared__ float sm[];
    float* xs = sm;
    float* Ws = sm + A_TN * A_PX;
    int tid = threadIdx.x;
    int tx = tid & 15, ty = tid >> 4;
    int n0 = blockIdx.x * A_TN;

    float4* xs4 = (float4*)xs;
    const float4* x4 = (const float4*)x;
    for (int idx = tid; idx < A_TN * 64; idx += 256) {
        int nl = idx >> 6, q = idx & 63;
        int n = n0 + nl;
        xs4[nl * 65 + q] = (n < NN) ? x4[n * 64 + q] : make_float4(0.f, 0.f, 0.f, 0.f);
    }
    for (int idx = tid; idx < FF * HH; idx += 256) {
        int f = idx >> 8, h = idx & 255;
        Ws[h * A_PW + f] = ntm_w[idx];
    }
    float bb[8], gg[8], be[8];
#pragma unroll
    for (int c = 0; c < 8; ++c) {
        int f = tx * 8 + c;
        bb[c] = ntm_b[f]; gg[c] = norm_g[f]; be[c] = norm_b[f];
    }
    __syncthreads();

    float acc[4][8];
#pragma unroll
    for (int r = 0; r < 4; ++r)
#pragma unroll
        for (int c = 0; c < 8; ++c) acc[r][c] = bb[c];

    const float4* Ws4 = (const float4*)Ws;
    for (int k = 0; k < HH; ++k) {
        float a[4];
#pragma unroll
        for (int r = 0; r < 4; ++r) a[r] = xs[(ty * 4 + r) * A_PX + k];
        float4 w0 = Ws4[k * 33 + tx * 2];
        float4 w1 = Ws4[k * 33 + tx * 2 + 1];
        float w[8] = {w0.x, w0.y, w0.z, w0.w, w1.x, w1.y, w1.z, w1.w};
#pragma unroll
        for (int r = 0; r < 4; ++r)
#pragma unroll
            for (int c = 0; c < 8; ++c) acc[r][c] = fmaf(a[r], w[c], acc[r][c]);
    }

#pragma unroll
    for (int r = 0; r < 4; ++r) {
        float s = 0.f;
#pragma unroll
        for (int c = 0; c < 8; ++c) s += acc[r][c];
#pragma unroll
        for (int m = 1; m < 16; m <<= 1) s += __shfl_xor_sync(0xffffffffu, s, m);
        float mu = s * (1.f / FF);
        float v = 0.f;
#pragma unroll
        for (int c = 0; c < 8; ++c) { float d = acc[r][c] - mu; v += d * d; }
#pragma unroll
        for (int m = 1; m < 16; m <<= 1) v += __shfl_xor_sync(0xffffffffu, v, m);
        float inv = rsqrtf(v * (1.f / FF) + 1e-5f);
        int n = n0 + ty * 4 + r;
        if (n < NN) {
            float o[8];
#pragma unroll
            for (int c = 0; c < 8; ++c) o[c] = (acc[r][c] - mu) * inv * gg[c] + be[c];
            float4* dst = (float4*)&g_xf[n * FF + tx * 8];
            dst[0] = make_float4(o[0], o[1], o[2], o[3]);
            dst[1] = make_float4(o[4], o[5], o[6], o[7]);
        }
    }
}

// ---------------- pq kernel: PQ = xf @ [W1a | W1b] ----------------
#define P_TN 128
#define P_PX 132

__global__ __launch_bounds__(512, 1)
void pq_kernel() {
    extern __shared__ float sm[];
    float* ts = sm;
    float* Wp = sm + P_TN * P_PX;
    int tid = threadIdx.x;
    int tx = tid & 31, ty = tid >> 5;
    int n0 = blockIdx.x * P_TN;

    float4* ts4 = (float4*)ts;
    const float4* xf4 = (const float4*)g_xf;
    for (int idx = tid; idx < P_TN * 32; idx += 512) {
        int nl = idx >> 5, q = idx & 31;
        int n = n0 + nl;
        ts4[nl * 33 + q] = (n < NN) ? xf4[n * 32 + q] : make_float4(0.f, 0.f, 0.f, 0.f);
    }
    float4* Wp4 = (float4*)Wp;
    const float4* gW4 = (const float4*)g_Wpq;
    for (int idx = tid; idx < FF * 256 / 4; idx += 512)
        Wp4[idx] = gW4[idx];
    __syncthreads();

    float acc[8][8];
#pragma unroll
    for (int r = 0; r < 8; ++r)
#pragma unroll
        for (int c = 0; c < 8; ++c) acc[r][c] = 0.f;

    for (int k = 0; k < FF; ++k) {
        float a[8];
#pragma unroll
        for (int r = 0; r < 8; ++r) a[r] = ts[(ty * 8 + r) * P_PX + k];
        float4 w0 = Wp4[k * 64 + tx * 2];
        float4 w1 = Wp4[k * 64 + tx * 2 + 1];
        float w[8] = {w0.x, w0.y, w0.z, w0.w, w1.x, w1.y, w1.z, w1.w};
#pragma unroll
        for (int r = 0; r < 8; ++r)
#pragma unroll
            for (int c = 0; c < 8; ++c) acc[r][c] = fmaf(a[r], w[c], acc[r][c]);
    }

#pragma unroll
    for (int r = 0; r < 8; ++r) {
        int n = n0 + ty * 8 + r;
        if (n < NN) {
            float4* dst = (float4*)&g_PQ[n * 256 + tx * 8];
            dst[0] = make_float4(acc[r][0], acc[r][1], acc[r][2], acc[r][3]);
            dst[1] = make_float4(acc[r][4], acc[r][5], acc[r][6], acc[r][7]);
        }
    }
}

// ---------------- edge kernel: h = P[i]+Q[j]+rbf@Wr+b1; LN; GELU; scatter ---------
// 256 threads, 64 edges per block. All fp32.
__global__ __launch_bounds__(256, 3)
void edge_kernel(const float* __restrict__ rbf, const int* __restrict__ edge_index,
                 const float* __restrict__ ln_g, const float* __restrict__ ln_b) {
    __shared__ float rbfs[64 * 36];
    __shared__ float Wr[RR * FF];
    __shared__ int ii_s[64], jj_s[64];
    int tid = threadIdx.x;
    int tx = tid & 15, ty = tid >> 4;          // tx: 16 f-groups of 8, ty: 16 e-groups of 4
    int e0 = blockIdx.x * 64;

    if (tid < 64) ii_s[tid] = edge_index[e0 + tid];
    else if (tid < 128) jj_s[tid - 64] = edge_index[EE + e0 + (tid - 64)];

    float4* rbfs4 = (float4*)rbfs;
    const float4* rbf4 = (const float4*)rbf;
    for (int idx = tid; idx < 64 * 8; idx += 256) {
        int e = idx >> 3, q = idx & 7;
        rbfs4[e * 9 + q] = rbf4[(e0 + e) * 8 + q];
    }
    float4* Wr4 = (float4*)Wr;
    const float4* gWr4 = (const float4*)g_Wr;
    for (int idx = tid; idx < RR * FF / 4; idx += 256)
        Wr4[idx] = gWr4[idx];

    float b1r[8], lg[8], lb[8];
#pragma unroll
    for (int c = 0; c < 8; ++c) {
        int f = tx * 8 + c;
        b1r[c] = g_b1f[f]; lg[c] = ln_g[f]; lb[c] = ln_b[f];
    }
    __syncthreads();

    // degree count (one thread per edge)
    if (tid < 64) atomicAdd(&g_deg[jj_s[tid]], 1.0f);

    // h = b1 + rbf @ Wr (K=32)
    float acc[4][8];
#pragma unroll
    for (int r = 0; r < 4; ++r)
#pragma unroll
        for (int c = 0; c < 8; ++c) acc[r][c] = b1r[c];

#pragma unroll 4
    for (int k = 0; k < RR; ++k) {
        float a[4];
#pragma unroll
        for (int r = 0; r < 4; ++r) a[r] = rbfs[(ty * 4 + r) * 36 + k];
        float4 w0 = Wr4[k * 32 + tx * 2];
        float4 w1 = Wr4[k * 32 + tx * 2 + 1];
        float w[8] = {w0.x, w0.y, w0.z, w0.w, w1.x, w1.y, w1.z, w1.w};
#pragma unroll
        for (int r = 0; r < 4; ++r)
#pragma unroll
            for (int c = 0; c < 8; ++c) acc[r][c] = fmaf(a[r], w[c], acc[r][c]);
    }

    // + P[i] + Q[j] gather, LN, GELU, atomic scatter into g_G[j]
    const float4* pq4 = (const float4*)g_PQ;
#pragma unroll
    for (int r = 0; r < 4; ++r) {
        int e = ty * 4 + r;
        int i = ii_s[e], j = jj_s[e];
        float4 p0 = pq4[i * 64 + tx * 2];
        float4 p1 = pq4[i * 64 + tx * 2 + 1];
        float4 q0 = pq4[j * 64 + 32 + tx * 2];
        float4 q1 = pq4[j * 64 + 32 + tx * 2 + 1];
        acc[r][0] += p0.x + q0.x; acc[r][1] += p0.y + q0.y;
        acc[r][2] += p0.z + q0.z; acc[r][3] += p0.w + q0.w;
        acc[r][4] += p1.x + q1.x; acc[r][5] += p1.y + q1.y;
        acc[r][6] += p1.z + q1.z; acc[r][7] += p1.w + q1.w;

        float s = 0.f;
#pragma unroll
        for (int c = 0; c < 8; ++c) s += acc[r][c];
#pragma unroll
        for (int m = 1; m < 16; m <<= 1) s += __shfl_xor_sync(0xffffffffu, s, m);
        float mu = s * (1.f / FF);
        float v = 0.f;
#pragma unroll
        for (int c = 0; c < 8; ++c) { float d = acc[r][c] - mu; v += d * d; }
#pragma unroll
        for (int m = 1; m < 16; m <<= 1) v += __shfl_xor_sync(0xffffffffu, v, m);
        float inv = rsqrtf(v * (1.f / FF) + 1e-5f);

        float o[8];
#pragma unroll
        for (int c = 0; c < 8; ++c) {
            float h = (acc[r][c] - mu) * inv * lg[c] + lb[c];
            o[c] = h * normcdff(h);              // exact gelu
        }
        float* dst = &g_G[j * FF + tx * 8];
        atomicAdd((float4*)dst,       make_float4(o[0], o[1], o[2], o[3]));
        atomicAdd((float4*)(dst + 4), make_float4(o[4], o[5], o[6], o[7]));
    }
}

// ---------------- output kernel: out = G @ M^T + deg * bm ----------------
#define C_TN 64
#define C_PA 132
#define C_PW 260

__global__ __launch_bounds__(256, 1)
void out_kernel(float* __restrict__ out) {
    extern __shared__ float sm[];
    float* aggs = sm;                    // 64 x 132
    float* Wt = sm + C_TN * C_PA;        // 128 x 260 ([k][h])
    int tid = threadIdx.x;
    int tx = tid & 31, ty = tid >> 5;
    int n0 = blockIdx.x * C_TN;

    float4* ag4 = (float4*)aggs;
    const float4* g4 = (const float4*)g_G;
    for (int idx = tid; idx < C_TN * 32; idx += 256) {
        int nl = idx >> 5, q = idx & 31;
        int n = n0 + nl;
        ag4[nl * 33 + q] = (n < NN) ? g4[n * 32 + q] : make_float4(0.f, 0.f, 0.f, 0.f);
    }
    float4* Wt4s = (float4*)Wt;
    const float4* mt4 = (const float4*)g_Mt;
    for (int idx = tid; idx < FF * 64; idx += 256) {
        int row = idx >> 6, q = idx & 63;
        Wt4s[row * 65 + q] = mt4[row * 64 + q];
    }
    float bmr[8];
#pragma unroll
    for (int c = 0; c < 8; ++c) bmr[c] = g_bm[tx * 8 + c];
    __syncthreads();

    float acc[8][8];
#pragma unroll
    for (int r = 0; r < 8; ++r)
#pragma unroll
        for (int c = 0; c < 8; ++c) acc[r][c] = 0.f;

    const float4* Wt4 = (const float4*)Wt;
    for (int k = 0; k < FF; ++k) {
        float a[8];
#pragma unroll
        for (int r = 0; r < 8; ++r) a[r] = aggs[(ty * 8 + r) * C_PA + k];
        float4 w0 = Wt4[k * 65 + tx * 2];
        float4 w1 = Wt4[k * 65 + tx * 2 + 1];
        float w[8] = {w0.x, w0.y, w0.z, w0.w, w1.x, w1.y, w1.z, w1.w};
#pragma unroll
        for (int r = 0; r < 8; ++r)
#pragma unroll
            for (int c = 0; c < 8; ++c) acc[r][c] = fmaf(a[r], w[c], acc[r][c]);
    }

#pragma unroll
    for (int r = 0; r < 8; ++r) {
        int n = n0 + ty * 8 + r;
        if (n < NN) {
            float d = g_deg[n];
            float4* dst = (float4*)&out[n * HH + tx * 8];
            dst[0] = make_float4(acc[r][0] + d * bmr[0], acc[r][1] + d * bmr[1],
                                 acc[r][2] + d * bmr[2], acc[r][3] + d * bmr[3]);
            dst[1] = make_float4(acc[r][4] + d * bmr[4], acc[r][5] + d * bmr[5],
                                 acc[r][6] + d * bmr[6], acc[r][7] + d * bmr[7]);
        }
    }
}

// ---------------- launch ----------------
extern "C" void kernel_launch(void* const* d_in, const int* in_sizes, int n_in,
                              void* d_out, int out_size) {
    const float* x      = (const float*)d_in[0];
    const float* rbf    = (const float*)d_in[1];
    const int*   eidx   = (const int*)d_in[2];
    const float* ntm_w  = (const float*)d_in[3];
    const float* ntm_b  = (const float*)d_in[4];
    const float* rtm_w  = (const float*)d_in[5];
    const float* rtm_b  = (const float*)d_in[6];
    const float* norm_g = (const float*)d_in[7];
    const float* norm_b = (const float*)d_in[8];
    const float* l1_w   = (const float*)d_in[9];
    const float* l1_b   = (const float*)d_in[10];
    const float* ln_g   = (const float*)d_in[11];
    const float* ln_b   = (const float*)d_in[12];
    const float* l2_w   = (const float*)d_in[13];
    const float* l2_b   = (const float*)d_in[14];
    const float* mtn_w  = (const float*)d_in[15];
    float* out = (float*)d_out;

    const int smem_node = (A_TN * A_PX + HH * A_PW) * 4;
    const int smem_pq   = (P_TN * P_PX + FF * 256) * 4;
    const int smem_out  = (C_TN * C_PA + FF * C_PW) * 4;

    cudaFuncSetAttribute(node_kernel, cudaFuncAttributeMaxDynamicSharedMemorySize, smem_node);
    cudaFuncSetAttribute(pq_kernel,   cudaFuncAttributeMaxDynamicSharedMemorySize, smem_pq);
    cudaFuncSetAttribute(out_kernel,  cudaFuncAttributeMaxDynamicSharedMemorySize, smem_out);

    zero_kernel<<<2048, 256>>>();
    prep_kernel<<<FF, 128>>>(l1_w, l1_b, rtm_w, rtm_b);
    prep2_kernel<<<HH, 128>>>(mtn_w, l2_w, l2_b);
    node_kernel<<<(NN + A_TN - 1) / A_TN, 256, smem_node>>>(x, ntm_w, ntm_b, norm_g, norm_b);
    pq_kernel<<<(NN + P_TN - 1) / P_TN, 512, smem_pq>>>();
    edge_kernel<<<EE / 64, 256>>>(rbf, eidx, ln_g, ln_b);
    out_kernel<<<(NN + C_TN - 1) / C_TN, 256, smem_out>>>(out);
}

// round 8
// speedup vs baseline: 4.6485x; 1.1279x over previous
#include <cuda_runtime.h>
#include <cuda_bf16.h>
#include <math.h>
#include <stdint.h>

#define NN 50000
#define EE 800000
#define HH 256
#define FF 128
#define RR 32

// ---------------- persistent device scratch ----------------
__device__ float g_xf[NN * FF];        // LN(node_to_message(x))
__device__ float g_PQ[NN * 256];       // per-node P (0:128) and Q (128:256)
__device__ float g_G[NN * FF];         // segment-sum of GELU outputs
__device__ float g_deg[NN];            // in-degree
__device__ float g_Wpq[FF * 256];      // [k][f']
__device__ float g_b1f[FF];            // folded GEMM1 bias
__device__ float g_Mt[FF * HH];        // (mtn_w @ l2_w) stored [k][h]
__device__ float g_bm[HH];             // mtn_w @ l2_b
__device__ __nv_bfloat16 g_Wrt_hi[FF * RR];  // folded rbf weight, [f][r], hi
__device__ __nv_bfloat16 g_Wrt_lo[FF * RR];  // lo

// ---------------- ptx helpers ----------------
__device__ __forceinline__ uint32_t smem_u32(const void* p) {
    uint32_t a;
    asm("{ .reg .u64 t; cvta.to.shared.u64 t, %1; cvt.u32.u64 %0, t; }" : "=r"(a) : "l"(p));
    return a;
}
__device__ __forceinline__ void ldsm_x4(uint32_t& r0, uint32_t& r1, uint32_t& r2, uint32_t& r3,
                                        uint32_t addr) {
    asm volatile("ldmatrix.sync.aligned.m8n8.x4.shared.b16 {%0,%1,%2,%3}, [%4];"
                 : "=r"(r0), "=r"(r1), "=r"(r2), "=r"(r3) : "r"(addr));
}
__device__ __forceinline__ void mma16816(float* c, const uint32_t* a, const uint32_t* b) {
    asm volatile(
        "mma.sync.aligned.m16n8k16.row.col.f32.bf16.bf16.f32 "
        "{%0,%1,%2,%3}, {%4,%5,%6,%7}, {%8,%9}, {%0,%1,%2,%3};"
        : "+f"(c[0]), "+f"(c[1]), "+f"(c[2]), "+f"(c[3])
        : "r"(a[0]), "r"(a[1]), "r"(a[2]), "r"(a[3]), "r"(b[0]), "r"(b[1]));
}

// ---------------- prep ----------------
__global__ void prep_kernel(const float* __restrict__ l1_w, const float* __restrict__ l1_b,
                            const float* __restrict__ rtm_w, const float* __restrict__ rtm_b) {
    int f = blockIdx.x;      // 128
    int t = threadIdx.x;     // 128
    g_Wpq[t * 256 + f]       = l1_w[f * 384 + t];
    g_Wpq[t * 256 + 128 + f] = l1_w[f * 384 + 128 + t];
    if (t < RR) {
        float s = 0.f;
        for (int c = 0; c < FF; ++c)
            s += l1_w[f * 384 + 256 + c] * rtm_w[c * RR + t];
        __nv_bfloat16 hi = __float2bfloat16_rn(s);
        g_Wrt_hi[f * RR + t] = hi;
        g_Wrt_lo[f * RR + t] = __float2bfloat16_rn(s - __bfloat162float(hi));
    } else if (t == RR) {
        float s = l1_b[f];
        for (int c = 0; c < FF; ++c)
            s += l1_w[f * 384 + 256 + c] * rtm_b[c];
        g_b1f[f] = s;
    }
}

__global__ void prep2_kernel(const float* __restrict__ mtn_w, const float* __restrict__ l2_w,
                             const float* __restrict__ l2_b) {
    __shared__ float mrow[FF];
    int h = blockIdx.x;      // 256
    int k = threadIdx.x;     // 128
    mrow[k] = mtn_w[h * FF + k];
    __syncthreads();
    float s = 0.f;
    for (int f = 0; f < FF; ++f)
        s = fmaf(mrow[f], l2_w[f * FF + k], s);
    g_Mt[k * HH + h] = s;
    if (k == 0) {
        float b = 0.f;
        for (int f = 0; f < FF; ++f)
            b = fmaf(mrow[f], l2_b[f], b);
        g_bm[h] = b;
    }
}

__global__ void zero_kernel() {
    float4 z = make_float4(0.f, 0.f, 0.f, 0.f);
    float4* p = (float4*)g_G;
    int total = NN * FF / 4;
    for (int i = blockIdx.x * blockDim.x + threadIdx.x; i < total; i += gridDim.x * blockDim.x)
        p[i] = z;
    for (int i = blockIdx.x * blockDim.x + threadIdx.x; i < NN; i += gridDim.x * blockDim.x)
        g_deg[i] = 0.f;
}

// ---------------- node kernel v2: xf = LN(x @ ntm_w^T + ntm_b), 512 thr, TN=128 ---
#define A_TN 128
#define A_P 132

__global__ __launch_bounds__(512, 1)
void node_kernel(const float* __restrict__ x,
                 const float* __restrict__ ntm_w, const float* __restrict__ ntm_b,
                 const float* __restrict__ norm_g, const float* __restrict__ norm_b) {
    extern __shared__ float sm[];
    float* xs = sm;                      // 128 x 132 (K chunk)
    float* Ws = sm + A_TN * A_P;         // 128 x 132 ([k][f])
    int tid = threadIdx.x;
    int tx = tid & 15, ty = tid >> 4;    // tx: 16 f-groups of 8, ty: 32 node-groups of 4
    int n0 = blockIdx.x * A_TN;

    float bb[8], gg[8], be[8];
#pragma unroll
    for (int c = 0; c < 8; ++c) {
        int f = tx * 8 + c;
        bb[c] = ntm_b[f]; gg[c] = norm_g[f]; be[c] = norm_b[f];
    }

    float acc[4][8];
#pragma unroll
    for (int r = 0; r < 4; ++r)
#pragma unroll
        for (int c = 0; c < 8; ++c) acc[r][c] = bb[c];

    float4* xs4 = (float4*)xs;
    const float4* x4 = (const float4*)x;
    const float4* w4 = (const float4*)ntm_w;
    const float4* Ws4 = (const float4*)Ws;

    for (int kc = 0; kc < HH; kc += 128) {
        __syncthreads();
        for (int idx = tid; idx < A_TN * 32; idx += 512) {
            int nl = idx >> 5, q = idx & 31;
            int n = n0 + nl;
            xs4[nl * 33 + q] = (n < NN) ? x4[n * 64 + kc / 4 + q] : make_float4(0.f, 0.f, 0.f, 0.f);
        }
        for (int idx = tid; idx < FF * 32; idx += 512) {
            int f = idx >> 5, kq = (idx & 31) * 4;
            float4 v = w4[f * 64 + kc / 4 + (idx & 31)];
            Ws[(kq + 0) * A_P + f] = v.x;
            Ws[(kq + 1) * A_P + f] = v.y;
            Ws[(kq + 2) * A_P + f] = v.z;
            Ws[(kq + 3) * A_P + f] = v.w;
        }
        __syncthreads();
        for (int k = 0; k < 128; ++k) {
            float a[4];
#pragma unroll
            for (int r = 0; r < 4; ++r) a[r] = xs[(ty * 4 + r) * A_P + k];
            float4 w0 = Ws4[k * 33 + tx * 2];
            float4 w1 = Ws4[k * 33 + tx * 2 + 1];
            float w[8] = {w0.x, w0.y, w0.z, w0.w, w1.x, w1.y, w1.z, w1.w};
#pragma unroll
            for (int r = 0; r < 4; ++r)
#pragma unroll
                for (int c = 0; c < 8; ++c) acc[r][c] = fmaf(a[r], w[c], acc[r][c]);
        }
    }

#pragma unroll
    for (int r = 0; r < 4; ++r) {
        float s = 0.f;
#pragma unroll
        for (int c = 0; c < 8; ++c) s += acc[r][c];
#pragma unroll
        for (int m = 1; m < 16; m <<= 1) s += __shfl_xor_sync(0xffffffffu, s, m);
        float mu = s * (1.f / FF);
        float v = 0.f;
#pragma unroll
        for (int c = 0; c < 8; ++c) { float d = acc[r][c] - mu; v += d * d; }
#pragma unroll
        for (int m = 1; m < 16; m <<= 1) v += __shfl_xor_sync(0xffffffffu, v, m);
        float inv = rsqrtf(v * (1.f / FF) + 1e-5f);
        int n = n0 + ty * 4 + r;
        if (n < NN) {
            float o[8];
#pragma unroll
            for (int c = 0; c < 8; ++c) o[c] = (acc[r][c] - mu) * inv * gg[c] + be[c];
            float4* dst = (float4*)&g_xf[n * FF + tx * 8];
            dst[0] = make_float4(o[0], o[1], o[2], o[3]);
            dst[1] = make_float4(o[4], o[5], o[6], o[7]);
        }
    }
}

// ---------------- pq kernel: PQ = xf @ [W1a | W1b] ----------------
#define P_TN 128
#define P_PX 132

__global__ __launch_bounds__(512, 1)
void pq_kernel() {
    extern __shared__ float sm[];
    float* ts = sm;
    float* Wp = sm + P_TN * P_PX;
    int tid = threadIdx.x;
    int tx = tid & 31, ty = tid >> 5;
    int n0 = blockIdx.x * P_TN;

    float4* ts4 = (float4*)ts;
    const float4* xf4 = (const float4*)g_xf;
    for (int idx = tid; idx < P_TN * 32; idx += 512) {
        int nl = idx >> 5, q = idx & 31;
        int n = n0 + nl;
        ts4[nl * 33 + q] = (n < NN) ? xf4[n * 32 + q] : make_float4(0.f, 0.f, 0.f, 0.f);
    }
    float4* Wp4 = (float4*)Wp;
    const float4* gW4 = (const float4*)g_Wpq;
    for (int idx = tid; idx < FF * 256 / 4; idx += 512)
        Wp4[idx] = gW4[idx];
    __syncthreads();

    float acc[8][8];
#pragma unroll
    for (int r = 0; r < 8; ++r)
#pragma unroll
        for (int c = 0; c < 8; ++c) acc[r][c] = 0.f;

    for (int k = 0; k < FF; ++k) {
        float a[8];
#pragma unroll
        for (int r = 0; r < 8; ++r) a[r] = ts[(ty * 8 + r) * P_PX + k];
        float4 w0 = Wp4[k * 64 + tx * 2];
        float4 w1 = Wp4[k * 64 + tx * 2 + 1];
        float w[8] = {w0.x, w0.y, w0.z, w0.w, w1.x, w1.y, w1.z, w1.w};
#pragma unroll
        for (int r = 0; r < 8; ++r)
#pragma unroll
            for (int c = 0; c < 8; ++c) acc[r][c] = fmaf(a[r], w[c], acc[r][c]);
    }

#pragma unroll
    for (int r = 0; r < 8; ++r) {
        int n = n0 + ty * 8 + r;
        if (n < NN) {
            float4* dst = (float4*)&g_PQ[n * 256 + tx * 8];
            dst[0] = make_float4(acc[r][0], acc[r][1], acc[r][2], acc[r][3]);
            dst[1] = make_float4(acc[r][4], acc[r][5], acc[r][6], acc[r][7]);
        }
    }
}

// ---------------- edge kernel v3: mma rbf-GEMM + LN + GELU + scatter --------------
// 512 threads, 128 edges/CTA. smem byte offsets:
#define EO_R    0          // 128 x 132 fp32 = 67584
#define EO_AHI  67584      // 128 x 40 bf16 = 10240
#define EO_ALO  77824
#define EO_BHI  88064      // 128 f x 40 bf16
#define EO_BLO  98304
#define EO_II   108544
#define EO_JJ   109056
#define E_SMEM  109568

__global__ __launch_bounds__(512, 1)
void edge_kernel(const float* __restrict__ rbf, const int* __restrict__ edge_index,
                 const float* __restrict__ ln_g, const float* __restrict__ ln_b) {
    extern __shared__ char sma[];
    uint32_t sbase = smem_u32(sma);
    float* R = (float*)(sma + EO_R);
    int* ii_s = (int*)(sma + EO_II);
    int* jj_s = (int*)(sma + EO_JJ);

    int tid = threadIdx.x;
    int wid = tid >> 5, lane = tid & 31;
    int tx = tid & 15, ty = tid >> 4;
    int e0 = blockIdx.x * 128;

    if (tid < 128) ii_s[tid] = edge_index[e0 + tid];
    else if (tid < 256) jj_s[tid - 128] = edge_index[EE + e0 + (tid - 128)];

    // rbf tile -> bf16 hi/lo, pitch 40 elems (80 B)
    {
        int e = tid >> 2, ks = (tid & 3) * 8;
        const float4* rbf4 = (const float4*)rbf;
        float4 v0 = rbf4[(e0 + e) * 8 + (tid & 3) * 2];
        float4 v1 = rbf4[(e0 + e) * 8 + (tid & 3) * 2 + 1];
        float vv[8] = {v0.x, v0.y, v0.z, v0.w, v1.x, v1.y, v1.z, v1.w};
        uint32_t hw[4], lw[4];
#pragma unroll
        for (int c = 0; c < 4; ++c) {
            __nv_bfloat16 h0 = __float2bfloat16_rn(vv[c * 2]);
            __nv_bfloat16 h1 = __float2bfloat16_rn(vv[c * 2 + 1]);
            __nv_bfloat162 hh = __halves2bfloat162(h0, h1);
            __nv_bfloat162 ll = __halves2bfloat162(
                __float2bfloat16_rn(vv[c * 2]     - __bfloat162float(h0)),
                __float2bfloat16_rn(vv[c * 2 + 1] - __bfloat162float(h1)));
            hw[c] = *(uint32_t*)&hh;
            lw[c] = *(uint32_t*)&ll;
        }
        *(uint4*)(sma + EO_AHI + e * 80 + ks * 2) = make_uint4(hw[0], hw[1], hw[2], hw[3]);
        *(uint4*)(sma + EO_ALO + e * 80 + ks * 2) = make_uint4(lw[0], lw[1], lw[2], lw[3]);
    }
    // Wrt hi/lo: [f][k] 32 bf16 per row = 4 uint4
    {
        const uint4* gh = (const uint4*)g_Wrt_hi;
        const uint4* gl = (const uint4*)g_Wrt_lo;
        if (tid < 512) {
            int f = tid >> 2, q = tid & 3;
            *(uint4*)(sma + EO_BHI + f * 80 + q * 16) = gh[tid];
            *(uint4*)(sma + EO_BLO + f * 80 + q * 16) = gl[tid];
        }
    }
    __syncthreads();

    if (tid < 128) atomicAdd(&g_deg[jj_s[tid]], 1.0f);

    // ---- mma: R = rbf @ Wrt^T (3 bf16 products) ----
    {
        int mrow0 = (wid >> 1) * 16;
        int nhalf = (wid & 1) * 64;
        float c[8][4];
#pragma unroll
        for (int nt = 0; nt < 8; ++nt)
#pragma unroll
            for (int q = 0; q < 4; ++q) c[nt][q] = 0.f;

        int arow = mrow0 + (lane & 15);
        int acolh = (lane >> 4) * 8;
        int brlo = ((lane & 7) | ((lane & 16) >> 1));
        int bcolh = ((lane >> 3) & 1) * 8;

#pragma unroll
        for (int kb = 0; kb < 32; kb += 16) {
            uint32_t ah[4], al[4];
            ldsm_x4(ah[0], ah[1], ah[2], ah[3],
                    sbase + EO_AHI + (uint32_t)(arow * 40 + kb + acolh) * 2);
            ldsm_x4(al[0], al[1], al[2], al[3],
                    sbase + EO_ALO + (uint32_t)(arow * 40 + kb + acolh) * 2);
            uint32_t bh[16], bl[16];
#pragma unroll
            for (int nb = 0; nb < 4; ++nb) {
                int brow = nhalf + nb * 16 + brlo;
                ldsm_x4(bh[nb * 4], bh[nb * 4 + 1], bh[nb * 4 + 2], bh[nb * 4 + 3],
                        sbase + EO_BHI + (uint32_t)(brow * 40 + kb + bcolh) * 2);
                ldsm_x4(bl[nb * 4], bl[nb * 4 + 1], bl[nb * 4 + 2], bl[nb * 4 + 3],
                        sbase + EO_BLO + (uint32_t)(brow * 40 + kb + bcolh) * 2);
            }
#pragma unroll
            for (int nt = 0; nt < 8; ++nt) {
                mma16816(c[nt], ah, bh + 2 * nt);
                mma16816(c[nt], ah, bl + 2 * nt);
                mma16816(c[nt], al, bh + 2 * nt);
            }
        }
        // store C to R
        int lr = lane >> 2, lc = (lane & 3) * 2;
#pragma unroll
        for (int nt = 0; nt < 8; ++nt) {
            int col = nhalf + nt * 8 + lc;
            *(float2*)&R[(mrow0 + lr) * 132 + col]     = make_float2(c[nt][0], c[nt][1]);
            *(float2*)&R[(mrow0 + 8 + lr) * 132 + col] = make_float2(c[nt][2], c[nt][3]);
        }
    }

    float b1r[8], lg[8], lb[8];
#pragma unroll
    for (int c = 0; c < 8; ++c) {
        int f = tx * 8 + c;
        b1r[c] = g_b1f[f]; lg[c] = ln_g[f]; lb[c] = ln_b[f];
    }
    __syncthreads();

    // ---- phase C: acc = R + b1 + P[i] + Q[j]; LN; GELU; scatter ----
    const float4* pq4 = (const float4*)g_PQ;
#pragma unroll
    for (int r = 0; r < 4; ++r) {
        int e = ty * 4 + r;
        int i = ii_s[e], j = jj_s[e];
        float4 r0 = *(float4*)&R[e * 132 + tx * 8];
        float4 r1 = *(float4*)&R[e * 132 + tx * 8 + 4];
        float4 p0 = pq4[i * 64 + tx * 2];
        float4 p1 = pq4[i * 64 + tx * 2 + 1];
        float4 q0 = pq4[j * 64 + 32 + tx * 2];
        float4 q1 = pq4[j * 64 + 32 + tx * 2 + 1];
        float acc[8];
        acc[0] = b1r[0] + r0.x + p0.x + q0.x; acc[1] = b1r[1] + r0.y + p0.y + q0.y;
        acc[2] = b1r[2] + r0.z + p0.z + q0.z; acc[3] = b1r[3] + r0.w + p0.w + q0.w;
        acc[4] = b1r[4] + r1.x + p1.x + q1.x; acc[5] = b1r[5] + r1.y + p1.y + q1.y;
        acc[6] = b1r[6] + r1.z + p1.z + q1.z; acc[7] = b1r[7] + r1.w + p1.w + q1.w;

        float s = 0.f;
#pragma unroll
        for (int c = 0; c < 8; ++c) s += acc[c];
#pragma unroll
        for (int m = 1; m < 16; m <<= 1) s += __shfl_xor_sync(0xffffffffu, s, m);
        float mu = s * (1.f / FF);
        float v = 0.f;
#pragma unroll
        for (int c = 0; c < 8; ++c) { float d = acc[c] - mu; v += d * d; }
#pragma unroll
        for (int m = 1; m < 16; m <<= 1) v += __shfl_xor_sync(0xffffffffu, v, m);
        float inv = rsqrtf(v * (1.f / FF) + 1e-5f);

        float o[8];
#pragma unroll
        for (int c = 0; c < 8; ++c) {
            float h = (acc[c] - mu) * inv * lg[c] + lb[c];
            o[c] = h * normcdff(h);
        }
        float* dst = &g_G[j * FF + tx * 8];
        atomicAdd((float4*)dst,       make_float4(o[0], o[1], o[2], o[3]));
        atomicAdd((float4*)(dst + 4), make_float4(o[4], o[5], o[6], o[7]));
    }
}

// ---------------- output kernel v2: out = G @ M^T + deg * bm, 512 thr, TN=128 -----
#define C_TN 128
#define C_PA 132
#define C_PW 260

__global__ __launch_bounds__(512, 1)
void out_kernel(float* __restrict__ out) {
    extern __shared__ float sm[];
    float* aggs = sm;                    // 128 x 132
    float* Wt = sm + C_TN * C_PA;        // 64 x 260 chunk ([k][h])
    int tid = threadIdx.x;
    int tx = tid & 31, ty = tid >> 5;    // tx: 32 h-groups of 8, ty: 16 node-groups of 8
    int n0 = blockIdx.x * C_TN;

    float4* ag4 = (float4*)aggs;
    const float4* g4 = (const float4*)g_G;
    for (int idx = tid; idx < C_TN * 32; idx += 512) {
        int nl = idx >> 5, q = idx & 31;
        int n = n0 + nl;
        ag4[nl * 33 + q] = (n < NN) ? g4[n * 32 + q] : make_float4(0.f, 0.f, 0.f, 0.f);
    }
    float bmr[8];
#pragma unroll
    for (int c = 0; c < 8; ++c) bmr[c] = g_bm[tx * 8 + c];

    float acc[8][8];
#pragma unroll
    for (int r = 0; r < 8; ++r)
#pragma unroll
        for (int c = 0; c < 8; ++c) acc[r][c] = 0.f;

    float4* Wt4 = (float4*)Wt;
    const float4* mt4 = (const float4*)g_Mt;
    for (int kc = 0; kc < FF; kc += 64) {
        __syncthreads();
        for (int idx = tid; idx < 64 * 64; idx += 512) {
            int k = idx >> 6, q = idx & 63;
            Wt4[k * 65 + q] = mt4[(kc + k) * 64 + q];
        }
        __syncthreads();
        for (int k = 0; k < 64; ++k) {
            float a[8];
#pragma unroll
            for (int r = 0; r < 8; ++r) a[r] = aggs[(ty * 8 + r) * C_PA + kc + k];
            float4 w0 = Wt4[k * 65 + tx * 2];
            float4 w1 = Wt4[k * 65 + tx * 2 + 1];
            float w[8] = {w0.x, w0.y, w0.z, w0.w, w1.x, w1.y, w1.z, w1.w};
#pragma unroll
            for (int r = 0; r < 8; ++r)
#pragma unroll
                for (int c = 0; c < 8; ++c) acc[r][c] = fmaf(a[r], w[c], acc[r][c]);
        }
    }

#pragma unroll
    for (int r = 0; r < 8; ++r) {
        int n = n0 + ty * 8 + r;
        if (n < NN) {
            float d = g_deg[n];
            float4* dst = (float4*)&out[n * HH + tx * 8];
            dst[0] = make_float4(acc[r][0] + d * bmr[0], acc[r][1] + d * bmr[1],
                                 acc[r][2] + d * bmr[2], acc[r][3] + d * bmr[3]);
            dst[1] = make_float4(acc[r][4] + d * bmr[4], acc[r][5] + d * bmr[5],
                                 acc[r][6] + d * bmr[6], acc[r][7] + d * bmr[7]);
        }
    }
}

// ---------------- launch ----------------
extern "C" void kernel_launch(void* const* d_in, const int* in_sizes, int n_in,
                              void* d_out, int out_size) {
    const float* x      = (const float*)d_in[0];
    const float* rbf    = (const float*)d_in[1];
    const int*   eidx   = (const int*)d_in[2];
    const float* ntm_w  = (const float*)d_in[3];
    const float* ntm_b  = (const float*)d_in[4];
    const float* rtm_w  = (const float*)d_in[5];
    const float* rtm_b  = (const float*)d_in[6];
    const float* norm_g = (const float*)d_in[7];
    const float* norm_b = (const float*)d_in[8];
    const float* l1_w   = (const float*)d_in[9];
    const float* l1_b   = (const float*)d_in[10];
    const float* ln_g   = (const float*)d_in[11];
    const float* ln_b   = (const float*)d_in[12];
    const float* l2_w   = (const float*)d_in[13];
    const float* l2_b   = (const float*)d_in[14];
    const float* mtn_w  = (const float*)d_in[15];
    float* out = (float*)d_out;

    const int smem_node = (A_TN * A_P + FF * A_P) * 4;             // 135168
    const int smem_pq   = (P_TN * P_PX + FF * 256) * 4;            // 198656
    const int smem_out  = (C_TN * C_PA + 64 * C_PW) * 4;           // 134144

    cudaFuncSetAttribute(node_kernel, cudaFuncAttributeMaxDynamicSharedMemorySize, smem_node);
    cudaFuncSetAttribute(pq_kernel,   cudaFuncAttributeMaxDynamicSharedMemorySize, smem_pq);
    cudaFuncSetAttribute(edge_kernel, cudaFuncAttributeMaxDynamicSharedMemorySize, E_SMEM);
    cudaFuncSetAttribute(out_kernel,  cudaFuncAttributeMaxDynamicSharedMemorySize, smem_out);

    zero_kernel<<<2048, 256>>>();
    prep_kernel<<<FF, 128>>>(l1_w, l1_b, rtm_w, rtm_b);
    prep2_kernel<<<HH, 128>>>(mtn_w, l2_w, l2_b);
    node_kernel<<<(NN + A_TN - 1) / A_TN, 512, smem_node>>>(x, ntm_w, ntm_b, norm_g, norm_b);
    pq_kernel<<<(NN + P_TN - 1) / P_TN, 512, smem_pq>>>();
    edge_kernel<<<EE / 128, 512, E_SMEM>>>(rbf, eidx, ln_g, ln_b);
    out_kernel<<<(NN + C_TN - 1) / C_TN, 512, smem_out>>>(out);
}

// round 9
// speedup vs baseline: 5.5167x; 1.1868x over previous
#include <cuda_runtime.h>
#include <cuda_bf16.h>
#include <math.h>
#include <stdint.h>

#define NN 50000
#define EE 800000
#define HH 256
#define FF 128
#define RR 32

// ---------------- persistent device scratch ----------------
__device__ float g_xf[NN * FF];        // LN(node_to_message(x))
__device__ float g_PQ[NN * 256];       // per-node P (0:128) and Q (128:256)
__device__ float g_G[NN * FF];         // segment-sum of GELU outputs
__device__ float g_deg[NN];            // in-degree
__device__ float g_Wpq[FF * 256];      // [k][f']
__device__ float g_b1f[FF];            // folded GEMM1 bias
__device__ float g_Mt[FF * HH];        // (mtn_w @ l2_w) stored [k][h]
__device__ float g_bm[HH];             // mtn_w @ l2_b
__device__ __nv_bfloat16 g_Wrt_hi[FF * RR];  // folded rbf weight, [f][r], hi
__device__ __nv_bfloat16 g_Wrt_lo[FF * RR];  // lo

// ---------------- ptx helpers ----------------
__device__ __forceinline__ uint32_t smem_u32(const void* p) {
    uint32_t a;
    asm("{ .reg .u64 t; cvta.to.shared.u64 t, %1; cvt.u32.u64 %0, t; }" : "=r"(a) : "l"(p));
    return a;
}
__device__ __forceinline__ void ldsm_x4(uint32_t& r0, uint32_t& r1, uint32_t& r2, uint32_t& r3,
                                        uint32_t addr) {
    asm volatile("ldmatrix.sync.aligned.m8n8.x4.shared.b16 {%0,%1,%2,%3}, [%4];"
                 : "=r"(r0), "=r"(r1), "=r"(r2), "=r"(r3) : "r"(addr));
}
__device__ __forceinline__ void mma16816(float* c, const uint32_t* a, const uint32_t* b) {
    asm volatile(
        "mma.sync.aligned.m16n8k16.row.col.f32.bf16.bf16.f32 "
        "{%0,%1,%2,%3}, {%4,%5,%6,%7}, {%8,%9}, {%0,%1,%2,%3};"
        : "+f"(c[0]), "+f"(c[1]), "+f"(c[2]), "+f"(c[3])
        : "r"(a[0]), "r"(a[1]), "r"(a[2]), "r"(a[3]), "r"(b[0]), "r"(b[1]));
}

// ---------------- prep ----------------
__global__ void prep_kernel(const float* __restrict__ l1_w, const float* __restrict__ l1_b,
                            const float* __restrict__ rtm_w, const float* __restrict__ rtm_b) {
    int f = blockIdx.x;      // 128
    int t = threadIdx.x;     // 128
    g_Wpq[t * 256 + f]       = l1_w[f * 384 + t];
    g_Wpq[t * 256 + 128 + f] = l1_w[f * 384 + 128 + t];
    if (t < RR) {
        float s = 0.f;
        for (int c = 0; c < FF; ++c)
            s += l1_w[f * 384 + 256 + c] * rtm_w[c * RR + t];
        __nv_bfloat16 hi = __float2bfloat16_rn(s);
        g_Wrt_hi[f * RR + t] = hi;
        g_Wrt_lo[f * RR + t] = __float2bfloat16_rn(s - __bfloat162float(hi));
    } else if (t == RR) {
        float s = l1_b[f];
        for (int c = 0; c < FF; ++c)
            s += l1_w[f * 384 + 256 + c] * rtm_b[c];
        g_b1f[f] = s;
    }
}

__global__ void prep2_kernel(const float* __restrict__ mtn_w, const float* __restrict__ l2_w,
                             const float* __restrict__ l2_b) {
    __shared__ float mrow[FF];
    int h = blockIdx.x;      // 256
    int k = threadIdx.x;     // 128
    mrow[k] = mtn_w[h * FF + k];
    __syncthreads();
    float s = 0.f;
    for (int f = 0; f < FF; ++f)
        s = fmaf(mrow[f], l2_w[f * FF + k], s);
    g_Mt[k * HH + h] = s;
    if (k == 0) {
        float b = 0.f;
        for (int f = 0; f < FF; ++f)
            b = fmaf(mrow[f], l2_b[f], b);
        g_bm[h] = b;
    }
}

__global__ void zero_kernel() {
    float4 z = make_float4(0.f, 0.f, 0.f, 0.f);
    float4* p = (float4*)g_G;
    int total = NN * FF / 4;
    for (int i = blockIdx.x * blockDim.x + threadIdx.x; i < total; i += gridDim.x * blockDim.x)
        p[i] = z;
    for (int i = blockIdx.x * blockDim.x + threadIdx.x; i < NN; i += gridDim.x * blockDim.x)
        g_deg[i] = 0.f;
}

// ---------------- node kernel v3: 8x8 blocking, TN=256, K-chunks of 64 ----------
#define A_TN 256
#define A_KC 64
#define A_PX 68     // xs pitch (64 + 4)
#define A_PW 132    // Ws pitch

__global__ __launch_bounds__(512, 1)
void node_kernel(const float* __restrict__ x,
                 const float* __restrict__ ntm_w, const float* __restrict__ ntm_b,
                 const float* __restrict__ norm_g, const float* __restrict__ norm_b) {
    extern __shared__ float sm[];
    float* xs = sm;                      // 256 x 68
    float* Ws = sm + A_TN * A_PX;        // 64 x 132 ([k][f])
    int tid = threadIdx.x;
    int tx = tid & 15, ty = tid >> 4;    // tx: 16 f-groups of 8, ty: 32 node-groups of 8
    int n0 = blockIdx.x * A_TN;

    float bb[8], gg[8], be[8];
#pragma unroll
    for (int c = 0; c < 8; ++c) {
        int f = tx * 8 + c;
        bb[c] = ntm_b[f]; gg[c] = norm_g[f]; be[c] = norm_b[f];
    }

    float acc[8][8];
#pragma unroll
    for (int r = 0; r < 8; ++r)
#pragma unroll
        for (int c = 0; c < 8; ++c) acc[r][c] = bb[c];

    float4* xs4 = (float4*)xs;
    const float4* x4 = (const float4*)x;
    const float4* w4 = (const float4*)ntm_w;
    const float4* Ws4 = (const float4*)Ws;

    for (int kc = 0; kc < HH; kc += A_KC) {
        __syncthreads();
        // x chunk: 256 nodes x 64 k = 16 float4 per node
        for (int idx = tid; idx < A_TN * 16; idx += 512) {
            int nl = idx >> 4, q = idx & 15;
            int n = n0 + nl;
            xs4[nl * 17 + q] = (n < NN) ? x4[n * 64 + kc / 4 + q] : make_float4(0.f, 0.f, 0.f, 0.f);
        }
        // weight chunk transposed: [k][f]
        for (int idx = tid; idx < FF * 16; idx += 512) {
            int f = idx >> 4, kq = idx & 15;
            float4 v = w4[f * 64 + kc / 4 + kq];
            Ws[(kq * 4 + 0) * A_PW + f] = v.x;
            Ws[(kq * 4 + 1) * A_PW + f] = v.y;
            Ws[(kq * 4 + 2) * A_PW + f] = v.z;
            Ws[(kq * 4 + 3) * A_PW + f] = v.w;
        }
        __syncthreads();
        for (int k = 0; k < A_KC; ++k) {
            float a[8];
#pragma unroll
            for (int r = 0; r < 8; ++r) a[r] = xs[(ty * 8 + r) * A_PX + k];
            float4 w0 = Ws4[k * 33 + tx * 2];
            float4 w1 = Ws4[k * 33 + tx * 2 + 1];
            float w[8] = {w0.x, w0.y, w0.z, w0.w, w1.x, w1.y, w1.z, w1.w};
#pragma unroll
            for (int r = 0; r < 8; ++r)
#pragma unroll
                for (int c = 0; c < 8; ++c) acc[r][c] = fmaf(a[r], w[c], acc[r][c]);
        }
    }

#pragma unroll
    for (int r = 0; r < 8; ++r) {
        float s = 0.f;
#pragma unroll
        for (int c = 0; c < 8; ++c) s += acc[r][c];
#pragma unroll
        for (int m = 1; m < 16; m <<= 1) s += __shfl_xor_sync(0xffffffffu, s, m);
        float mu = s * (1.f / FF);
        float v = 0.f;
#pragma unroll
        for (int c = 0; c < 8; ++c) { float d = acc[r][c] - mu; v += d * d; }
#pragma unroll
        for (int m = 1; m < 16; m <<= 1) v += __shfl_xor_sync(0xffffffffu, v, m);
        float inv = rsqrtf(v * (1.f / FF) + 1e-5f);
        int n = n0 + ty * 8 + r;
        if (n < NN) {
            float o[8];
#pragma unroll
            for (int c = 0; c < 8; ++c) o[c] = (acc[r][c] - mu) * inv * gg[c] + be[c];
            float4* dst = (float4*)&g_xf[n * FF + tx * 8];
            dst[0] = make_float4(o[0], o[1], o[2], o[3]);
            dst[1] = make_float4(o[4], o[5], o[6], o[7]);
        }
    }
}

// ---------------- pq kernel: PQ = xf @ [W1a | W1b] ----------------
#define P_TN 128
#define P_PX 132

__global__ __launch_bounds__(512, 1)
void pq_kernel() {
    extern __shared__ float sm[];
    float* ts = sm;
    float* Wp = sm + P_TN * P_PX;
    int tid = threadIdx.x;
    int tx = tid & 31, ty = tid >> 5;
    int n0 = blockIdx.x * P_TN;

    float4* ts4 = (float4*)ts;
    const float4* xf4 = (const float4*)g_xf;
    for (int idx = tid; idx < P_TN * 32; idx += 512) {
        int nl = idx >> 5, q = idx & 31;
        int n = n0 + nl;
        ts4[nl * 33 + q] = (n < NN) ? xf4[n * 32 + q] : make_float4(0.f, 0.f, 0.f, 0.f);
    }
    float4* Wp4 = (float4*)Wp;
    const float4* gW4 = (const float4*)g_Wpq;
    for (int idx = tid; idx < FF * 256 / 4; idx += 512)
        Wp4[idx] = gW4[idx];
    __syncthreads();

    float acc[8][8];
#pragma unroll
    for (int r = 0; r < 8; ++r)
#pragma unroll
        for (int c = 0; c < 8; ++c) acc[r][c] = 0.f;

    for (int k = 0; k < FF; ++k) {
        float a[8];
#pragma unroll
        for (int r = 0; r < 8; ++r) a[r] = ts[(ty * 8 + r) * P_PX + k];
        float4 w0 = Wp4[k * 64 + tx * 2];
        float4 w1 = Wp4[k * 64 + tx * 2 + 1];
        float w[8] = {w0.x, w0.y, w0.z, w0.w, w1.x, w1.y, w1.z, w1.w};
#pragma unroll
        for (int r = 0; r < 8; ++r)
#pragma unroll
            for (int c = 0; c < 8; ++c) acc[r][c] = fmaf(a[r], w[c], acc[r][c]);
    }

#pragma unroll
    for (int r = 0; r < 8; ++r) {
        int n = n0 + ty * 8 + r;
        if (n < NN) {
            float4* dst = (float4*)&g_PQ[n * 256 + tx * 8];
            dst[0] = make_float4(acc[r][0], acc[r][1], acc[r][2], acc[r][3]);
            dst[1] = make_float4(acc[r][4], acc[r][5], acc[r][6], acc[r][7]);
        }
    }
}

// ---------------- edge kernel v4: 256 thr / 64 edges / 3 CTAs per SM --------------
// smem byte offsets:
#define EO_R    0          // 64 x 132 fp32 = 33792
#define EO_AHI  33792      // 64 x 40 bf16 = 5120
#define EO_ALO  38912
#define EO_BHI  44032      // 128 x 40 bf16 = 10240
#define EO_BLO  54272
#define EO_II   64512      // 64 ints
#define EO_JJ   64768
#define E_SMEM  65024

__global__ __launch_bounds__(256, 3)
void edge_kernel(const float* __restrict__ rbf, const int* __restrict__ edge_index,
                 const float* __restrict__ ln_g, const float* __restrict__ ln_b) {
    extern __shared__ char sma[];
    uint32_t sbase = smem_u32(sma);
    float* R = (float*)(sma + EO_R);
    int* ii_s = (int*)(sma + EO_II);
    int* jj_s = (int*)(sma + EO_JJ);

    int tid = threadIdx.x;
    int wid = tid >> 5, lane = tid & 31;
    int tx = tid & 15, ty = tid >> 4;          // tx: 16 f-groups of 8, ty: 16 e-groups of 4
    int e0 = blockIdx.x * 64;

    if (tid < 64) ii_s[tid] = edge_index[e0 + tid];
    else if (tid < 128) jj_s[tid - 64] = edge_index[EE + e0 + (tid - 64)];

    // rbf tile -> bf16 hi/lo, pitch 40 elems (80 B). 64 edges x 4 k-groups of 8.
    {
        int e = tid >> 2, ks = (tid & 3) * 8;
        const float4* rbf4 = (const float4*)rbf;
        float4 v0 = rbf4[(e0 + e) * 8 + (tid & 3) * 2];
        float4 v1 = rbf4[(e0 + e) * 8 + (tid & 3) * 2 + 1];
        float vv[8] = {v0.x, v0.y, v0.z, v0.w, v1.x, v1.y, v1.z, v1.w};
        uint32_t hw[4], lw[4];
#pragma unroll
        for (int c = 0; c < 4; ++c) {
            __nv_bfloat16 h0 = __float2bfloat16_rn(vv[c * 2]);
            __nv_bfloat16 h1 = __float2bfloat16_rn(vv[c * 2 + 1]);
            __nv_bfloat162 hh = __halves2bfloat162(h0, h1);
            __nv_bfloat162 ll = __halves2bfloat162(
                __float2bfloat16_rn(vv[c * 2]     - __bfloat162float(h0)),
                __float2bfloat16_rn(vv[c * 2 + 1] - __bfloat162float(h1)));
            hw[c] = *(uint32_t*)&hh;
            lw[c] = *(uint32_t*)&ll;
        }
        *(uint4*)(sma + EO_AHI + e * 80 + ks * 2) = make_uint4(hw[0], hw[1], hw[2], hw[3]);
        *(uint4*)(sma + EO_ALO + e * 80 + ks * 2) = make_uint4(lw[0], lw[1], lw[2], lw[3]);
    }
    // Wrt hi/lo: [f][k] 32 bf16 per row = 4 uint4; 512 uint4 over 256 threads
    {
        const uint4* gh = (const uint4*)g_Wrt_hi;
        const uint4* gl = (const uint4*)g_Wrt_lo;
        for (int idx = tid; idx < 512; idx += 256) {
            int f = idx >> 2, q = idx & 3;
            *(uint4*)(sma + EO_BHI + f * 80 + q * 16) = gh[idx];
            *(uint4*)(sma + EO_BLO + f * 80 + q * 16) = gl[idx];
        }
    }
    __syncthreads();

    if (tid < 64) atomicAdd(&g_deg[jj_s[tid]], 1.0f);

    // ---- mma: R = rbf @ Wrt^T (3 bf16 products). 8 warps: 4 M-groups x 2 N-halves.
    {
        int mrow0 = (wid >> 1) * 16;
        int nhalf = (wid & 1) * 64;
        float c[8][4];
#pragma unroll
        for (int nt = 0; nt < 8; ++nt)
#pragma unroll
            for (int q = 0; q < 4; ++q) c[nt][q] = 0.f;

        int arow = mrow0 + (lane & 15);
        int acolh = (lane >> 4) * 8;
        int brlo = ((lane & 7) | ((lane & 16) >> 1));
        int bcolh = ((lane >> 3) & 1) * 8;

#pragma unroll
        for (int kb = 0; kb < 32; kb += 16) {
            uint32_t ah[4], al[4];
            ldsm_x4(ah[0], ah[1], ah[2], ah[3],
                    sbase + EO_AHI + (uint32_t)(arow * 40 + kb + acolh) * 2);
            ldsm_x4(al[0], al[1], al[2], al[3],
                    sbase + EO_ALO + (uint32_t)(arow * 40 + kb + acolh) * 2);
#pragma unroll
            for (int nb = 0; nb < 4; ++nb) {
                int brow = nhalf + nb * 16 + brlo;
                uint32_t bh[4], bl[4];
                ldsm_x4(bh[0], bh[1], bh[2], bh[3],
                        sbase + EO_BHI + (uint32_t)(brow * 40 + kb + bcolh) * 2);
                ldsm_x4(bl[0], bl[1], bl[2], bl[3],
                        sbase + EO_BLO + (uint32_t)(brow * 40 + kb + bcolh) * 2);
                mma16816(c[nb * 2],     ah, bh);
                mma16816(c[nb * 2],     ah, bl);
                mma16816(c[nb * 2],     al, bh);
                mma16816(c[nb * 2 + 1], ah, bh + 2);
                mma16816(c[nb * 2 + 1], ah, bl + 2);
                mma16816(c[nb * 2 + 1], al, bh + 2);
            }
        }
        int lr = lane >> 2, lc = (lane & 3) * 2;
#pragma unroll
        for (int nt = 0; nt < 8; ++nt) {
            int col = nhalf + nt * 8 + lc;
            *(float2*)&R[(mrow0 + lr) * 132 + col]     = make_float2(c[nt][0], c[nt][1]);
            *(float2*)&R[(mrow0 + 8 + lr) * 132 + col] = make_float2(c[nt][2], c[nt][3]);
        }
    }

    float b1r[8], lg[8], lb[8];
#pragma unroll
    for (int c = 0; c < 8; ++c) {
        int f = tx * 8 + c;
        b1r[c] = g_b1f[f]; lg[c] = ln_g[f]; lb[c] = ln_b[f];
    }
    __syncthreads();

    // ---- phase C: acc = R + b1 + P[i] + Q[j]; LN; GELU; scatter ----
    const float4* pq4 = (const float4*)g_PQ;
#pragma unroll
    for (int r = 0; r < 4; ++r) {
        int e = ty * 4 + r;
        int i = ii_s[e], j = jj_s[e];
        float4 r0 = *(float4*)&R[e * 132 + tx * 8];
        float4 r1 = *(float4*)&R[e * 132 + tx * 8 + 4];
        float4 p0 = pq4[i * 64 + tx * 2];
        float4 p1 = pq4[i * 64 + tx * 2 + 1];
        float4 q0 = pq4[j * 64 + 32 + tx * 2];
        float4 q1 = pq4[j * 64 + 32 + tx * 2 + 1];
        float acc[8];
        acc[0] = b1r[0] + r0.x + p0.x + q0.x; acc[1] = b1r[1] + r0.y + p0.y + q0.y;
        acc[2] = b1r[2] + r0.z + p0.z + q0.z; acc[3] = b1r[3] + r0.w + p0.w + q0.w;
        acc[4] = b1r[4] + r1.x + p1.x + q1.x; acc[5] = b1r[5] + r1.y + p1.y + q1.y;
        acc[6] = b1r[6] + r1.z + p1.z + q1.z; acc[7] = b1r[7] + r1.w + p1.w + q1.w;

        float s = 0.f;
#pragma unroll
        for (int c = 0; c < 8; ++c) s += acc[c];
#pragma unroll
        for (int m = 1; m < 16; m <<= 1) s += __shfl_xor_sync(0xffffffffu, s, m);
        float mu = s * (1.f / FF);
        float v = 0.f;
#pragma unroll
        for (int c = 0; c < 8; ++c) { float d = acc[c] - mu; v += d * d; }
#pragma unroll
        for (int m = 1; m < 16; m <<= 1) v += __shfl_xor_sync(0xffffffffu, v, m);
        float inv = rsqrtf(v * (1.f / FF) + 1e-5f);

        float o[8];
#pragma unroll
        for (int c = 0; c < 8; ++c) {
            float h = (acc[c] - mu) * inv * lg[c] + lb[c];
            o[c] = 0.5f * h * (1.0f + erff(h * 0.70710678118654752f));  // exact gelu
        }
        float* dst = &g_G[j * FF + tx * 8];
        atomicAdd((float4*)dst,       make_float4(o[0], o[1], o[2], o[3]));
        atomicAdd((float4*)(dst + 4), make_float4(o[4], o[5], o[6], o[7]));
    }
}

// ---------------- output kernel: out = G @ M^T + deg * bm, 512 thr, TN=128 --------
#define C_TN 128
#define C_PA 132
#define C_PW 260

__global__ __launch_bounds__(512, 1)
void out_kernel(float* __restrict__ out) {
    extern __shared__ float sm[];
    float* aggs = sm;                    // 128 x 132
    float* Wt = sm + C_TN * C_PA;        // 64 x 260 chunk ([k][h])
    int tid = threadIdx.x;
    int tx = tid & 31, ty = tid >> 5;
    int n0 = blockIdx.x * C_TN;

    float4* ag4 = (float4*)aggs;
    const float4* g4 = (const float4*)g_G;
    for (int idx = tid; idx < C_TN * 32; idx += 512) {
        int nl = idx >> 5, q = idx & 31;
        int n = n0 + nl;
        ag4[nl * 33 + q] = (n < NN) ? g4[n * 32 + q] : make_float4(0.f, 0.f, 0.f, 0.f);
    }
    float bmr[8];
#pragma unroll
    for (int c = 0; c < 8; ++c) bmr[c] = g_bm[tx * 8 + c];

    float acc[8][8];
#pragma unroll
    for (int r = 0; r < 8; ++r)
#pragma unroll
        for (int c = 0; c < 8; ++c) acc[r][c] = 0.f;

    float4* Wt4 = (float4*)Wt;
    const float4* mt4 = (const float4*)g_Mt;
    for (int kc = 0; kc < FF; kc += 64) {
        __syncthreads();
        for (int idx = tid; idx < 64 * 64; idx += 512) {
            int k = idx >> 6, q = idx & 63;
            Wt4[k * 65 + q] = mt4[(kc + k) * 64 + q];
        }
        __syncthreads();
        for (int k = 0; k < 64; ++k) {
            float a[8];
#pragma unroll
            for (int r = 0; r < 8; ++r) a[r] = aggs[(ty * 8 + r) * C_PA + kc + k];
            float4 w0 = Wt4[k * 65 + tx * 2];
            float4 w1 = Wt4[k * 65 + tx * 2 + 1];
            float w[8] = {w0.x, w0.y, w0.z, w0.w, w1.x, w1.y, w1.z, w1.w};
#pragma unroll
            for (int r = 0; r < 8; ++r)
#pragma unroll
                for (int c = 0; c < 8; ++c) acc[r][c] = fmaf(a[r], w[c], acc[r][c]);
        }
    }

#pragma unroll
    for (int r = 0; r < 8; ++r) {
        int n = n0 + ty * 8 + r;
        if (n < NN) {
            float d = g_deg[n];
            float4* dst = (float4*)&out[n * HH + tx * 8];
            dst[0] = make_float4(acc[r][0] + d * bmr[0], acc[r][1] + d * bmr[1],
                                 acc[r][2] + d * bmr[2], acc[r][3] + d * bmr[3]);
            dst[1] = make_float4(acc[r][4] + d * bmr[4], acc[r][5] + d * bmr[5],
                                 acc[r][6] + d * bmr[6], acc[r][7] + d * bmr[7]);
        }
    }
}

// ---------------- launch ----------------
extern "C" void kernel_launch(void* const* d_in, const int* in_sizes, int n_in,
                              void* d_out, int out_size) {
    const float* x      = (const float*)d_in[0];
    const float* rbf    = (const float*)d_in[1];
    const int*   eidx   = (const int*)d_in[2];
    const float* ntm_w  = (const float*)d_in[3];
    const float* ntm_b  = (const float*)d_in[4];
    const float* rtm_w  = (const float*)d_in[5];
    const float* rtm_b  = (const float*)d_in[6];
    const float* norm_g = (const float*)d_in[7];
    const float* norm_b = (const float*)d_in[8];
    const float* l1_w   = (const float*)d_in[9];
    const float* l1_b   = (const float*)d_in[10];
    const float* ln_g   = (const float*)d_in[11];
    const float* ln_b   = (const float*)d_in[12];
    const float* l2_w   = (const float*)d_in[13];
    const float* l2_b   = (const float*)d_in[14];
    const float* mtn_w  = (const float*)d_in[15];
    float* out = (float*)d_out;

    const int smem_node = (A_TN * A_PX + A_KC * A_PW) * 4;         // 103424
    const int smem_pq   = (P_TN * P_PX + FF * 256) * 4;            // 198656
    const int smem_out  = (C_TN * C_PA + 64 * C_PW) * 4;           // 134144

    cudaFuncSetAttribute(node_kernel, cudaFuncAttributeMaxDynamicSharedMemorySize, smem_node);
    cudaFuncSetAttribute(pq_kernel,   cudaFuncAttributeMaxDynamicSharedMemorySize, smem_pq);
    cudaFuncSetAttribute(edge_kernel, cudaFuncAttributeMaxDynamicSharedMemorySize, E_SMEM);
    cudaFuncSetAttribute(out_kernel,  cudaFuncAttributeMaxDynamicSharedMemorySize, smem_out);

    zero_kernel<<<2048, 256>>>();
    prep_kernel<<<FF, 128>>>(l1_w, l1_b, rtm_w, rtm_b);
    prep2_kernel<<<HH, 128>>>(mtn_w, l2_w, l2_b);
    node_kernel<<<(NN + A_TN - 1) / A_TN, 512, smem_node>>>(x, ntm_w, ntm_b, norm_g, norm_b);
    pq_kernel<<<(NN + P_TN - 1) / P_TN, 512, smem_pq>>>();
    edge_kernel<<<EE / 64, 256, E_SMEM>>>(rbf, eidx, ln_g, ln_b);
    out_kernel<<<(NN + C_TN - 1) / C_TN, 512, smem_out>>>(out);
}

// round 10
// speedup vs baseline: 7.4770x; 1.3553x over previous
#include <cuda_runtime.h>
#include <cuda_bf16.h>
#include <math.h>
#include <stdint.h>

#define NN 50000
#define EE 800000
#define HH 256
#define FF 128
#define RR 32

// ---------------- persistent device scratch ----------------
__device__ __nv_bfloat16 g_xf_hi[NN * FF];   // LN(node_to_message(x)), hi
__device__ __nv_bfloat16 g_xf_lo[NN * FF];   // lo
__device__ float g_PQ[NN * 256];             // per-node P (0:128) and Q (128:256)
__device__ float g_G[NN * FF];               // segment-sum of GELU outputs
__device__ float g_deg[NN];                  // in-degree
__device__ float g_b1f[FF];                  // folded GEMM1 bias
__device__ float g_Mt[FF * HH];              // (mtn_w @ l2_w) stored [k][h]
__device__ float g_bm[HH];                   // mtn_w @ l2_b
__device__ __nv_bfloat16 g_Wrt_hi[FF * RR];  // folded rbf weight, [f][r]
__device__ __nv_bfloat16 g_Wrt_lo[FF * RR];
__device__ __nv_bfloat16 g_ntm_hi[FF * HH];  // ntm_w [f][h]
__device__ __nv_bfloat16 g_ntm_lo[FF * HH];
__device__ __nv_bfloat16 g_Wpq_hi[256 * FF]; // B for pq mma: [f'][k]
__device__ __nv_bfloat16 g_Wpq_lo[256 * FF];

// ---------------- ptx helpers ----------------
__device__ __forceinline__ uint32_t smem_u32(const void* p) {
    uint32_t a;
    asm("{ .reg .u64 t; cvta.to.shared.u64 t, %1; cvt.u32.u64 %0, t; }" : "=r"(a) : "l"(p));
    return a;
}
__device__ __forceinline__ void ldsm_x4(uint32_t& r0, uint32_t& r1, uint32_t& r2, uint32_t& r3,
                                        uint32_t addr) {
    asm volatile("ldmatrix.sync.aligned.m8n8.x4.shared.b16 {%0,%1,%2,%3}, [%4];"
                 : "=r"(r0), "=r"(r1), "=r"(r2), "=r"(r3) : "r"(addr));
}
__device__ __forceinline__ void mma16816(float* c, const uint32_t* a, const uint32_t* b) {
    asm volatile(
        "mma.sync.aligned.m16n8k16.row.col.f32.bf16.bf16.f32 "
        "{%0,%1,%2,%3}, {%4,%5,%6,%7}, {%8,%9}, {%0,%1,%2,%3};"
        : "+f"(c[0]), "+f"(c[1]), "+f"(c[2]), "+f"(c[3])
        : "r"(a[0]), "r"(a[1]), "r"(a[2]), "r"(a[3]), "r"(b[0]), "r"(b[1]));
}
// split 8 fp32 -> 4 packed bf16x2 hi words + 4 lo words
__device__ __forceinline__ void split8(const float* v, uint32_t* hw, uint32_t* lw) {
#pragma unroll
    for (int c = 0; c < 4; ++c) {
        __nv_bfloat16 h0 = __float2bfloat16_rn(v[c * 2]);
        __nv_bfloat16 h1 = __float2bfloat16_rn(v[c * 2 + 1]);
        __nv_bfloat162 hh = __halves2bfloat162(h0, h1);
        __nv_bfloat162 ll = __halves2bfloat162(
            __float2bfloat16_rn(v[c * 2]     - __bfloat162float(h0)),
            __float2bfloat16_rn(v[c * 2 + 1] - __bfloat162float(h1)));
        hw[c] = *(uint32_t*)&hh;
        lw[c] = *(uint32_t*)&ll;
    }
}

// ---------------- prep ----------------
__global__ void prep_kernel(const float* __restrict__ l1_w, const float* __restrict__ l1_b,
                            const float* __restrict__ rtm_w, const float* __restrict__ rtm_b,
                            const float* __restrict__ ntm_w) {
    int f = blockIdx.x;      // 128
    int t = threadIdx.x;     // 128
    // ntm_w [f][256] -> bf16 hi/lo
#pragma unroll
    for (int kk = 0; kk < 2; ++kk) {
        int k = t + kk * 128;
        float w = ntm_w[f * HH + k];
        __nv_bfloat16 hi = __float2bfloat16_rn(w);
        g_ntm_hi[f * HH + k] = hi;
        g_ntm_lo[f * HH + k] = __float2bfloat16_rn(w - __bfloat162float(hi));
    }
    // pq B: row f = l1a[f][:], row 128+f = l1b[f][:]
    {
        float wa = l1_w[f * 384 + t];
        __nv_bfloat16 ha = __float2bfloat16_rn(wa);
        g_Wpq_hi[f * FF + t] = ha;
        g_Wpq_lo[f * FF + t] = __float2bfloat16_rn(wa - __bfloat162float(ha));
        float wb = l1_w[f * 384 + 128 + t];
        __nv_bfloat16 hb = __float2bfloat16_rn(wb);
        g_Wpq_hi[(128 + f) * FF + t] = hb;
        g_Wpq_lo[(128 + f) * FF + t] = __float2bfloat16_rn(wb - __bfloat162float(hb));
    }
    if (t < RR) {
        float s = 0.f;
        for (int c = 0; c < FF; ++c)
            s += l1_w[f * 384 + 256 + c] * rtm_w[c * RR + t];
        __nv_bfloat16 hi = __float2bfloat16_rn(s);
        g_Wrt_hi[f * RR + t] = hi;
        g_Wrt_lo[f * RR + t] = __float2bfloat16_rn(s - __bfloat162float(hi));
    } else if (t == RR) {
        float s = l1_b[f];
        for (int c = 0; c < FF; ++c)
            s += l1_w[f * 384 + 256 + c] * rtm_b[c];
        g_b1f[f] = s;
    }
}

__global__ void prep2_kernel(const float* __restrict__ mtn_w, const float* __restrict__ l2_w,
                             const float* __restrict__ l2_b) {
    __shared__ float mrow[FF];
    int h = blockIdx.x;      // 256
    int k = threadIdx.x;     // 128
    mrow[k] = mtn_w[h * FF + k];
    __syncthreads();
    float s = 0.f;
    for (int f = 0; f < FF; ++f)
        s = fmaf(mrow[f], l2_w[f * FF + k], s);
    g_Mt[k * HH + h] = s;
    if (k == 0) {
        float b = 0.f;
        for (int f = 0; f < FF; ++f)
            b = fmaf(mrow[f], l2_b[f], b);
        g_bm[h] = b;
    }
}

__global__ void zero_kernel() {
    float4 z = make_float4(0.f, 0.f, 0.f, 0.f);
    float4* p = (float4*)g_G;
    int total = NN * FF / 4;
    for (int i = blockIdx.x * blockDim.x + threadIdx.x; i < total; i += gridDim.x * blockDim.x)
        p[i] = z;
    for (int i = blockIdx.x * blockDim.x + threadIdx.x; i < NN; i += gridDim.x * blockDim.x)
        g_deg[i] = 0.f;
}

// ---------------- node mma kernel: xf = LN(x @ ntm^T + b), bf16 hi/lo out ---------
// 256 threads, 128 nodes/CTA. smem: X hi/lo + W hi/lo (pitch 72 bf16), R aliases.
#define NO_XHI 0
#define NO_XLO 18432
#define NO_WHI 36864
#define NO_WLO 55296
#define N_SMEM 73728

__global__ __launch_bounds__(256, 1)
void node_kernel(const float* __restrict__ x,
                 const float* __restrict__ ntm_b,
                 const float* __restrict__ norm_g, const float* __restrict__ norm_b) {
    extern __shared__ char sma[];
    uint32_t sbase = smem_u32(sma);
    float* R = (float*)sma;              // [128][132] fp32, aliases X/W region

    int tid = threadIdx.x;
    int wid = tid >> 5, lane = tid & 31;
    int n0 = blockIdx.x * 128;

    int wm = wid >> 1, wn = wid & 1;
    int lrow = lane & 15, acolh = (lane >> 4) * 8;
    int brlo = (lane & 7) | ((lane & 16) >> 1), bcolh = ((lane >> 3) & 1) * 8;

    float c[2][8][4];
#pragma unroll
    for (int mi = 0; mi < 2; ++mi)
#pragma unroll
        for (int nt = 0; nt < 8; ++nt)
#pragma unroll
            for (int q = 0; q < 4; ++q) c[mi][nt][q] = 0.f;

    const float4* x4 = (const float4*)x;

    for (int kc = 0; kc < HH; kc += 64) {
        __syncthreads();
        // X chunk: 128 nodes x 64 k fp32 -> bf16 hi/lo (1024 groups of 8)
#pragma unroll
        for (int it = 0; it < 4; ++it) {
            int idx = tid + it * 256;
            int nl = idx >> 3, kq = idx & 7;
            int n = n0 + nl;
            float4 v0 = make_float4(0.f, 0.f, 0.f, 0.f), v1 = v0;
            if (n < NN) {
                v0 = x4[n * 64 + kc / 4 + kq * 2];
                v1 = x4[n * 64 + kc / 4 + kq * 2 + 1];
            }
            float vv[8] = {v0.x, v0.y, v0.z, v0.w, v1.x, v1.y, v1.z, v1.w};
            uint32_t hw[4], lw[4];
            split8(vv, hw, lw);
            *(uint4*)(sma + NO_XHI + nl * 144 + kq * 16) = make_uint4(hw[0], hw[1], hw[2], hw[3]);
            *(uint4*)(sma + NO_XLO + nl * 144 + kq * 16) = make_uint4(lw[0], lw[1], lw[2], lw[3]);
        }
        // W chunk (pre-split bf16): rows [f][kc..kc+64]
        const uint4* gh = (const uint4*)g_ntm_hi;
        const uint4* gl = (const uint4*)g_ntm_lo;
#pragma unroll
        for (int it = 0; it < 4; ++it) {
            int idx = tid + it * 256;
            int f = idx >> 3, q = idx & 7;
            *(uint4*)(sma + NO_WHI + f * 144 + q * 16) = gh[f * 32 + kc / 8 + q];
            *(uint4*)(sma + NO_WLO + f * 144 + q * 16) = gl[f * 32 + kc / 8 + q];
        }
        __syncthreads();
#pragma unroll
        for (int kb = 0; kb < 64; kb += 16) {
            uint32_t ah[2][4], al[2][4];
#pragma unroll
            for (int mi = 0; mi < 2; ++mi) {
                int arow = wm * 32 + mi * 16 + lrow;
                ldsm_x4(ah[mi][0], ah[mi][1], ah[mi][2], ah[mi][3],
                        sbase + NO_XHI + (uint32_t)(arow * 72 + kb + acolh) * 2);
                ldsm_x4(al[mi][0], al[mi][1], al[mi][2], al[mi][3],
                        sbase + NO_XLO + (uint32_t)(arow * 72 + kb + acolh) * 2);
            }
#pragma unroll
            for (int nb = 0; nb < 4; ++nb) {
                int brow = wn * 64 + nb * 16 + brlo;
                uint32_t bh[4], bl[4];
                ldsm_x4(bh[0], bh[1], bh[2], bh[3],
                        sbase + NO_WHI + (uint32_t)(brow * 72 + kb + bcolh) * 2);
                ldsm_x4(bl[0], bl[1], bl[2], bl[3],
                        sbase + NO_WLO + (uint32_t)(brow * 72 + kb + bcolh) * 2);
#pragma unroll
                for (int mi = 0; mi < 2; ++mi) {
                    mma16816(c[mi][nb * 2],     ah[mi], bh);
                    mma16816(c[mi][nb * 2],     ah[mi], bl);
                    mma16816(c[mi][nb * 2],     al[mi], bh);
                    mma16816(c[mi][nb * 2 + 1], ah[mi], bh + 2);
                    mma16816(c[mi][nb * 2 + 1], ah[mi], bl + 2);
                    mma16816(c[mi][nb * 2 + 1], al[mi], bh + 2);
                }
            }
        }
    }

    __syncthreads();   // mma reads done; R aliases X/W
    {
        int lr = lane >> 2, lc = (lane & 3) * 2;
#pragma unroll
        for (int mi = 0; mi < 2; ++mi) {
            int row0 = wm * 32 + mi * 16;
#pragma unroll
            for (int nt = 0; nt < 8; ++nt) {
                int col = wn * 64 + nt * 8 + lc;
                *(float2*)&R[(row0 + lr) * 132 + col]     = make_float2(c[mi][nt][0], c[mi][nt][1]);
                *(float2*)&R[(row0 + 8 + lr) * 132 + col] = make_float2(c[mi][nt][2], c[mi][nt][3]);
            }
        }
    }
    __syncthreads();

    // LN epilogue: 16x16 thread layout, 8 rows x 8 cols each
    int tx = tid & 15, ty = tid >> 4;
    float bb[8], gg[8], be[8];
#pragma unroll
    for (int cc = 0; cc < 8; ++cc) {
        int f = tx * 8 + cc;
        bb[cc] = ntm_b[f]; gg[cc] = norm_g[f]; be[cc] = norm_b[f];
    }
#pragma unroll
    for (int r = 0; r < 8; ++r) {
        int row = ty * 8 + r;
        float a[8];
        float4 a0 = *(float4*)&R[row * 132 + tx * 8];
        float4 a1 = *(float4*)&R[row * 132 + tx * 8 + 4];
        a[0] = a0.x + bb[0]; a[1] = a0.y + bb[1]; a[2] = a0.z + bb[2]; a[3] = a0.w + bb[3];
        a[4] = a1.x + bb[4]; a[5] = a1.y + bb[5]; a[6] = a1.z + bb[6]; a[7] = a1.w + bb[7];

        float s = 0.f;
#pragma unroll
        for (int cc = 0; cc < 8; ++cc) s += a[cc];
#pragma unroll
        for (int m = 1; m < 16; m <<= 1) s += __shfl_xor_sync(0xffffffffu, s, m);
        float mu = s * (1.f / FF);
        float v = 0.f;
#pragma unroll
        for (int cc = 0; cc < 8; ++cc) { float d = a[cc] - mu; v += d * d; }
#pragma unroll
        for (int m = 1; m < 16; m <<= 1) v += __shfl_xor_sync(0xffffffffu, v, m);
        float inv = rsqrtf(v * (1.f / FF) + 1e-5f);

        int n = n0 + row;
        if (n < NN) {
            float o[8];
#pragma unroll
            for (int cc = 0; cc < 8; ++cc) o[cc] = (a[cc] - mu) * inv * gg[cc] + be[cc];
            uint32_t hw[4], lw[4];
            split8(o, hw, lw);
            *(uint4*)&g_xf_hi[n * FF + tx * 8] = make_uint4(hw[0], hw[1], hw[2], hw[3]);
            *(uint4*)&g_xf_lo[n * FF + tx * 8] = make_uint4(lw[0], lw[1], lw[2], lw[3]);
        }
    }
}

// ---------------- pq mma kernel: PQ = xf @ Wpq^T, M=128/CTA, N=256, K=128 ---------
#define QO_AHI 0
#define QO_ALO 34816
#define QO_BHI 69632
#define QO_BLO 104448
#define Q_SMEM 139264

__global__ __launch_bounds__(256, 1)
void pq_kernel() {
    extern __shared__ char sma[];
    uint32_t sbase = smem_u32(sma);
    int tid = threadIdx.x;
    int wid = tid >> 5, lane = tid & 31;
    int n0 = blockIdx.x * 128;

    int wm = wid >> 1, wn = wid & 1;
    int lrow = lane & 15, acolh = (lane >> 4) * 8;
    int brlo = (lane & 7) | ((lane & 16) >> 1), bcolh = ((lane >> 3) & 1) * 8;
    int lr = lane >> 2, lc = (lane & 3) * 2;

    // load A (xf hi/lo): 128 rows x 16 uint4
    {
        const uint4* gh = (const uint4*)g_xf_hi;
        const uint4* gl = (const uint4*)g_xf_lo;
        uint4 z = make_uint4(0, 0, 0, 0);
#pragma unroll
        for (int it = 0; it < 8; ++it) {
            int idx = tid + it * 256;
            int nl = idx >> 4, q = idx & 15;
            int n = n0 + nl;
            *(uint4*)(sma + QO_AHI + nl * 272 + q * 16) = (n < NN) ? gh[n * 16 + q] : z;
            *(uint4*)(sma + QO_ALO + nl * 272 + q * 16) = (n < NN) ? gl[n * 16 + q] : z;
        }
    }

    for (int nh = 0; nh < 2; ++nh) {
        __syncthreads();
        // load B half: rows nh*128 .. +128 of g_Wpq (each row 16 uint4)
        {
            const uint4* gh = (const uint4*)g_Wpq_hi;
            const uint4* gl = (const uint4*)g_Wpq_lo;
#pragma unroll
            for (int it = 0; it < 8; ++it) {
                int idx = tid + it * 256;
                int f = idx >> 4, q = idx & 15;
                *(uint4*)(sma + QO_BHI + f * 272 + q * 16) = gh[(nh * 128 + f) * 16 + q];
                *(uint4*)(sma + QO_BLO + f * 272 + q * 16) = gl[(nh * 128 + f) * 16 + q];
            }
        }
        __syncthreads();

        float c[2][8][4];
#pragma unroll
        for (int mi = 0; mi < 2; ++mi)
#pragma unroll
            for (int nt = 0; nt < 8; ++nt)
#pragma unroll
                for (int q = 0; q < 4; ++q) c[mi][nt][q] = 0.f;

#pragma unroll
        for (int kb = 0; kb < 128; kb += 16) {
            uint32_t ah[2][4], al[2][4];
#pragma unroll
            for (int mi = 0; mi < 2; ++mi) {
                int arow = wm * 32 + mi * 16 + lrow;
                ldsm_x4(ah[mi][0], ah[mi][1], ah[mi][2], ah[mi][3],
                        sbase + QO_AHI + (uint32_t)(arow * 136 + kb + acolh) * 2);
                ldsm_x4(al[mi][0], al[mi][1], al[mi][2], al[mi][3],
                        sbase + QO_ALO + (uint32_t)(arow * 136 + kb + acolh) * 2);
            }
#pragma unroll
            for (int nb = 0; nb < 4; ++nb) {
                int brow = wn * 64 + nb * 16 + brlo;
                uint32_t bh[4], bl[4];
                ldsm_x4(bh[0], bh[1], bh[2], bh[3],
                        sbase + QO_BHI + (uint32_t)(brow * 136 + kb + bcolh) * 2);
                ldsm_x4(bl[0], bl[1], bl[2], bl[3],
                        sbase + QO_BLO + (uint32_t)(brow * 136 + kb + bcolh) * 2);
#pragma unroll
                for (int mi = 0; mi < 2; ++mi) {
                    mma16816(c[mi][nb * 2],     ah[mi], bh);
                    mma16816(c[mi][nb * 2],     ah[mi], bl);
                    mma16816(c[mi][nb * 2],     al[mi], bh);
                    mma16816(c[mi][nb * 2 + 1], ah[mi], bh + 2);
                    mma16816(c[mi][nb * 2 + 1], ah[mi], bl + 2);
                    mma16816(c[mi][nb * 2 + 1], al[mi], bh + 2);
                }
            }
        }
        // write this N-half straight to g_PQ
#pragma unroll
        for (int mi = 0; mi < 2; ++mi) {
            int row0 = n0 + wm * 32 + mi * 16;
#pragma unroll
            for (int nt = 0; nt < 8; ++nt) {
                int col = nh * 128 + wn * 64 + nt * 8 + lc;
                if (row0 + lr < NN)
                    *(float2*)&g_PQ[(row0 + lr) * 256 + col] = make_float2(c[mi][nt][0], c[mi][nt][1]);
                if (row0 + 8 + lr < NN)
                    *(float2*)&g_PQ[(row0 + 8 + lr) * 256 + col] = make_float2(c[mi][nt][2], c[mi][nt][3]);
            }
        }
    }
}

// ---------------- edge kernel: 256 thr / 64 edges / 3 CTAs per SM -----------------
#define EO_R    0          // 64 x 132 fp32 = 33792
#define EO_AHI  33792
#define EO_ALO  38912
#define EO_BHI  44032
#define EO_BLO  54272
#define EO_II   64512
#define EO_JJ   64768
#define E_SMEM  65024

__global__ __launch_bounds__(256, 3)
void edge_kernel(const float* __restrict__ rbf, const int* __restrict__ edge_index,
                 const float* __restrict__ ln_g, const float* __restrict__ ln_b) {
    extern __shared__ char sma[];
    uint32_t sbase = smem_u32(sma);
    float* R = (float*)(sma + EO_R);
    int* ii_s = (int*)(sma + EO_II);
    int* jj_s = (int*)(sma + EO_JJ);

    int tid = threadIdx.x;
    int wid = tid >> 5, lane = tid & 31;
    int tx = tid & 15, ty = tid >> 4;
    int e0 = blockIdx.x * 64;

    if (tid < 64) ii_s[tid] = edge_index[e0 + tid];
    else if (tid < 128) jj_s[tid - 64] = edge_index[EE + e0 + (tid - 64)];

    {
        int e = tid >> 2, ks = (tid & 3) * 8;
        const float4* rbf4 = (const float4*)rbf;
        float4 v0 = rbf4[(e0 + e) * 8 + (tid & 3) * 2];
        float4 v1 = rbf4[(e0 + e) * 8 + (tid & 3) * 2 + 1];
        float vv[8] = {v0.x, v0.y, v0.z, v0.w, v1.x, v1.y, v1.z, v1.w};
        uint32_t hw[4], lw[4];
        split8(vv, hw, lw);
        *(uint4*)(sma + EO_AHI + e * 80 + ks * 2) = make_uint4(hw[0], hw[1], hw[2], hw[3]);
        *(uint4*)(sma + EO_ALO + e * 80 + ks * 2) = make_uint4(lw[0], lw[1], lw[2], lw[3]);
    }
    {
        const uint4* gh = (const uint4*)g_Wrt_hi;
        const uint4* gl = (const uint4*)g_Wrt_lo;
        for (int idx = tid; idx < 512; idx += 256) {
            int f = idx >> 2, q = idx & 3;
            *(uint4*)(sma + EO_BHI + f * 80 + q * 16) = gh[idx];
            *(uint4*)(sma + EO_BLO + f * 80 + q * 16) = gl[idx];
        }
    }
    __syncthreads();

    if (tid < 64) atomicAdd(&g_deg[jj_s[tid]], 1.0f);

    {
        int mrow0 = (wid >> 1) * 16;
        int nhalf = (wid & 1) * 64;
        float c[8][4];
#pragma unroll
        for (int nt = 0; nt < 8; ++nt)
#pragma unroll
            for (int q = 0; q < 4; ++q) c[nt][q] = 0.f;

        int arow = mrow0 + (lane & 15);
        int acolh = (lane >> 4) * 8;
        int brlo = ((lane & 7) | ((lane & 16) >> 1));
        int bcolh = ((lane >> 3) & 1) * 8;

#pragma unroll
        for (int kb = 0; kb < 32; kb += 16) {
            uint32_t ah[4], al[4];
            ldsm_x4(ah[0], ah[1], ah[2], ah[3],
                    sbase + EO_AHI + (uint32_t)(arow * 40 + kb + acolh) * 2);
            ldsm_x4(al[0], al[1], al[2], al[3],
                    sbase + EO_ALO + (uint32_t)(arow * 40 + kb + acolh) * 2);
#pragma unroll
            for (int nb = 0; nb < 4; ++nb) {
                int brow = nhalf + nb * 16 + brlo;
                uint32_t bh[4], bl[4];
                ldsm_x4(bh[0], bh[1], bh[2], bh[3],
                        sbase + EO_BHI + (uint32_t)(brow * 40 + kb + bcolh) * 2);
                ldsm_x4(bl[0], bl[1], bl[2], bl[3],
                        sbase + EO_BLO + (uint32_t)(brow * 40 + kb + bcolh) * 2);
                mma16816(c[nb * 2],     ah, bh);
                mma16816(c[nb * 2],     ah, bl);
                mma16816(c[nb * 2],     al, bh);
                mma16816(c[nb * 2 + 1], ah, bh + 2);
                mma16816(c[nb * 2 + 1], ah, bl + 2);
                mma16816(c[nb * 2 + 1], al, bh + 2);
            }
        }
        int lr = lane >> 2, lc = (lane & 3) * 2;
#pragma unroll
        for (int nt = 0; nt < 8; ++nt) {
            int col = nhalf + nt * 8 + lc;
            *(float2*)&R[(mrow0 + lr) * 132 + col]     = make_float2(c[nt][0], c[nt][1]);
            *(float2*)&R[(mrow0 + 8 + lr) * 132 + col] = make_float2(c[nt][2], c[nt][3]);
        }
    }

    float b1r[8], lg[8], lb[8];
#pragma unroll
    for (int c = 0; c < 8; ++c) {
        int f = tx * 8 + c;
        b1r[c] = g_b1f[f]; lg[c] = ln_g[f]; lb[c] = ln_b[f];
    }
    __syncthreads();

    const float4* pq4 = (const float4*)g_PQ;
#pragma unroll
    for (int r = 0; r < 4; ++r) {
        int e = ty * 4 + r;
        int i = ii_s[e], j = jj_s[e];
        float4 r0 = *(float4*)&R[e * 132 + tx * 8];
        float4 r1 = *(float4*)&R[e * 132 + tx * 8 + 4];
        float4 p0 = pq4[i * 64 + tx * 2];
        float4 p1 = pq4[i * 64 + tx * 2 + 1];
        float4 q0 = pq4[j * 64 + 32 + tx * 2];
        float4 q1 = pq4[j * 64 + 32 + tx * 2 + 1];
        float acc[8];
        acc[0] = b1r[0] + r0.x + p0.x + q0.x; acc[1] = b1r[1] + r0.y + p0.y + q0.y;
        acc[2] = b1r[2] + r0.z + p0.z + q0.z; acc[3] = b1r[3] + r0.w + p0.w + q0.w;
        acc[4] = b1r[4] + r1.x + p1.x + q1.x; acc[5] = b1r[5] + r1.y + p1.y + q1.y;
        acc[6] = b1r[6] + r1.z + p1.z + q1.z; acc[7] = b1r[7] + r1.w + p1.w + q1.w;

        float s = 0.f;
#pragma unroll
        for (int c = 0; c < 8; ++c) s += acc[c];
#pragma unroll
        for (int m = 1; m < 16; m <<= 1) s += __shfl_xor_sync(0xffffffffu, s, m);
        float mu = s * (1.f / FF);
        float v = 0.f;
#pragma unroll
        for (int c = 0; c < 8; ++c) { float d = acc[c] - mu; v += d * d; }
#pragma unroll
        for (int m = 1; m < 16; m <<= 1) v += __shfl_xor_sync(0xffffffffu, v, m);
        float inv = rsqrtf(v * (1.f / FF) + 1e-5f);

        float o[8];
#pragma unroll
        for (int c = 0; c < 8; ++c) {
            float h = (acc[c] - mu) * inv * lg[c] + lb[c];
            o[c] = 0.5f * h * (1.0f + erff(h * 0.70710678118654752f));
        }
        float* dst = &g_G[j * FF + tx * 8];
        atomicAdd((float4*)dst,       make_float4(o[0], o[1], o[2], o[3]));
        atomicAdd((float4*)(dst + 4), make_float4(o[4], o[5], o[6], o[7]));
    }
}

// ---------------- output kernel: out = G @ M^T + deg * bm -------------------------
#define C_TN 128
#define C_PA 132
#define C_PW 260

__global__ __launch_bounds__(512, 1)
void out_kernel(float* __restrict__ out) {
    extern __shared__ float sm[];
    float* aggs = sm;
    float* Wt = sm + C_TN * C_PA;
    int tid = threadIdx.x;
    int tx = tid & 31, ty = tid >> 5;
    int n0 = blockIdx.x * C_TN;

    float4* ag4 = (float4*)aggs;
    const float4* g4 = (const float4*)g_G;
    for (int idx = tid; idx < C_TN * 32; idx += 512) {
        int nl = idx >> 5, q = idx & 31;
        int n = n0 + nl;
        ag4[nl * 33 + q] = (n < NN) ? g4[n * 32 + q] : make_float4(0.f, 0.f, 0.f, 0.f);
    }
    float bmr[8];
#pragma unroll
    for (int c = 0; c < 8; ++c) bmr[c] = g_bm[tx * 8 + c];

    float acc[8][8];
#pragma unroll
    for (int r = 0; r < 8; ++r)
#pragma unroll
        for (int c = 0; c < 8; ++c) acc[r][c] = 0.f;

    float4* Wt4 = (float4*)Wt;
    const float4* mt4 = (const float4*)g_Mt;
    for (int kc = 0; kc < FF; kc += 64) {
        __syncthreads();
        for (int idx = tid; idx < 64 * 64; idx += 512) {
            int k = idx >> 6, q = idx & 63;
            Wt4[k * 65 + q] = mt4[(kc + k) * 64 + q];
        }
        __syncthreads();
        for (int k = 0; k < 64; ++k) {
            float a[8];
#pragma unroll
            for (int r = 0; r < 8; ++r) a[r] = aggs[(ty * 8 + r) * C_PA + kc + k];
            float4 w0 = Wt4[k * 65 + tx * 2];
            float4 w1 = Wt4[k * 65 + tx * 2 + 1];
            float w[8] = {w0.x, w0.y, w0.z, w0.w, w1.x, w1.y, w1.z, w1.w};
#pragma unroll
            for (int r = 0; r < 8; ++r)
#pragma unroll
                for (int c = 0; c < 8; ++c) acc[r][c] = fmaf(a[r], w[c], acc[r][c]);
        }
    }

#pragma unroll
    for (int r = 0; r < 8; ++r) {
        int n = n0 + ty * 8 + r;
        if (n < NN) {
            float d = g_deg[n];
            float4* dst = (float4*)&out[n * HH + tx * 8];
            dst[0] = make_float4(acc[r][0] + d * bmr[0], acc[r][1] + d * bmr[1],
                                 acc[r][2] + d * bmr[2], acc[r][3] + d * bmr[3]);
            dst[1] = make_float4(acc[r][4] + d * bmr[4], acc[r][5] + d * bmr[5],
                                 acc[r][6] + d * bmr[6], acc[r][7] + d * bmr[7]);
        }
    }
}

// ---------------- launch ----------------
extern "C" void kernel_launch(void* const* d_in, const int* in_sizes, int n_in,
                              void* d_out, int out_size) {
    const float* x      = (const float*)d_in[0];
    const float* rbf    = (const float*)d_in[1];
    const int*   eidx   = (const int*)d_in[2];
    const float* ntm_w  = (const float*)d_in[3];
    const float* ntm_b  = (const float*)d_in[4];
    const float* rtm_w  = (const float*)d_in[5];
    const float* rtm_b  = (const float*)d_in[6];
    const float* norm_g = (const float*)d_in[7];
    const float* norm_b = (const float*)d_in[8];
    const float* l1_w   = (const float*)d_in[9];
    const float* l1_b   = (const float*)d_in[10];
    const float* ln_g   = (const float*)d_in[11];
    const float* ln_b   = (const float*)d_in[12];
    const float* l2_w   = (const float*)d_in[13];
    const float* l2_b   = (const float*)d_in[14];
    const float* mtn_w  = (const float*)d_in[15];
    float* out = (float*)d_out;

    const int smem_out = (C_TN * C_PA + 64 * C_PW) * 4;

    cudaFuncSetAttribute(node_kernel, cudaFuncAttributeMaxDynamicSharedMemorySize, N_SMEM);
    cudaFuncSetAttribute(pq_kernel,   cudaFuncAttributeMaxDynamicSharedMemorySize, Q_SMEM);
    cudaFuncSetAttribute(edge_kernel, cudaFuncAttributeMaxDynamicSharedMemorySize, E_SMEM);
    cudaFuncSetAttribute(out_kernel,  cudaFuncAttributeMaxDynamicSharedMemorySize, smem_out);

    zero_kernel<<<2048, 256>>>();
    prep_kernel<<<FF, 128>>>(l1_w, l1_b, rtm_w, rtm_b, ntm_w);
    prep2_kernel<<<HH, 128>>>(mtn_w, l2_w, l2_b);
    node_kernel<<<(NN + 127) / 128, 256, N_SMEM>>>(x, ntm_b, norm_g, norm_b);
    pq_kernel<<<(NN + 127) / 128, 256, Q_SMEM>>>();
    edge_kernel<<<EE / 64, 256, E_SMEM>>>(rbf, eidx, ln_g, ln_b);
    out_kernel<<<(NN + C_TN - 1) / C_TN, 512, smem_out>>>(out);
}

// round 11
// speedup vs baseline: 8.7838x; 1.1748x over previous
#include <cuda_runtime.h>
#include <cuda_bf16.h>
#include <math.h>
#include <stdint.h>

#define NN 50000
#define EE 800000
#define HH 256
#define FF 128
#define RR 32

// ---------------- persistent device scratch ----------------
__device__ __nv_bfloat16 g_xf_hi[NN * FF];   // LN(node_to_message(x)), hi
__device__ __nv_bfloat16 g_xf_lo[NN * FF];   // lo
__device__ float g_PQ[NN * 256];             // per-node P (0:128) and Q (128:256)
__device__ float g_G[NN * FF];               // segment-sum of GELU outputs
__device__ float g_deg[NN];                  // in-degree
__device__ float g_b1f[FF];                  // folded GEMM1 bias
__device__ float g_bm[HH];                   // mtn_w @ l2_b
__device__ __nv_bfloat16 g_Wrt_hi[FF * RR];  // folded rbf weight, [f][r]
__device__ __nv_bfloat16 g_Wrt_lo[FF * RR];
__device__ __nv_bfloat16 g_ntm_hi[FF * HH];  // ntm_w [f][h]
__device__ __nv_bfloat16 g_ntm_lo[FF * HH];
__device__ __nv_bfloat16 g_Wpq_hi[256 * FF]; // B for pq mma: [f'][k]
__device__ __nv_bfloat16 g_Wpq_lo[256 * FF];
__device__ __nv_bfloat16 g_Mo_hi[HH * FF];   // (mtn_w @ l2_w) as B: [h][k]
__device__ __nv_bfloat16 g_Mo_lo[HH * FF];

// ---------------- ptx helpers ----------------
__device__ __forceinline__ uint32_t smem_u32(const void* p) {
    uint32_t a;
    asm("{ .reg .u64 t; cvta.to.shared.u64 t, %1; cvt.u32.u64 %0, t; }" : "=r"(a) : "l"(p));
    return a;
}
__device__ __forceinline__ void ldsm_x4(uint32_t& r0, uint32_t& r1, uint32_t& r2, uint32_t& r3,
                                        uint32_t addr) {
    asm volatile("ldmatrix.sync.aligned.m8n8.x4.shared.b16 {%0,%1,%2,%3}, [%4];"
                 : "=r"(r0), "=r"(r1), "=r"(r2), "=r"(r3) : "r"(addr));
}
__device__ __forceinline__ void mma16816(float* c, const uint32_t* a, const uint32_t* b) {
    asm volatile(
        "mma.sync.aligned.m16n8k16.row.col.f32.bf16.bf16.f32 "
        "{%0,%1,%2,%3}, {%4,%5,%6,%7}, {%8,%9}, {%0,%1,%2,%3};"
        : "+f"(c[0]), "+f"(c[1]), "+f"(c[2]), "+f"(c[3])
        : "r"(a[0]), "r"(a[1]), "r"(a[2]), "r"(a[3]), "r"(b[0]), "r"(b[1]));
}
__device__ __forceinline__ void split8(const float* v, uint32_t* hw, uint32_t* lw) {
#pragma unroll
    for (int c = 0; c < 4; ++c) {
        __nv_bfloat16 h0 = __float2bfloat16_rn(v[c * 2]);
        __nv_bfloat16 h1 = __float2bfloat16_rn(v[c * 2 + 1]);
        __nv_bfloat162 hh = __halves2bfloat162(h0, h1);
        __nv_bfloat162 ll = __halves2bfloat162(
            __float2bfloat16_rn(v[c * 2]     - __bfloat162float(h0)),
            __float2bfloat16_rn(v[c * 2 + 1] - __bfloat162float(h1)));
        hw[c] = *(uint32_t*)&hh;
        lw[c] = *(uint32_t*)&ll;
    }
}

// ---------------- prep ----------------
__global__ void prep_kernel(const float* __restrict__ l1_w, const float* __restrict__ l1_b,
                            const float* __restrict__ rtm_w, const float* __restrict__ rtm_b,
                            const float* __restrict__ ntm_w) {
    int f = blockIdx.x;      // 128
    int t = threadIdx.x;     // 128
#pragma unroll
    for (int kk = 0; kk < 2; ++kk) {
        int k = t + kk * 128;
        float w = ntm_w[f * HH + k];
        __nv_bfloat16 hi = __float2bfloat16_rn(w);
        g_ntm_hi[f * HH + k] = hi;
        g_ntm_lo[f * HH + k] = __float2bfloat16_rn(w - __bfloat162float(hi));
    }
    {
        float wa = l1_w[f * 384 + t];
        __nv_bfloat16 ha = __float2bfloat16_rn(wa);
        g_Wpq_hi[f * FF + t] = ha;
        g_Wpq_lo[f * FF + t] = __float2bfloat16_rn(wa - __bfloat162float(ha));
        float wb = l1_w[f * 384 + 128 + t];
        __nv_bfloat16 hb = __float2bfloat16_rn(wb);
        g_Wpq_hi[(128 + f) * FF + t] = hb;
        g_Wpq_lo[(128 + f) * FF + t] = __float2bfloat16_rn(wb - __bfloat162float(hb));
    }
    if (t < RR) {
        float s = 0.f;
        for (int c = 0; c < FF; ++c)
            s += l1_w[f * 384 + 256 + c] * rtm_w[c * RR + t];
        __nv_bfloat16 hi = __float2bfloat16_rn(s);
        g_Wrt_hi[f * RR + t] = hi;
        g_Wrt_lo[f * RR + t] = __float2bfloat16_rn(s - __bfloat162float(hi));
    } else if (t == RR) {
        float s = l1_b[f];
        for (int c = 0; c < FF; ++c)
            s += l1_w[f * 384 + 256 + c] * rtm_b[c];
        g_b1f[f] = s;
    }
}

__global__ void prep2_kernel(const float* __restrict__ mtn_w, const float* __restrict__ l2_w,
                             const float* __restrict__ l2_b) {
    __shared__ float mrow[FF];
    int h = blockIdx.x;      // 256
    int k = threadIdx.x;     // 128
    mrow[k] = mtn_w[h * FF + k];
    __syncthreads();
    float s = 0.f;
    for (int f = 0; f < FF; ++f)
        s = fmaf(mrow[f], l2_w[f * FF + k], s);
    __nv_bfloat16 hi = __float2bfloat16_rn(s);
    g_Mo_hi[h * FF + k] = hi;
    g_Mo_lo[h * FF + k] = __float2bfloat16_rn(s - __bfloat162float(hi));
    if (k == 0) {
        float b = 0.f;
        for (int f = 0; f < FF; ++f)
            b = fmaf(mrow[f], l2_b[f], b);
        g_bm[h] = b;
    }
}

__global__ void zero_kernel() {
    float4 z = make_float4(0.f, 0.f, 0.f, 0.f);
    float4* p = (float4*)g_G;
    int total = NN * FF / 4;
    for (int i = blockIdx.x * blockDim.x + threadIdx.x; i < total; i += gridDim.x * blockDim.x)
        p[i] = z;
    for (int i = blockIdx.x * blockDim.x + threadIdx.x; i < NN; i += gridDim.x * blockDim.x)
        g_deg[i] = 0.f;
}

// ---------------- node mma kernel: xf = LN(x @ ntm^T + b), bf16 hi/lo out ---------
#define NO_XHI 0
#define NO_XLO 18432
#define NO_WHI 36864
#define NO_WLO 55296
#define N_SMEM 73728

__global__ __launch_bounds__(256, 1)
void node_kernel(const float* __restrict__ x,
                 const float* __restrict__ ntm_b,
                 const float* __restrict__ norm_g, const float* __restrict__ norm_b) {
    extern __shared__ char sma[];
    uint32_t sbase = smem_u32(sma);
    float* R = (float*)sma;              // [128][132] fp32, aliases X/W region

    int tid = threadIdx.x;
    int wid = tid >> 5, lane = tid & 31;
    int n0 = blockIdx.x * 128;

    int wm = wid >> 1, wn = wid & 1;
    int lrow = lane & 15, acolh = (lane >> 4) * 8;
    int brlo = (lane & 7) | ((lane & 16) >> 1), bcolh = ((lane >> 3) & 1) * 8;

    float c[2][8][4];
#pragma unroll
    for (int mi = 0; mi < 2; ++mi)
#pragma unroll
        for (int nt = 0; nt < 8; ++nt)
#pragma unroll
            for (int q = 0; q < 4; ++q) c[mi][nt][q] = 0.f;

    const float4* x4 = (const float4*)x;

    for (int kc = 0; kc < HH; kc += 64) {
        __syncthreads();
#pragma unroll
        for (int it = 0; it < 4; ++it) {
            int idx = tid + it * 256;
            int nl = idx >> 3, kq = idx & 7;
            int n = n0 + nl;
            float4 v0 = make_float4(0.f, 0.f, 0.f, 0.f), v1 = v0;
            if (n < NN) {
                v0 = x4[n * 64 + kc / 4 + kq * 2];
                v1 = x4[n * 64 + kc / 4 + kq * 2 + 1];
            }
            float vv[8] = {v0.x, v0.y, v0.z, v0.w, v1.x, v1.y, v1.z, v1.w};
            uint32_t hw[4], lw[4];
            split8(vv, hw, lw);
            *(uint4*)(sma + NO_XHI + nl * 144 + kq * 16) = make_uint4(hw[0], hw[1], hw[2], hw[3]);
            *(uint4*)(sma + NO_XLO + nl * 144 + kq * 16) = make_uint4(lw[0], lw[1], lw[2], lw[3]);
        }
        const uint4* gh = (const uint4*)g_ntm_hi;
        const uint4* gl = (const uint4*)g_ntm_lo;
#pragma unroll
        for (int it = 0; it < 4; ++it) {
            int idx = tid + it * 256;
            int f = idx >> 3, q = idx & 7;
            *(uint4*)(sma + NO_WHI + f * 144 + q * 16) = gh[f * 32 + kc / 8 + q];
            *(uint4*)(sma + NO_WLO + f * 144 + q * 16) = gl[f * 32 + kc / 8 + q];
        }
        __syncthreads();
#pragma unroll
        for (int kb = 0; kb < 64; kb += 16) {
            uint32_t ah[2][4], al[2][4];
#pragma unroll
            for (int mi = 0; mi < 2; ++mi) {
                int arow = wm * 32 + mi * 16 + lrow;
                ldsm_x4(ah[mi][0], ah[mi][1], ah[mi][2], ah[mi][3],
                        sbase + NO_XHI + (uint32_t)(arow * 72 + kb + acolh) * 2);
                ldsm_x4(al[mi][0], al[mi][1], al[mi][2], al[mi][3],
                        sbase + NO_XLO + (uint32_t)(arow * 72 + kb + acolh) * 2);
            }
#pragma unroll
            for (int nb = 0; nb < 4; ++nb) {
                int brow = wn * 64 + nb * 16 + brlo;
                uint32_t bh[4], bl[4];
                ldsm_x4(bh[0], bh[1], bh[2], bh[3],
                        sbase + NO_WHI + (uint32_t)(brow * 72 + kb + bcolh) * 2);
                ldsm_x4(bl[0], bl[1], bl[2], bl[3],
                        sbase + NO_WLO + (uint32_t)(brow * 72 + kb + bcolh) * 2);
#pragma unroll
                for (int mi = 0; mi < 2; ++mi) {
                    mma16816(c[mi][nb * 2],     ah[mi], bh);
                    mma16816(c[mi][nb * 2],     ah[mi], bl);
                    mma16816(c[mi][nb * 2],     al[mi], bh);
                    mma16816(c[mi][nb * 2 + 1], ah[mi], bh + 2);
                    mma16816(c[mi][nb * 2 + 1], ah[mi], bl + 2);
                    mma16816(c[mi][nb * 2 + 1], al[mi], bh + 2);
                }
            }
        }
    }

    __syncthreads();
    {
        int lr = lane >> 2, lc = (lane & 3) * 2;
#pragma unroll
        for (int mi = 0; mi < 2; ++mi) {
            int row0 = wm * 32 + mi * 16;
#pragma unroll
            for (int nt = 0; nt < 8; ++nt) {
                int col = wn * 64 + nt * 8 + lc;
                *(float2*)&R[(row0 + lr) * 132 + col]     = make_float2(c[mi][nt][0], c[mi][nt][1]);
                *(float2*)&R[(row0 + 8 + lr) * 132 + col] = make_float2(c[mi][nt][2], c[mi][nt][3]);
            }
        }
    }
    __syncthreads();

    int tx = tid & 15, ty = tid >> 4;
    float bb[8], gg[8], be[8];
#pragma unroll
    for (int cc = 0; cc < 8; ++cc) {
        int f = tx * 8 + cc;
        bb[cc] = ntm_b[f]; gg[cc] = norm_g[f]; be[cc] = norm_b[f];
    }
#pragma unroll
    for (int r = 0; r < 8; ++r) {
        int row = ty * 8 + r;
        float a[8];
        float4 a0 = *(float4*)&R[row * 132 + tx * 8];
        float4 a1 = *(float4*)&R[row * 132 + tx * 8 + 4];
        a[0] = a0.x + bb[0]; a[1] = a0.y + bb[1]; a[2] = a0.z + bb[2]; a[3] = a0.w + bb[3];
        a[4] = a1.x + bb[4]; a[5] = a1.y + bb[5]; a[6] = a1.z + bb[6]; a[7] = a1.w + bb[7];

        float s = 0.f;
#pragma unroll
        for (int cc = 0; cc < 8; ++cc) s += a[cc];
#pragma unroll
        for (int m = 1; m < 16; m <<= 1) s += __shfl_xor_sync(0xffffffffu, s, m);
        float mu = s * (1.f / FF);
        float v = 0.f;
#pragma unroll
        for (int cc = 0; cc < 8; ++cc) { float d = a[cc] - mu; v += d * d; }
#pragma unroll
        for (int m = 1; m < 16; m <<= 1) v += __shfl_xor_sync(0xffffffffu, v, m);
        float inv = rsqrtf(v * (1.f / FF) + 1e-5f);

        int n = n0 + row;
        if (n < NN) {
            float o[8];
#pragma unroll
            for (int cc = 0; cc < 8; ++cc) o[cc] = (a[cc] - mu) * inv * gg[cc] + be[cc];
            uint32_t hw[4], lw[4];
            split8(o, hw, lw);
            *(uint4*)&g_xf_hi[n * FF + tx * 8] = make_uint4(hw[0], hw[1], hw[2], hw[3]);
            *(uint4*)&g_xf_lo[n * FF + tx * 8] = make_uint4(lw[0], lw[1], lw[2], lw[3]);
        }
    }
}

// ---------------- pq mma kernel: PQ = xf @ Wpq^T, M=128/CTA, N=256, K=128 ---------
#define QO_AHI 0
#define QO_ALO 34816
#define QO_BHI 69632
#define QO_BLO 104448
#define Q_SMEM 139264

__global__ __launch_bounds__(256, 1)
void pq_kernel() {
    extern __shared__ char sma[];
    uint32_t sbase = smem_u32(sma);
    int tid = threadIdx.x;
    int wid = tid >> 5, lane = tid & 31;
    int n0 = blockIdx.x * 128;

    int wm = wid >> 1, wn = wid & 1;
    int lrow = lane & 15, acolh = (lane >> 4) * 8;
    int brlo = (lane & 7) | ((lane & 16) >> 1), bcolh = ((lane >> 3) & 1) * 8;
    int lr = lane >> 2, lc = (lane & 3) * 2;

    {
        const uint4* gh = (const uint4*)g_xf_hi;
        const uint4* gl = (const uint4*)g_xf_lo;
        uint4 z = make_uint4(0, 0, 0, 0);
#pragma unroll
        for (int it = 0; it < 8; ++it) {
            int idx = tid + it * 256;
            int nl = idx >> 4, q = idx & 15;
            int n = n0 + nl;
            *(uint4*)(sma + QO_AHI + nl * 272 + q * 16) = (n < NN) ? gh[n * 16 + q] : z;
            *(uint4*)(sma + QO_ALO + nl * 272 + q * 16) = (n < NN) ? gl[n * 16 + q] : z;
        }
    }

    for (int nh = 0; nh < 2; ++nh) {
        __syncthreads();
        {
            const uint4* gh = (const uint4*)g_Wpq_hi;
            const uint4* gl = (const uint4*)g_Wpq_lo;
#pragma unroll
            for (int it = 0; it < 8; ++it) {
                int idx = tid + it * 256;
                int f = idx >> 4, q = idx & 15;
                *(uint4*)(sma + QO_BHI + f * 272 + q * 16) = gh[(nh * 128 + f) * 16 + q];
                *(uint4*)(sma + QO_BLO + f * 272 + q * 16) = gl[(nh * 128 + f) * 16 + q];
            }
        }
        __syncthreads();

        float c[2][8][4];
#pragma unroll
        for (int mi = 0; mi < 2; ++mi)
#pragma unroll
            for (int nt = 0; nt < 8; ++nt)
#pragma unroll
                for (int q = 0; q < 4; ++q) c[mi][nt][q] = 0.f;

#pragma unroll
        for (int kb = 0; kb < 128; kb += 16) {
            uint32_t ah[2][4], al[2][4];
#pragma unroll
            for (int mi = 0; mi < 2; ++mi) {
                int arow = wm * 32 + mi * 16 + lrow;
                ldsm_x4(ah[mi][0], ah[mi][1], ah[mi][2], ah[mi][3],
                        sbase + QO_AHI + (uint32_t)(arow * 136 + kb + acolh) * 2);
                ldsm_x4(al[mi][0], al[mi][1], al[mi][2], al[mi][3],
                        sbase + QO_ALO + (uint32_t)(arow * 136 + kb + acolh) * 2);
            }
#pragma unroll
            for (int nb = 0; nb < 4; ++nb) {
                int brow = wn * 64 + nb * 16 + brlo;
                uint32_t bh[4], bl[4];
                ldsm_x4(bh[0], bh[1], bh[2], bh[3],
                        sbase + QO_BHI + (uint32_t)(brow * 136 + kb + bcolh) * 2);
                ldsm_x4(bl[0], bl[1], bl[2], bl[3],
                        sbase + QO_BLO + (uint32_t)(brow * 136 + kb + bcolh) * 2);
#pragma unroll
                for (int mi = 0; mi < 2; ++mi) {
                    mma16816(c[mi][nb * 2],     ah[mi], bh);
                    mma16816(c[mi][nb * 2],     ah[mi], bl);
                    mma16816(c[mi][nb * 2],     al[mi], bh);
                    mma16816(c[mi][nb * 2 + 1], ah[mi], bh + 2);
                    mma16816(c[mi][nb * 2 + 1], ah[mi], bl + 2);
                    mma16816(c[mi][nb * 2 + 1], al[mi], bh + 2);
                }
            }
        }
#pragma unroll
        for (int mi = 0; mi < 2; ++mi) {
            int row0 = n0 + wm * 32 + mi * 16;
#pragma unroll
            for (int nt = 0; nt < 8; ++nt) {
                int col = nh * 128 + wn * 64 + nt * 8 + lc;
                if (row0 + lr < NN)
                    *(float2*)&g_PQ[(row0 + lr) * 256 + col] = make_float2(c[mi][nt][0], c[mi][nt][1]);
                if (row0 + 8 + lr < NN)
                    *(float2*)&g_PQ[(row0 + 8 + lr) * 256 + col] = make_float2(c[mi][nt][2], c[mi][nt][3]);
            }
        }
    }
}

// ---------------- edge kernel: 256 thr / 64 edges / 3 CTAs per SM -----------------
#define EO_R    0
#define EO_AHI  33792
#define EO_ALO  38912
#define EO_BHI  44032
#define EO_BLO  54272
#define EO_II   64512
#define EO_JJ   64768
#define E_SMEM  65024

__global__ __launch_bounds__(256, 3)
void edge_kernel(const float* __restrict__ rbf, const int* __restrict__ edge_index,
                 const float* __restrict__ ln_g, const float* __restrict__ ln_b) {
    extern __shared__ char sma[];
    uint32_t sbase = smem_u32(sma);
    float* R = (float*)(sma + EO_R);
    int* ii_s = (int*)(sma + EO_II);
    int* jj_s = (int*)(sma + EO_JJ);

    int tid = threadIdx.x;
    int wid = tid >> 5, lane = tid & 31;
    int tx = tid & 15, ty = tid >> 4;
    int e0 = blockIdx.x * 64;

    if (tid < 64) ii_s[tid] = edge_index[e0 + tid];
    else if (tid < 128) jj_s[tid - 64] = edge_index[EE + e0 + (tid - 64)];

    {
        int e = tid >> 2, ks = (tid & 3) * 8;
        const float4* rbf4 = (const float4*)rbf;
        float4 v0 = rbf4[(e0 + e) * 8 + (tid & 3) * 2];
        float4 v1 = rbf4[(e0 + e) * 8 + (tid & 3) * 2 + 1];
        float vv[8] = {v0.x, v0.y, v0.z, v0.w, v1.x, v1.y, v1.z, v1.w};
        uint32_t hw[4], lw[4];
        split8(vv, hw, lw);
        *(uint4*)(sma + EO_AHI + e * 80 + ks * 2) = make_uint4(hw[0], hw[1], hw[2], hw[3]);
        *(uint4*)(sma + EO_ALO + e * 80 + ks * 2) = make_uint4(lw[0], lw[1], lw[2], lw[3]);
    }
    {
        const uint4* gh = (const uint4*)g_Wrt_hi;
        const uint4* gl = (const uint4*)g_Wrt_lo;
        for (int idx = tid; idx < 512; idx += 256) {
            int f = idx >> 2, q = idx & 3;
            *(uint4*)(sma + EO_BHI + f * 80 + q * 16) = gh[idx];
            *(uint4*)(sma + EO_BLO + f * 80 + q * 16) = gl[idx];
        }
    }
    __syncthreads();

    if (tid < 64) atomicAdd(&g_deg[jj_s[tid]], 1.0f);

    {
        int mrow0 = (wid >> 1) * 16;
        int nhalf = (wid & 1) * 64;
        float c[8][4];
#pragma unroll
        for (int nt = 0; nt < 8; ++nt)
#pragma unroll
            for (int q = 0; q < 4; ++q) c[nt][q] = 0.f;

        int arow = mrow0 + (lane & 15);
        int acolh = (lane >> 4) * 8;
        int brlo = ((lane & 7) | ((lane & 16) >> 1));
        int bcolh = ((lane >> 3) & 1) * 8;

#pragma unroll
        for (int kb = 0; kb < 32; kb += 16) {
            uint32_t ah[4], al[4];
            ldsm_x4(ah[0], ah[1], ah[2], ah[3],
                    sbase + EO_AHI + (uint32_t)(arow * 40 + kb + acolh) * 2);
            ldsm_x4(al[0], al[1], al[2], al[3],
                    sbase + EO_ALO + (uint32_t)(arow * 40 + kb + acolh) * 2);
#pragma unroll
            for (int nb = 0; nb < 4; ++nb) {
                int brow = nhalf + nb * 16 + brlo;
                uint32_t bh[4], bl[4];
                ldsm_x4(bh[0], bh[1], bh[2], bh[3],
                        sbase + EO_BHI + (uint32_t)(brow * 40 + kb + bcolh) * 2);
                ldsm_x4(bl[0], bl[1], bl[2], bl[3],
                        sbase + EO_BLO + (uint32_t)(brow * 40 + kb + bcolh) * 2);
                mma16816(c[nb * 2],     ah, bh);
                mma16816(c[nb * 2],     ah, bl);
                mma16816(c[nb * 2],     al, bh);
                mma16816(c[nb * 2 + 1], ah, bh + 2);
                mma16816(c[nb * 2 + 1], ah, bl + 2);
                mma16816(c[nb * 2 + 1], al, bh + 2);
            }
        }
        int lr = lane >> 2, lc = (lane & 3) * 2;
#pragma unroll
        for (int nt = 0; nt < 8; ++nt) {
            int col = nhalf + nt * 8 + lc;
            *(float2*)&R[(mrow0 + lr) * 132 + col]     = make_float2(c[nt][0], c[nt][1]);
            *(float2*)&R[(mrow0 + 8 + lr) * 132 + col] = make_float2(c[nt][2], c[nt][3]);
        }
    }

    float b1r[8], lg[8], lb[8];
#pragma unroll
    for (int c = 0; c < 8; ++c) {
        int f = tx * 8 + c;
        b1r[c] = g_b1f[f]; lg[c] = ln_g[f]; lb[c] = ln_b[f];
    }
    __syncthreads();

    const float4* pq4 = (const float4*)g_PQ;
#pragma unroll
    for (int r = 0; r < 4; ++r) {
        int e = ty * 4 + r;
        int i = ii_s[e], j = jj_s[e];
        float4 r0 = *(float4*)&R[e * 132 + tx * 8];
        float4 r1 = *(float4*)&R[e * 132 + tx * 8 + 4];
        float4 p0 = pq4[i * 64 + tx * 2];
        float4 p1 = pq4[i * 64 + tx * 2 + 1];
        float4 q0 = pq4[j * 64 + 32 + tx * 2];
        float4 q1 = pq4[j * 64 + 32 + tx * 2 + 1];
        float acc[8];
        acc[0] = b1r[0] + r0.x + p0.x + q0.x; acc[1] = b1r[1] + r0.y + p0.y + q0.y;
        acc[2] = b1r[2] + r0.z + p0.z + q0.z; acc[3] = b1r[3] + r0.w + p0.w + q0.w;
        acc[4] = b1r[4] + r1.x + p1.x + q1.x; acc[5] = b1r[5] + r1.y + p1.y + q1.y;
        acc[6] = b1r[6] + r1.z + p1.z + q1.z; acc[7] = b1r[7] + r1.w + p1.w + q1.w;

        float s = 0.f;
#pragma unroll
        for (int c = 0; c < 8; ++c) s += acc[c];
#pragma unroll
        for (int m = 1; m < 16; m <<= 1) s += __shfl_xor_sync(0xffffffffu, s, m);
        float mu = s * (1.f / FF);
        float v = 0.f;
#pragma unroll
        for (int c = 0; c < 8; ++c) { float d = acc[c] - mu; v += d * d; }
#pragma unroll
        for (int m = 1; m < 16; m <<= 1) v += __shfl_xor_sync(0xffffffffu, v, m);
        float inv = rsqrtf(v * (1.f / FF) + 1e-5f);

        float o[8];
#pragma unroll
        for (int c = 0; c < 8; ++c) {
            float h = (acc[c] - mu) * inv * lg[c] + lb[c];
            o[c] = 0.5f * h * (1.0f + erff(h * 0.70710678118654752f));
        }
        float* dst = &g_G[j * FF + tx * 8];
        atomicAdd((float4*)dst,       make_float4(o[0], o[1], o[2], o[3]));
        atomicAdd((float4*)(dst + 4), make_float4(o[4], o[5], o[6], o[7]));
    }
}

// ---------------- out mma kernel: out = G @ Mo^T + deg*bm, M=128/CTA, N=256, K=128
#define OO_AHI 0
#define OO_ALO 34816
#define OO_BHI 69632
#define OO_BLO 104448
#define O_SMEM 139264

__global__ __launch_bounds__(256, 1)
void out_kernel(float* __restrict__ out) {
    extern __shared__ char sma[];
    uint32_t sbase = smem_u32(sma);
    int tid = threadIdx.x;
    int wid = tid >> 5, lane = tid & 31;
    int n0 = blockIdx.x * 128;

    int wm = wid >> 1, wn = wid & 1;
    int lrow = lane & 15, acolh = (lane >> 4) * 8;
    int brlo = (lane & 7) | ((lane & 16) >> 1), bcolh = ((lane >> 3) & 1) * 8;
    int lr = lane >> 2, lc = (lane & 3) * 2;

    // A: G tile fp32 -> bf16 hi/lo in smem
    {
        const float4* g4 = (const float4*)g_G;
#pragma unroll
        for (int it = 0; it < 8; ++it) {
            int idx = tid + it * 256;
            int nl = idx >> 4, q = idx & 15;
            int n = n0 + nl;
            float4 v0 = make_float4(0.f, 0.f, 0.f, 0.f), v1 = v0;
            if (n < NN) {
                v0 = g4[n * 32 + q * 2];
                v1 = g4[n * 32 + q * 2 + 1];
            }
            float vv[8] = {v0.x, v0.y, v0.z, v0.w, v1.x, v1.y, v1.z, v1.w};
            uint32_t hw[4], lw[4];
            split8(vv, hw, lw);
            *(uint4*)(sma + OO_AHI + nl * 272 + q * 16) = make_uint4(hw[0], hw[1], hw[2], hw[3]);
            *(uint4*)(sma + OO_ALO + nl * 272 + q * 16) = make_uint4(lw[0], lw[1], lw[2], lw[3]);
        }
    }

    for (int nh = 0; nh < 2; ++nh) {
        __syncthreads();
        {
            const uint4* gh = (const uint4*)g_Mo_hi;
            const uint4* gl = (const uint4*)g_Mo_lo;
#pragma unroll
            for (int it = 0; it < 8; ++it) {
                int idx = tid + it * 256;
                int f = idx >> 4, q = idx & 15;
                *(uint4*)(sma + OO_BHI + f * 272 + q * 16) = gh[(nh * 128 + f) * 16 + q];
                *(uint4*)(sma + OO_BLO + f * 272 + q * 16) = gl[(nh * 128 + f) * 16 + q];
            }
        }
        __syncthreads();

        float c[2][8][4];
#pragma unroll
        for (int mi = 0; mi < 2; ++mi)
#pragma unroll
            for (int nt = 0; nt < 8; ++nt)
#pragma unroll
                for (int q = 0; q < 4; ++q) c[mi][nt][q] = 0.f;

#pragma unroll
        for (int kb = 0; kb < 128; kb += 16) {
            uint32_t ah[2][4], al[2][4];
#pragma unroll
            for (int mi = 0; mi < 2; ++mi) {
                int arow = wm * 32 + mi * 16 + lrow;
                ldsm_x4(ah[mi][0], ah[mi][1], ah[mi][2], ah[mi][3],
                        sbase + OO_AHI + (uint32_t)(arow * 136 + kb + acolh) * 2);
                ldsm_x4(al[mi][0], al[mi][1], al[mi][2], al[mi][3],
                        sbase + OO_ALO + (uint32_t)(arow * 136 + kb + acolh) * 2);
            }
#pragma unroll
            for (int nb = 0; nb < 4; ++nb) {
                int brow = wn * 64 + nb * 16 + brlo;
                uint32_t bh[4], bl[4];
                ldsm_x4(bh[0], bh[1], bh[2], bh[3],
                        sbase + OO_BHI + (uint32_t)(brow * 136 + kb + bcolh) * 2);
                ldsm_x4(bl[0], bl[1], bl[2], bl[3],
                        sbase + OO_BLO + (uint32_t)(brow * 136 + kb + bcolh) * 2);
#pragma unroll
                for (int mi = 0; mi < 2; ++mi) {
                    mma16816(c[mi][nb * 2],     ah[mi], bh);
                    mma16816(c[mi][nb * 2],     ah[mi], bl);
                    mma16816(c[mi][nb * 2],     al[mi], bh);
                    mma16816(c[mi][nb * 2 + 1], ah[mi], bh + 2);
                    mma16816(c[mi][nb * 2 + 1], ah[mi], bl + 2);
                    mma16816(c[mi][nb * 2 + 1], al[mi], bh + 2);
                }
            }
        }
        // epilogue: out[n][col] = c + deg[n]*bm[col]
#pragma unroll
        for (int mi = 0; mi < 2; ++mi) {
            int row0 = n0 + wm * 32 + mi * 16;
            int n1 = row0 + lr, n2 = row0 + 8 + lr;
            float d1 = (n1 < NN) ? g_deg[n1] : 0.f;
            float d2 = (n2 < NN) ? g_deg[n2] : 0.f;
#pragma unroll
            for (int nt = 0; nt < 8; ++nt) {
                int col = nh * 128 + wn * 64 + nt * 8 + lc;
                float2 bv = *(float2*)&g_bm[col];
                if (n1 < NN)
                    *(float2*)&out[n1 * HH + col] = make_float2(c[mi][nt][0] + d1 * bv.x,
                                                                c[mi][nt][1] + d1 * bv.y);
                if (n2 < NN)
                    *(float2*)&out[n2 * HH + col] = make_float2(c[mi][nt][2] + d2 * bv.x,
                                                                c[mi][nt][3] + d2 * bv.y);
            }
        }
    }
}

// ---------------- launch ----------------
extern "C" void kernel_launch(void* const* d_in, const int* in_sizes, int n_in,
                              void* d_out, int out_size) {
    const float* x      = (const float*)d_in[0];
    const float* rbf    = (const float*)d_in[1];
    const int*   eidx   = (const int*)d_in[2];
    const float* ntm_w  = (const float*)d_in[3];
    const float* ntm_b  = (const float*)d_in[4];
    const float* rtm_w  = (const float*)d_in[5];
    const float* rtm_b  = (const float*)d_in[6];
    const float* norm_g = (const float*)d_in[7];
    const float* norm_b = (const float*)d_in[8];
    const float* l1_w   = (const float*)d_in[9];
    const float* l1_b   = (const float*)d_in[10];
    const float* ln_g   = (const float*)d_in[11];
    const float* ln_b   = (const float*)d_in[12];
    const float* l2_w   = (const float*)d_in[13];
    const float* l2_b   = (const float*)d_in[14];
    const float* mtn_w  = (const float*)d_in[15];
    float* out = (float*)d_out;

    cudaFuncSetAttribute(node_kernel, cudaFuncAttributeMaxDynamicSharedMemorySize, N_SMEM);
    cudaFuncSetAttribute(pq_kernel,   cudaFuncAttributeMaxDynamicSharedMemorySize, Q_SMEM);
    cudaFuncSetAttribute(edge_kernel, cudaFuncAttributeMaxDynamicSharedMemorySize, E_SMEM);
    cudaFuncSetAttribute(out_kernel,  cudaFuncAttributeMaxDynamicSharedMemorySize, O_SMEM);

    zero_kernel<<<2048, 256>>>();
    prep_kernel<<<FF, 128>>>(l1_w, l1_b, rtm_w, rtm_b, ntm_w);
    prep2_kernel<<<HH, 128>>>(mtn_w, l2_w, l2_b);
    node_kernel<<<(NN + 127) / 128, 256, N_SMEM>>>(x, ntm_b, norm_g, norm_b);
    pq_kernel<<<(NN + 127) / 128, 256, Q_SMEM>>>();
    edge_kernel<<<EE / 64, 256, E_SMEM>>>(rbf, eidx, ln_g, ln_b);
    out_kernel<<<(NN + 127) / 128, 256, O_SMEM>>>(out);
}

// round 12
// speedup vs baseline: 8.7852x; 1.0002x over previous
#include <cuda_runtime.h>
#include <cuda_bf16.h>
#include <math.h>
#include <stdint.h>

#define NN 50000
#define EE 800000
#define HH 256
#define FF 128
#define RR 32

// ---------------- persistent device scratch ----------------
__device__ __nv_bfloat16 g_xf_hi[NN * FF];
__device__ __nv_bfloat16 g_xf_lo[NN * FF];
__device__ float g_PQ[NN * 256];
__device__ float g_G[NN * FF];
__device__ float g_deg[NN];
__device__ float g_b1f[FF];
__device__ float g_bm[HH];
__device__ __nv_bfloat16 g_Wrt_hi[FF * RR];
__device__ __nv_bfloat16 g_Wrt_lo[FF * RR];
__device__ __nv_bfloat16 g_ntm_hi[FF * HH];
__device__ __nv_bfloat16 g_ntm_lo[FF * HH];
__device__ __nv_bfloat16 g_Wpq_hi[256 * FF];
__device__ __nv_bfloat16 g_Wpq_lo[256 * FF];
__device__ __nv_bfloat16 g_Mo_hi[HH * FF];
__device__ __nv_bfloat16 g_Mo_lo[HH * FF];

// ---------------- ptx helpers ----------------
__device__ __forceinline__ uint32_t smem_u32(const void* p) {
    uint32_t a;
    asm("{ .reg .u64 t; cvta.to.shared.u64 t, %1; cvt.u32.u64 %0, t; }" : "=r"(a) : "l"(p));
    return a;
}
__device__ __forceinline__ void ldsm_x4(uint32_t& r0, uint32_t& r1, uint32_t& r2, uint32_t& r3,
                                        uint32_t addr) {
    asm volatile("ldmatrix.sync.aligned.m8n8.x4.shared.b16 {%0,%1,%2,%3}, [%4];"
                 : "=r"(r0), "=r"(r1), "=r"(r2), "=r"(r3) : "r"(addr));
}
__device__ __forceinline__ void mma16816(float* c, const uint32_t* a, const uint32_t* b) {
    asm volatile(
        "mma.sync.aligned.m16n8k16.row.col.f32.bf16.bf16.f32 "
        "{%0,%1,%2,%3}, {%4,%5,%6,%7}, {%8,%9}, {%0,%1,%2,%3};"
        : "+f"(c[0]), "+f"(c[1]), "+f"(c[2]), "+f"(c[3])
        : "r"(a[0]), "r"(a[1]), "r"(a[2]), "r"(a[3]), "r"(b[0]), "r"(b[1]));
}
__device__ __forceinline__ void split8(const float* v, uint32_t* hw, uint32_t* lw) {
#pragma unroll
    for (int c = 0; c < 4; ++c) {
        __nv_bfloat16 h0 = __float2bfloat16_rn(v[c * 2]);
        __nv_bfloat16 h1 = __float2bfloat16_rn(v[c * 2 + 1]);
        __nv_bfloat162 hh = __halves2bfloat162(h0, h1);
        __nv_bfloat162 ll = __halves2bfloat162(
            __float2bfloat16_rn(v[c * 2]     - __bfloat162float(h0)),
            __float2bfloat16_rn(v[c * 2 + 1] - __bfloat162float(h1)));
        hw[c] = *(uint32_t*)&hh;
        lw[c] = *(uint32_t*)&ll;
    }
}

// ---------------- prep ----------------
__global__ void prep_kernel(const float* __restrict__ l1_w, const float* __restrict__ l1_b,
                            const float* __restrict__ rtm_w, const float* __restrict__ rtm_b,
                            const float* __restrict__ ntm_w) {
    int f = blockIdx.x;      // 128
    int t = threadIdx.x;     // 128
#pragma unroll
    for (int kk = 0; kk < 2; ++kk) {
        int k = t + kk * 128;
        float w = ntm_w[f * HH + k];
        __nv_bfloat16 hi = __float2bfloat16_rn(w);
        g_ntm_hi[f * HH + k] = hi;
        g_ntm_lo[f * HH + k] = __float2bfloat16_rn(w - __bfloat162float(hi));
    }
    {
        float wa = l1_w[f * 384 + t];
        __nv_bfloat16 ha = __float2bfloat16_rn(wa);
        g_Wpq_hi[f * FF + t] = ha;
        g_Wpq_lo[f * FF + t] = __float2bfloat16_rn(wa - __bfloat162float(ha));
        float wb = l1_w[f * 384 + 128 + t];
        __nv_bfloat16 hb = __float2bfloat16_rn(wb);
        g_Wpq_hi[(128 + f) * FF + t] = hb;
        g_Wpq_lo[(128 + f) * FF + t] = __float2bfloat16_rn(wb - __bfloat162float(hb));
    }
    if (t < RR) {
        float s = 0.f;
        for (int c = 0; c < FF; ++c)
            s += l1_w[f * 384 + 256 + c] * rtm_w[c * RR + t];
        __nv_bfloat16 hi = __float2bfloat16_rn(s);
        g_Wrt_hi[f * RR + t] = hi;
        g_Wrt_lo[f * RR + t] = __float2bfloat16_rn(s - __bfloat162float(hi));
    } else if (t == RR) {
        float s = l1_b[f];
        for (int c = 0; c < FF; ++c)
            s += l1_w[f * 384 + 256 + c] * rtm_b[c];
        g_b1f[f] = s;
    }
}

__global__ void prep2_kernel(const float* __restrict__ mtn_w, const float* __restrict__ l2_w,
                             const float* __restrict__ l2_b) {
    __shared__ float mrow[FF];
    int h = blockIdx.x;      // 256
    int k = threadIdx.x;     // 128
    mrow[k] = mtn_w[h * FF + k];
    __syncthreads();
    float s = 0.f;
    for (int f = 0; f < FF; ++f)
        s = fmaf(mrow[f], l2_w[f * FF + k], s);
    __nv_bfloat16 hi = __float2bfloat16_rn(s);
    g_Mo_hi[h * FF + k] = hi;
    g_Mo_lo[h * FF + k] = __float2bfloat16_rn(s - __bfloat162float(hi));
    if (k == 0) {
        float b = 0.f;
        for (int f = 0; f < FF; ++f)
            b = fmaf(mrow[f], l2_b[f], b);
        g_bm[h] = b;
    }
}

__global__ void zero_kernel() {
    float4 z = make_float4(0.f, 0.f, 0.f, 0.f);
    float4* p = (float4*)g_G;
    int total = NN * FF / 4;
    for (int i = blockIdx.x * blockDim.x + threadIdx.x; i < total; i += gridDim.x * blockDim.x)
        p[i] = z;
    for (int i = blockIdx.x * blockDim.x + threadIdx.x; i < NN; i += gridDim.x * blockDim.x)
        g_deg[i] = 0.f;
}

// ---------------- node mma kernel: 512 thr, 4x4 warp grid, warp tile 32x32 --------
#define NO_XHI 0
#define NO_XLO 18432
#define NO_WHI 36864
#define NO_WLO 55296
#define N_SMEM 73728

__global__ __launch_bounds__(512, 1)
void node_kernel(const float* __restrict__ x,
                 const float* __restrict__ ntm_b,
                 const float* __restrict__ norm_g, const float* __restrict__ norm_b) {
    extern __shared__ char sma[];
    uint32_t sbase = smem_u32(sma);
    float* R = (float*)sma;              // [128][132] fp32, aliases X/W region

    int tid = threadIdx.x;
    int wid = tid >> 5, lane = tid & 31;
    int n0 = blockIdx.x * 128;

    int wm = wid >> 2, wn = wid & 3;
    int lrow = lane & 15, acolh = (lane >> 4) * 8;
    int brlo = (lane & 7) | ((lane & 16) >> 1), bcolh = ((lane >> 3) & 1) * 8;

    float c[2][4][4];
#pragma unroll
    for (int mi = 0; mi < 2; ++mi)
#pragma unroll
        for (int nt = 0; nt < 4; ++nt)
#pragma unroll
            for (int q = 0; q < 4; ++q) c[mi][nt][q] = 0.f;

    const float4* x4 = (const float4*)x;

    for (int kc = 0; kc < HH; kc += 64) {
        __syncthreads();
#pragma unroll
        for (int it = 0; it < 2; ++it) {
            int idx = tid + it * 512;
            int nl = idx >> 3, kq = idx & 7;
            int n = n0 + nl;
            float4 v0 = make_float4(0.f, 0.f, 0.f, 0.f), v1 = v0;
            if (n < NN) {
                v0 = x4[n * 64 + kc / 4 + kq * 2];
                v1 = x4[n * 64 + kc / 4 + kq * 2 + 1];
            }
            float vv[8] = {v0.x, v0.y, v0.z, v0.w, v1.x, v1.y, v1.z, v1.w};
            uint32_t hw[4], lw[4];
            split8(vv, hw, lw);
            *(uint4*)(sma + NO_XHI + nl * 144 + kq * 16) = make_uint4(hw[0], hw[1], hw[2], hw[3]);
            *(uint4*)(sma + NO_XLO + nl * 144 + kq * 16) = make_uint4(lw[0], lw[1], lw[2], lw[3]);
        }
        const uint4* gh = (const uint4*)g_ntm_hi;
        const uint4* gl = (const uint4*)g_ntm_lo;
#pragma unroll
        for (int it = 0; it < 2; ++it) {
            int idx = tid + it * 512;
            int f = idx >> 3, q = idx & 7;
            *(uint4*)(sma + NO_WHI + f * 144 + q * 16) = gh[f * 32 + kc / 8 + q];
            *(uint4*)(sma + NO_WLO + f * 144 + q * 16) = gl[f * 32 + kc / 8 + q];
        }
        __syncthreads();
#pragma unroll
        for (int kb = 0; kb < 64; kb += 16) {
            uint32_t ah[2][4], al[2][4];
#pragma unroll
            for (int mi = 0; mi < 2; ++mi) {
                int arow = wm * 32 + mi * 16 + lrow;
                ldsm_x4(ah[mi][0], ah[mi][1], ah[mi][2], ah[mi][3],
                        sbase + NO_XHI + (uint32_t)(arow * 72 + kb + acolh) * 2);
                ldsm_x4(al[mi][0], al[mi][1], al[mi][2], al[mi][3],
                        sbase + NO_XLO + (uint32_t)(arow * 72 + kb + acolh) * 2);
            }
#pragma unroll
            for (int nb = 0; nb < 2; ++nb) {
                int brow = wn * 32 + nb * 16 + brlo;
                uint32_t bh[4], bl[4];
                ldsm_x4(bh[0], bh[1], bh[2], bh[3],
                        sbase + NO_WHI + (uint32_t)(brow * 72 + kb + bcolh) * 2);
                ldsm_x4(bl[0], bl[1], bl[2], bl[3],
                        sbase + NO_WLO + (uint32_t)(brow * 72 + kb + bcolh) * 2);
#pragma unroll
                for (int mi = 0; mi < 2; ++mi) {
                    mma16816(c[mi][nb * 2],     ah[mi], bh);
                    mma16816(c[mi][nb * 2],     ah[mi], bl);
                    mma16816(c[mi][nb * 2],     al[mi], bh);
                    mma16816(c[mi][nb * 2 + 1], ah[mi], bh + 2);
                    mma16816(c[mi][nb * 2 + 1], ah[mi], bl + 2);
                    mma16816(c[mi][nb * 2 + 1], al[mi], bh + 2);
                }
            }
        }
    }

    __syncthreads();
    {
        int lr = lane >> 2, lc = (lane & 3) * 2;
#pragma unroll
        for (int mi = 0; mi < 2; ++mi) {
            int row0 = wm * 32 + mi * 16;
#pragma unroll
            for (int nt = 0; nt < 4; ++nt) {
                int col = wn * 32 + nt * 8 + lc;
                *(float2*)&R[(row0 + lr) * 132 + col]     = make_float2(c[mi][nt][0], c[mi][nt][1]);
                *(float2*)&R[(row0 + 8 + lr) * 132 + col] = make_float2(c[mi][nt][2], c[mi][nt][3]);
            }
        }
    }
    __syncthreads();

    // LN epilogue: 512 threads, tx 16 f-groups, ty 32 row-groups of 4
    int tx = tid & 15, ty = tid >> 4;
    float bb[8], gg[8], be[8];
#pragma unroll
    for (int cc = 0; cc < 8; ++cc) {
        int f = tx * 8 + cc;
        bb[cc] = ntm_b[f]; gg[cc] = norm_g[f]; be[cc] = norm_b[f];
    }
#pragma unroll
    for (int r = 0; r < 4; ++r) {
        int row = ty * 4 + r;
        float a[8];
        float4 a0 = *(float4*)&R[row * 132 + tx * 8];
        float4 a1 = *(float4*)&R[row * 132 + tx * 8 + 4];
        a[0] = a0.x + bb[0]; a[1] = a0.y + bb[1]; a[2] = a0.z + bb[2]; a[3] = a0.w + bb[3];
        a[4] = a1.x + bb[4]; a[5] = a1.y + bb[5]; a[6] = a1.z + bb[6]; a[7] = a1.w + bb[7];

        float s = 0.f;
#pragma unroll
        for (int cc = 0; cc < 8; ++cc) s += a[cc];
#pragma unroll
        for (int m = 1; m < 16; m <<= 1) s += __shfl_xor_sync(0xffffffffu, s, m);
        float mu = s * (1.f / FF);
        float v = 0.f;
#pragma unroll
        for (int cc = 0; cc < 8; ++cc) { float d = a[cc] - mu; v += d * d; }
#pragma unroll
        for (int m = 1; m < 16; m <<= 1) v += __shfl_xor_sync(0xffffffffu, v, m);
        float inv = rsqrtf(v * (1.f / FF) + 1e-5f);

        int n = n0 + row;
        if (n < NN) {
            float o[8];
#pragma unroll
            for (int cc = 0; cc < 8; ++cc) o[cc] = (a[cc] - mu) * inv * gg[cc] + be[cc];
            uint32_t hw[4], lw[4];
            split8(o, hw, lw);
            *(uint4*)&g_xf_hi[n * FF + tx * 8] = make_uint4(hw[0], hw[1], hw[2], hw[3]);
            *(uint4*)&g_xf_lo[n * FF + tx * 8] = make_uint4(lw[0], lw[1], lw[2], lw[3]);
        }
    }
}

// ---------------- pq mma kernel: 512 thr, M=128/CTA, N=256 in 2 halves ------------
#define QO_AHI 0
#define QO_ALO 34816
#define QO_BHI 69632
#define QO_BLO 104448
#define Q_SMEM 139264

__global__ __launch_bounds__(512, 1)
void pq_kernel() {
    extern __shared__ char sma[];
    uint32_t sbase = smem_u32(sma);
    int tid = threadIdx.x;
    int wid = tid >> 5, lane = tid & 31;
    int n0 = blockIdx.x * 128;

    int wm = wid >> 2, wn = wid & 3;
    int lrow = lane & 15, acolh = (lane >> 4) * 8;
    int brlo = (lane & 7) | ((lane & 16) >> 1), bcolh = ((lane >> 3) & 1) * 8;
    int lr = lane >> 2, lc = (lane & 3) * 2;

    {
        const uint4* gh = (const uint4*)g_xf_hi;
        const uint4* gl = (const uint4*)g_xf_lo;
        uint4 z = make_uint4(0, 0, 0, 0);
#pragma unroll
        for (int it = 0; it < 4; ++it) {
            int idx = tid + it * 512;
            int nl = idx >> 4, q = idx & 15;
            int n = n0 + nl;
            *(uint4*)(sma + QO_AHI + nl * 272 + q * 16) = (n < NN) ? gh[n * 16 + q] : z;
            *(uint4*)(sma + QO_ALO + nl * 272 + q * 16) = (n < NN) ? gl[n * 16 + q] : z;
        }
    }

    for (int nh = 0; nh < 2; ++nh) {
        __syncthreads();
        {
            const uint4* gh = (const uint4*)g_Wpq_hi;
            const uint4* gl = (const uint4*)g_Wpq_lo;
#pragma unroll
            for (int it = 0; it < 4; ++it) {
                int idx = tid + it * 512;
                int f = idx >> 4, q = idx & 15;
                *(uint4*)(sma + QO_BHI + f * 272 + q * 16) = gh[(nh * 128 + f) * 16 + q];
                *(uint4*)(sma + QO_BLO + f * 272 + q * 16) = gl[(nh * 128 + f) * 16 + q];
            }
        }
        __syncthreads();

        float c[2][4][4];
#pragma unroll
        for (int mi = 0; mi < 2; ++mi)
#pragma unroll
            for (int nt = 0; nt < 4; ++nt)
#pragma unroll
                for (int q = 0; q < 4; ++q) c[mi][nt][q] = 0.f;

#pragma unroll
        for (int kb = 0; kb < 128; kb += 16) {
            uint32_t ah[2][4], al[2][4];
#pragma unroll
            for (int mi = 0; mi < 2; ++mi) {
                int arow = wm * 32 + mi * 16 + lrow;
                ldsm_x4(ah[mi][0], ah[mi][1], ah[mi][2], ah[mi][3],
                        sbase + QO_AHI + (uint32_t)(arow * 136 + kb + acolh) * 2);
                ldsm_x4(al[mi][0], al[mi][1], al[mi][2], al[mi][3],
                        sbase + QO_ALO + (uint32_t)(arow * 136 + kb + acolh) * 2);
            }
#pragma unroll
            for (int nb = 0; nb < 2; ++nb) {
                int brow = wn * 32 + nb * 16 + brlo;
                uint32_t bh[4], bl[4];
                ldsm_x4(bh[0], bh[1], bh[2], bh[3],
                        sbase + QO_BHI + (uint32_t)(brow * 136 + kb + bcolh) * 2);
                ldsm_x4(bl[0], bl[1], bl[2], bl[3],
                        sbase + QO_BLO + (uint32_t)(brow * 136 + kb + bcolh) * 2);
#pragma unroll
                for (int mi = 0; mi < 2; ++mi) {
                    mma16816(c[mi][nb * 2],     ah[mi], bh);
                    mma16816(c[mi][nb * 2],     ah[mi], bl);
                    mma16816(c[mi][nb * 2],     al[mi], bh);
                    mma16816(c[mi][nb * 2 + 1], ah[mi], bh + 2);
                    mma16816(c[mi][nb * 2 + 1], ah[mi], bl + 2);
                    mma16816(c[mi][nb * 2 + 1], al[mi], bh + 2);
                }
            }
        }
#pragma unroll
        for (int mi = 0; mi < 2; ++mi) {
            int row0 = n0 + wm * 32 + mi * 16;
#pragma unroll
            for (int nt = 0; nt < 4; ++nt) {
                int col = nh * 128 + wn * 32 + nt * 8 + lc;
                if (row0 + lr < NN)
                    *(float2*)&g_PQ[(row0 + lr) * 256 + col] = make_float2(c[mi][nt][0], c[mi][nt][1]);
                if (row0 + 8 + lr < NN)
                    *(float2*)&g_PQ[(row0 + 8 + lr) * 256 + col] = make_float2(c[mi][nt][2], c[mi][nt][3]);
            }
        }
    }
}

// ---------------- edge kernel: 256 thr / 64 edges / 3 CTAs per SM -----------------
#define EO_R    0
#define EO_AHI  33792
#define EO_ALO  38912
#define EO_BHI  44032
#define EO_BLO  54272
#define EO_II   64512
#define EO_JJ   64768
#define E_SMEM  65024

__global__ __launch_bounds__(256, 3)
void edge_kernel(const float* __restrict__ rbf, const int* __restrict__ edge_index,
                 const float* __restrict__ ln_g, const float* __restrict__ ln_b) {
    extern __shared__ char sma[];
    uint32_t sbase = smem_u32(sma);
    float* R = (float*)(sma + EO_R);
    int* ii_s = (int*)(sma + EO_II);
    int* jj_s = (int*)(sma + EO_JJ);

    int tid = threadIdx.x;
    int wid = tid >> 5, lane = tid & 31;
    int tx = tid & 15, ty = tid >> 4;
    int e0 = blockIdx.x * 64;

    if (tid < 64) ii_s[tid] = edge_index[e0 + tid];
    else if (tid < 128) jj_s[tid - 64] = edge_index[EE + e0 + (tid - 64)];

    {
        int e = tid >> 2, ks = (tid & 3) * 8;
        const float4* rbf4 = (const float4*)rbf;
        float4 v0 = rbf4[(e0 + e) * 8 + (tid & 3) * 2];
        float4 v1 = rbf4[(e0 + e) * 8 + (tid & 3) * 2 + 1];
        float vv[8] = {v0.x, v0.y, v0.z, v0.w, v1.x, v1.y, v1.z, v1.w};
        uint32_t hw[4], lw[4];
        split8(vv, hw, lw);
        *(uint4*)(sma + EO_AHI + e * 80 + ks * 2) = make_uint4(hw[0], hw[1], hw[2], hw[3]);
        *(uint4*)(sma + EO_ALO + e * 80 + ks * 2) = make_uint4(lw[0], lw[1], lw[2], lw[3]);
    }
    {
        const uint4* gh = (const uint4*)g_Wrt_hi;
        const uint4* gl = (const uint4*)g_Wrt_lo;
        for (int idx = tid; idx < 512; idx += 256) {
            int f = idx >> 2, q = idx & 3;
            *(uint4*)(sma + EO_BHI + f * 80 + q * 16) = gh[idx];
            *(uint4*)(sma + EO_BLO + f * 80 + q * 16) = gl[idx];
        }
    }
    __syncthreads();

    if (tid < 64) atomicAdd(&g_deg[jj_s[tid]], 1.0f);

    {
        int mrow0 = (wid >> 1) * 16;
        int nhalf = (wid & 1) * 64;
        float c[8][4];
#pragma unroll
        for (int nt = 0; nt < 8; ++nt)
#pragma unroll
            for (int q = 0; q < 4; ++q) c[nt][q] = 0.f;

        int arow = mrow0 + (lane & 15);
        int acolh = (lane >> 4) * 8;
        int brlo = ((lane & 7) | ((lane & 16) >> 1));
        int bcolh = ((lane >> 3) & 1) * 8;

#pragma unroll
        for (int kb = 0; kb < 32; kb += 16) {
            uint32_t ah[4], al[4];
            ldsm_x4(ah[0], ah[1], ah[2], ah[3],
                    sbase + EO_AHI + (uint32_t)(arow * 40 + kb + acolh) * 2);
            ldsm_x4(al[0], al[1], al[2], al[3],
                    sbase + EO_ALO + (uint32_t)(arow * 40 + kb + acolh) * 2);
#pragma unroll
            for (int nb = 0; nb < 4; ++nb) {
                int brow = nhalf + nb * 16 + brlo;
                uint32_t bh[4], bl[4];
                ldsm_x4(bh[0], bh[1], bh[2], bh[3],
                        sbase + EO_BHI + (uint32_t)(brow * 40 + kb + bcolh) * 2);
                ldsm_x4(bl[0], bl[1], bl[2], bl[3],
                        sbase + EO_BLO + (uint32_t)(brow * 40 + kb + bcolh) * 2);
                mma16816(c[nb * 2],     ah, bh);
                mma16816(c[nb * 2],     ah, bl);
                mma16816(c[nb * 2],     al, bh);
                mma16816(c[nb * 2 + 1], ah, bh + 2);
                mma16816(c[nb * 2 + 1], ah, bl + 2);
                mma16816(c[nb * 2 + 1], al, bh + 2);
            }
        }
        int lr = lane >> 2, lc = (lane & 3) * 2;
#pragma unroll
        for (int nt = 0; nt < 8; ++nt) {
            int col = nhalf + nt * 8 + lc;
            *(float2*)&R[(mrow0 + lr) * 132 + col]     = make_float2(c[nt][0], c[nt][1]);
            *(float2*)&R[(mrow0 + 8 + lr) * 132 + col] = make_float2(c[nt][2], c[nt][3]);
        }
    }

    float b1r[8], lg[8], lb[8];
#pragma unroll
    for (int c = 0; c < 8; ++c) {
        int f = tx * 8 + c;
        b1r[c] = g_b1f[f]; lg[c] = ln_g[f]; lb[c] = ln_b[f];
    }
    __syncthreads();

    const float4* pq4 = (const float4*)g_PQ;
#pragma unroll
    for (int r = 0; r < 4; ++r) {
        int e = ty * 4 + r;
        int i = ii_s[e], j = jj_s[e];
        float4 r0 = *(float4*)&R[e * 132 + tx * 8];
        float4 r1 = *(float4*)&R[e * 132 + tx * 8 + 4];
        float4 p0 = pq4[i * 64 + tx * 2];
        float4 p1 = pq4[i * 64 + tx * 2 + 1];
        float4 q0 = pq4[j * 64 + 32 + tx * 2];
        float4 q1 = pq4[j * 64 + 32 + tx * 2 + 1];
        float acc[8];
        acc[0] = b1r[0] + r0.x + p0.x + q0.x; acc[1] = b1r[1] + r0.y + p0.y + q0.y;
        acc[2] = b1r[2] + r0.z + p0.z + q0.z; acc[3] = b1r[3] + r0.w + p0.w + q0.w;
        acc[4] = b1r[4] + r1.x + p1.x + q1.x; acc[5] = b1r[5] + r1.y + p1.y + q1.y;
        acc[6] = b1r[6] + r1.z + p1.z + q1.z; acc[7] = b1r[7] + r1.w + p1.w + q1.w;

        float s = 0.f;
#pragma unroll
        for (int c = 0; c < 8; ++c) s += acc[c];
#pragma unroll
        for (int m = 1; m < 16; m <<= 1) s += __shfl_xor_sync(0xffffffffu, s, m);
        float mu = s * (1.f / FF);
        float v = 0.f;
#pragma unroll
        for (int c = 0; c < 8; ++c) { float d = acc[c] - mu; v += d * d; }
#pragma unroll
        for (int m = 1; m < 16; m <<= 1) v += __shfl_xor_sync(0xffffffffu, v, m);
        float inv = rsqrtf(v * (1.f / FF) + 1e-5f);

        float o[8];
#pragma unroll
        for (int c = 0; c < 8; ++c) {
            float h = (acc[c] - mu) * inv * lg[c] + lb[c];
            o[c] = 0.5f * h * (1.0f + erff(h * 0.70710678118654752f));
        }
        float* dst = &g_G[j * FF + tx * 8];
        atomicAdd((float4*)dst,       make_float4(o[0], o[1], o[2], o[3]));
        atomicAdd((float4*)(dst + 4), make_float4(o[4], o[5], o[6], o[7]));
    }
}

// ---------------- out mma kernel: 512 thr, M=128/CTA, N=256 in 2 halves -----------
#define OO_AHI 0
#define OO_ALO 34816
#define OO_BHI 69632
#define OO_BLO 104448
#define O_SMEM 139264

__global__ __launch_bounds__(512, 1)
void out_kernel(float* __restrict__ out) {
    extern __shared__ char sma[];
    uint32_t sbase = smem_u32(sma);
    int tid = threadIdx.x;
    int wid = tid >> 5, lane = tid & 31;
    int n0 = blockIdx.x * 128;

    int wm = wid >> 2, wn = wid & 3;
    int lrow = lane & 15, acolh = (lane >> 4) * 8;
    int brlo = (lane & 7) | ((lane & 16) >> 1), bcolh = ((lane >> 3) & 1) * 8;
    int lr = lane >> 2, lc = (lane & 3) * 2;

    {
        const float4* g4 = (const float4*)g_G;
#pragma unroll
        for (int it = 0; it < 4; ++it) {
            int idx = tid + it * 512;
            int nl = idx >> 4, q = idx & 15;
            int n = n0 + nl;
            float4 v0 = make_float4(0.f, 0.f, 0.f, 0.f), v1 = v0;
            if (n < NN) {
                v0 = g4[n * 32 + q * 2];
                v1 = g4[n * 32 + q * 2 + 1];
            }
            float vv[8] = {v0.x, v0.y, v0.z, v0.w, v1.x, v1.y, v1.z, v1.w};
            uint32_t hw[4], lw[4];
            split8(vv, hw, lw);
            *(uint4*)(sma + OO_AHI + nl * 272 + q * 16) = make_uint4(hw[0], hw[1], hw[2], hw[3]);
            *(uint4*)(sma + OO_ALO + nl * 272 + q * 16) = make_uint4(lw[0], lw[1], lw[2], lw[3]);
        }
    }

    for (int nh = 0; nh < 2; ++nh) {
        __syncthreads();
        {
            const uint4* gh = (const uint4*)g_Mo_hi;
            const uint4* gl = (const uint4*)g_Mo_lo;
#pragma unroll
            for (int it = 0; it < 4; ++it) {
                int idx = tid + it * 512;
                int f = idx >> 4, q = idx & 15;
                *(uint4*)(sma + OO_BHI + f * 272 + q * 16) = gh[(nh * 128 + f) * 16 + q];
                *(uint4*)(sma + OO_BLO + f * 272 + q * 16) = gl[(nh * 128 + f) * 16 + q];
            }
        }
        __syncthreads();

        float c[2][4][4];
#pragma unroll
        for (int mi = 0; mi < 2; ++mi)
#pragma unroll
            for (int nt = 0; nt < 4; ++nt)
#pragma unroll
                for (int q = 0; q < 4; ++q) c[mi][nt][q] = 0.f;

#pragma unroll
        for (int kb = 0; kb < 128; kb += 16) {
            uint32_t ah[2][4], al[2][4];
#pragma unroll
            for (int mi = 0; mi < 2; ++mi) {
                int arow = wm * 32 + mi * 16 + lrow;
                ldsm_x4(ah[mi][0], ah[mi][1], ah[mi][2], ah[mi][3],
                        sbase + OO_AHI + (uint32_t)(arow * 136 + kb + acolh) * 2);
                ldsm_x4(al[mi][0], al[mi][1], al[mi][2], al[mi][3],
                        sbase + OO_ALO + (uint32_t)(arow * 136 + kb + acolh) * 2);
            }
#pragma unroll
            for (int nb = 0; nb < 2; ++nb) {
                int brow = wn * 32 + nb * 16 + brlo;
                uint32_t bh[4], bl[4];
                ldsm_x4(bh[0], bh[1], bh[2], bh[3],
                        sbase + OO_BHI + (uint32_t)(brow * 136 + kb + bcolh) * 2);
                ldsm_x4(bl[0], bl[1], bl[2], bl[3],
                        sbase + OO_BLO + (uint32_t)(brow * 136 + kb + bcolh) * 2);
#pragma unroll
                for (int mi = 0; mi < 2; ++mi) {
                    mma16816(c[mi][nb * 2],     ah[mi], bh);
                    mma16816(c[mi][nb * 2],     ah[mi], bl);
                    mma16816(c[mi][nb * 2],     al[mi], bh);
                    mma16816(c[mi][nb * 2 + 1], ah[mi], bh + 2);
                    mma16816(c[mi][nb * 2 + 1], ah[mi], bl + 2);
                    mma16816(c[mi][nb * 2 + 1], al[mi], bh + 2);
                }
            }
        }
#pragma unroll
        for (int mi = 0; mi < 2; ++mi) {
            int row0 = n0 + wm * 32 + mi * 16;
            int n1 = row0 + lr, n2 = row0 + 8 + lr;
            float d1 = (n1 < NN) ? g_deg[n1] : 0.f;
            float d2 = (n2 < NN) ? g_deg[n2] : 0.f;
#pragma unroll
            for (int nt = 0; nt < 4; ++nt) {
                int col = nh * 128 + wn * 32 + nt * 8 + lc;
                float2 bv = *(float2*)&g_bm[col];
                if (n1 < NN)
                    *(float2*)&out[n1 * HH + col] = make_float2(c[mi][nt][0] + d1 * bv.x,
                                                                c[mi][nt][1] + d1 * bv.y);
                if (n2 < NN)
                    *(float2*)&out[n2 * HH + col] = make_float2(c[mi][nt][2] + d2 * bv.x,
                                                                c[mi][nt][3] + d2 * bv.y);
            }
        }
    }
}

// ---------------- launch ----------------
extern "C" void kernel_launch(void* const* d_in, const int* in_sizes, int n_in,
                              void* d_out, int out_size) {
    const float* x      = (const float*)d_in[0];
    const float* rbf    = (const float*)d_in[1];
    const int*   eidx   = (const int*)d_in[2];
    const float* ntm_w  = (const float*)d_in[3];
    const float* ntm_b  = (const float*)d_in[4];
    const float* rtm_w  = (const float*)d_in[5];
    const float* rtm_b  = (const float*)d_in[6];
    const float* norm_g = (const float*)d_in[7];
    const float* norm_b = (const float*)d_in[8];
    const float* l1_w   = (const float*)d_in[9];
    const float* l1_b   = (const float*)d_in[10];
    const float* ln_g   = (const float*)d_in[11];
    const float* ln_b   = (const float*)d_in[12];
    const float* l2_w   = (const float*)d_in[13];
    const float* l2_b   = (const float*)d_in[14];
    const float* mtn_w  = (const float*)d_in[15];
    float* out = (float*)d_out;

    cudaFuncSetAttribute(node_kernel, cudaFuncAttributeMaxDynamicSharedMemorySize, N_SMEM);
    cudaFuncSetAttribute(pq_kernel,   cudaFuncAttributeMaxDynamicSharedMemorySize, Q_SMEM);
    cudaFuncSetAttribute(edge_kernel, cudaFuncAttributeMaxDynamicSharedMemorySize, E_SMEM);
    cudaFuncSetAttribute(out_kernel,  cudaFuncAttributeMaxDynamicSharedMemorySize, O_SMEM);

    zero_kernel<<<2048, 256>>>();
    prep_kernel<<<FF, 128>>>(l1_w, l1_b, rtm_w, rtm_b, ntm_w);
    prep2_kernel<<<HH, 128>>>(mtn_w, l2_w, l2_b);
    node_kernel<<<(NN + 127) / 128, 512, N_SMEM>>>(x, ntm_b, norm_g, norm_b);
    pq_kernel<<<(NN + 127) / 128, 512, Q_SMEM>>>();
    edge_kernel<<<EE / 64, 256, E_SMEM>>>(rbf, eidx, ln_g, ln_b);
    out_kernel<<<(NN + 127) / 128, 512, O_SMEM>>>(out);
}

// round 13
// speedup vs baseline: 8.9204x; 1.0154x over previous
#include <cuda_runtime.h>
#include <cuda_bf16.h>
#include <math.h>
#include <stdint.h>

#define NN 50000
#define EE 800000
#define HH 256
#define FF 128
#define RR 32

// ---------------- persistent device scratch ----------------
__device__ float g_PQ[NN * 256];
__device__ float g_G[NN * FF];
__device__ float g_deg[NN];
__device__ float g_b1f[FF];
__device__ float g_bm[HH];
__device__ __nv_bfloat16 g_Wrt_hi[FF * RR];
__device__ __nv_bfloat16 g_Wrt_lo[FF * RR];
__device__ __nv_bfloat16 g_ntm_hi[FF * HH];
__device__ __nv_bfloat16 g_ntm_lo[FF * HH];
__device__ __nv_bfloat16 g_Wpq_hi[256 * FF];
__device__ __nv_bfloat16 g_Wpq_lo[256 * FF];
__device__ __nv_bfloat16 g_Mo_hi[HH * FF];
__device__ __nv_bfloat16 g_Mo_lo[HH * FF];

// ---------------- ptx helpers ----------------
__device__ __forceinline__ uint32_t smem_u32(const void* p) {
    uint32_t a;
    asm("{ .reg .u64 t; cvta.to.shared.u64 t, %1; cvt.u32.u64 %0, t; }" : "=r"(a) : "l"(p));
    return a;
}
__device__ __forceinline__ void ldsm_x4(uint32_t& r0, uint32_t& r1, uint32_t& r2, uint32_t& r3,
                                        uint32_t addr) {
    asm volatile("ldmatrix.sync.aligned.m8n8.x4.shared.b16 {%0,%1,%2,%3}, [%4];"
                 : "=r"(r0), "=r"(r1), "=r"(r2), "=r"(r3) : "r"(addr));
}
__device__ __forceinline__ void mma16816(float* c, const uint32_t* a, const uint32_t* b) {
    asm volatile(
        "mma.sync.aligned.m16n8k16.row.col.f32.bf16.bf16.f32 "
        "{%0,%1,%2,%3}, {%4,%5,%6,%7}, {%8,%9}, {%0,%1,%2,%3};"
        : "+f"(c[0]), "+f"(c[1]), "+f"(c[2]), "+f"(c[3])
        : "r"(a[0]), "r"(a[1]), "r"(a[2]), "r"(a[3]), "r"(b[0]), "r"(b[1]));
}
__device__ __forceinline__ void split8(const float* v, uint32_t* hw, uint32_t* lw) {
#pragma unroll
    for (int c = 0; c < 4; ++c) {
        __nv_bfloat16 h0 = __float2bfloat16_rn(v[c * 2]);
        __nv_bfloat16 h1 = __float2bfloat16_rn(v[c * 2 + 1]);
        __nv_bfloat162 hh = __halves2bfloat162(h0, h1);
        __nv_bfloat162 ll = __halves2bfloat162(
            __float2bfloat16_rn(v[c * 2]     - __bfloat162float(h0)),
            __float2bfloat16_rn(v[c * 2 + 1] - __bfloat162float(h1)));
        hw[c] = *(uint32_t*)&hh;
        lw[c] = *(uint32_t*)&ll;
    }
}

// ---------------- prep ----------------
__global__ void prep_kernel(const float* __restrict__ l1_w, const float* __restrict__ l1_b,
                            const float* __restrict__ rtm_w, const float* __restrict__ rtm_b,
                            const float* __restrict__ ntm_w) {
    int f = blockIdx.x;      // 128
    int t = threadIdx.x;     // 128
#pragma unroll
    for (int kk = 0; kk < 2; ++kk) {
        int k = t + kk * 128;
        float w = ntm_w[f * HH + k];
        __nv_bfloat16 hi = __float2bfloat16_rn(w);
        g_ntm_hi[f * HH + k] = hi;
        g_ntm_lo[f * HH + k] = __float2bfloat16_rn(w - __bfloat162float(hi));
    }
    {
        float wa = l1_w[f * 384 + t];
        __nv_bfloat16 ha = __float2bfloat16_rn(wa);
        g_Wpq_hi[f * FF + t] = ha;
        g_Wpq_lo[f * FF + t] = __float2bfloat16_rn(wa - __bfloat162float(ha));
        float wb = l1_w[f * 384 + 128 + t];
        __nv_bfloat16 hb = __float2bfloat16_rn(wb);
        g_Wpq_hi[(128 + f) * FF + t] = hb;
        g_Wpq_lo[(128 + f) * FF + t] = __float2bfloat16_rn(wb - __bfloat162float(hb));
    }
    if (t < RR) {
        float s = 0.f;
        for (int c = 0; c < FF; ++c)
            s += l1_w[f * 384 + 256 + c] * rtm_w[c * RR + t];
        __nv_bfloat16 hi = __float2bfloat16_rn(s);
        g_Wrt_hi[f * RR + t] = hi;
        g_Wrt_lo[f * RR + t] = __float2bfloat16_rn(s - __bfloat162float(hi));
    } else if (t == RR) {
        float s = l1_b[f];
        for (int c = 0; c < FF; ++c)
            s += l1_w[f * 384 + 256 + c] * rtm_b[c];
        g_b1f[f] = s;
    }
}

__global__ void prep2_kernel(const float* __restrict__ mtn_w, const float* __restrict__ l2_w,
                             const float* __restrict__ l2_b) {
    __shared__ float mrow[FF];
    int h = blockIdx.x;      // 256
    int k = threadIdx.x;     // 128
    mrow[k] = mtn_w[h * FF + k];
    __syncthreads();
    float s = 0.f;
    for (int f = 0; f < FF; ++f)
        s = fmaf(mrow[f], l2_w[f * FF + k], s);
    __nv_bfloat16 hi = __float2bfloat16_rn(s);
    g_Mo_hi[h * FF + k] = hi;
    g_Mo_lo[h * FF + k] = __float2bfloat16_rn(s - __bfloat162float(hi));
    if (k == 0) {
        float b = 0.f;
        for (int f = 0; f < FF; ++f)
            b = fmaf(mrow[f], l2_b[f], b);
        g_bm[h] = b;
    }
}

__global__ void zero_kernel() {
    float4 z = make_float4(0.f, 0.f, 0.f, 0.f);
    float4* p = (float4*)g_G;
    int total = NN * FF / 4;
    for (int i = blockIdx.x * blockDim.x + threadIdx.x; i < total; i += gridDim.x * blockDim.x)
        p[i] = z;
    for (int i = blockIdx.x * blockDim.x + threadIdx.x; i < NN; i += gridDim.x * blockDim.x)
        g_deg[i] = 0.f;
}

// ---------------- fused node kernel: xf = LN(x@ntm^T+b); PQ = xf @ Wpq^T ----------
// 512 threads, 128 nodes/CTA.
// smem map (bytes):
//   phase 1 staging: XHI 0..18432, XLO 18432..36864, WHI 36864..55296, WLO 55296..73728
//   R fp32 [128][132] aliases 0..67584
//   phase 3: A tiles (xf hi/lo, pitch 136 elem) 0..34816, 34816..69632
//            B tiles (Wpq half)                69632..104448, 104448..139264
#define NO_XHI 0
#define NO_XLO 18432
#define NO_WHI 36864
#define NO_WLO 55296
#define NA_HI  0
#define NA_LO  34816
#define NB_HI  69632
#define NB_LO  104448
#define N_SMEM 139264

__global__ __launch_bounds__(512, 1)
void node_kernel(const float* __restrict__ x,
                 const float* __restrict__ ntm_b,
                 const float* __restrict__ norm_g, const float* __restrict__ norm_b) {
    extern __shared__ char sma[];
    uint32_t sbase = smem_u32(sma);
    float* R = (float*)sma;

    int tid = threadIdx.x;
    int wid = tid >> 5, lane = tid & 31;
    int n0 = blockIdx.x * 128;

    int wm = wid >> 2, wn = wid & 3;
    int lrow = lane & 15, acolh = (lane >> 4) * 8;
    int brlo = (lane & 7) | ((lane & 16) >> 1), bcolh = ((lane >> 3) & 1) * 8;
    int lr = lane >> 2, lc = (lane & 3) * 2;

    // ================= phase 1: R = x @ ntm^T ==================
    {
        float c[2][4][4];
#pragma unroll
        for (int mi = 0; mi < 2; ++mi)
#pragma unroll
            for (int nt = 0; nt < 4; ++nt)
#pragma unroll
                for (int q = 0; q < 4; ++q) c[mi][nt][q] = 0.f;

        const float4* x4 = (const float4*)x;

        for (int kc = 0; kc < HH; kc += 64) {
            __syncthreads();
#pragma unroll
            for (int it = 0; it < 2; ++it) {
                int idx = tid + it * 512;
                int nl = idx >> 3, kq = idx & 7;
                int n = n0 + nl;
                float4 v0 = make_float4(0.f, 0.f, 0.f, 0.f), v1 = v0;
                if (n < NN) {
                    v0 = x4[n * 64 + kc / 4 + kq * 2];
                    v1 = x4[n * 64 + kc / 4 + kq * 2 + 1];
                }
                float vv[8] = {v0.x, v0.y, v0.z, v0.w, v1.x, v1.y, v1.z, v1.w};
                uint32_t hw[4], lw[4];
                split8(vv, hw, lw);
                *(uint4*)(sma + NO_XHI + nl * 144 + kq * 16) = make_uint4(hw[0], hw[1], hw[2], hw[3]);
                *(uint4*)(sma + NO_XLO + nl * 144 + kq * 16) = make_uint4(lw[0], lw[1], lw[2], lw[3]);
            }
            const uint4* gh = (const uint4*)g_ntm_hi;
            const uint4* gl = (const uint4*)g_ntm_lo;
#pragma unroll
            for (int it = 0; it < 2; ++it) {
                int idx = tid + it * 512;
                int f = idx >> 3, q = idx & 7;
                *(uint4*)(sma + NO_WHI + f * 144 + q * 16) = gh[f * 32 + kc / 8 + q];
                *(uint4*)(sma + NO_WLO + f * 144 + q * 16) = gl[f * 32 + kc / 8 + q];
            }
            __syncthreads();
#pragma unroll
            for (int kb = 0; kb < 64; kb += 16) {
                uint32_t ah[2][4], al[2][4];
#pragma unroll
                for (int mi = 0; mi < 2; ++mi) {
                    int arow = wm * 32 + mi * 16 + lrow;
                    ldsm_x4(ah[mi][0], ah[mi][1], ah[mi][2], ah[mi][3],
                            sbase + NO_XHI + (uint32_t)(arow * 72 + kb + acolh) * 2);
                    ldsm_x4(al[mi][0], al[mi][1], al[mi][2], al[mi][3],
                            sbase + NO_XLO + (uint32_t)(arow * 72 + kb + acolh) * 2);
                }
#pragma unroll
                for (int nb = 0; nb < 2; ++nb) {
                    int brow = wn * 32 + nb * 16 + brlo;
                    uint32_t bh[4], bl[4];
                    ldsm_x4(bh[0], bh[1], bh[2], bh[3],
                            sbase + NO_WHI + (uint32_t)(brow * 72 + kb + bcolh) * 2);
                    ldsm_x4(bl[0], bl[1], bl[2], bl[3],
                            sbase + NO_WLO + (uint32_t)(brow * 72 + kb + bcolh) * 2);
#pragma unroll
                    for (int mi = 0; mi < 2; ++mi) {
                        mma16816(c[mi][nb * 2],     ah[mi], bh);
                        mma16816(c[mi][nb * 2],     ah[mi], bl);
                        mma16816(c[mi][nb * 2],     al[mi], bh);
                        mma16816(c[mi][nb * 2 + 1], ah[mi], bh + 2);
                        mma16816(c[mi][nb * 2 + 1], ah[mi], bl + 2);
                        mma16816(c[mi][nb * 2 + 1], al[mi], bh + 2);
                    }
                }
            }
        }

        __syncthreads();
#pragma unroll
        for (int mi = 0; mi < 2; ++mi) {
            int row0 = wm * 32 + mi * 16;
#pragma unroll
            for (int nt = 0; nt < 4; ++nt) {
                int col = wn * 32 + nt * 8 + lc;
                *(float2*)&R[(row0 + lr) * 132 + col]     = make_float2(c[mi][nt][0], c[mi][nt][1]);
                *(float2*)&R[(row0 + 8 + lr) * 132 + col] = make_float2(c[mi][nt][2], c[mi][nt][3]);
            }
        }
        __syncthreads();
    }

    // ================= phase 2: LN epilogue -> A tiles (xf bf16 hi/lo) =============
    {
        int tx = tid & 15, ty = tid >> 4;
        float a[4][8];
#pragma unroll
        for (int r = 0; r < 4; ++r) {
            int row = ty * 4 + r;
            float4 a0 = *(float4*)&R[row * 132 + tx * 8];
            float4 a1 = *(float4*)&R[row * 132 + tx * 8 + 4];
            a[r][0] = a0.x; a[r][1] = a0.y; a[r][2] = a0.z; a[r][3] = a0.w;
            a[r][4] = a1.x; a[r][5] = a1.y; a[r][6] = a1.z; a[r][7] = a1.w;
        }
        __syncthreads();   // all R reads done before A-tile writes overwrite region

        float bb[8], gg[8], be[8];
#pragma unroll
        for (int cc = 0; cc < 8; ++cc) {
            int f = tx * 8 + cc;
            bb[cc] = ntm_b[f]; gg[cc] = norm_g[f]; be[cc] = norm_b[f];
        }
#pragma unroll
        for (int r = 0; r < 4; ++r) {
            int row = ty * 4 + r;
#pragma unroll
            for (int cc = 0; cc < 8; ++cc) a[r][cc] += bb[cc];

            float s = 0.f;
#pragma unroll
            for (int cc = 0; cc < 8; ++cc) s += a[r][cc];
#pragma unroll
            for (int m = 1; m < 16; m <<= 1) s += __shfl_xor_sync(0xffffffffu, s, m);
            float mu = s * (1.f / FF);
            float v = 0.f;
#pragma unroll
            for (int cc = 0; cc < 8; ++cc) { float d = a[r][cc] - mu; v += d * d; }
#pragma unroll
            for (int m = 1; m < 16; m <<= 1) v += __shfl_xor_sync(0xffffffffu, v, m);
            float inv = rsqrtf(v * (1.f / FF) + 1e-5f);

            float o[8];
#pragma unroll
            for (int cc = 0; cc < 8; ++cc) o[cc] = (a[r][cc] - mu) * inv * gg[cc] + be[cc];
            uint32_t hw[4], lw[4];
            split8(o, hw, lw);
            *(uint4*)(sma + NA_HI + row * 272 + tx * 16) = make_uint4(hw[0], hw[1], hw[2], hw[3]);
            *(uint4*)(sma + NA_LO + row * 272 + tx * 16) = make_uint4(lw[0], lw[1], lw[2], lw[3]);
        }
    }

    // ================= phase 3: PQ = xf @ Wpq^T (2 N-halves) ======================
    for (int nh = 0; nh < 2; ++nh) {
        __syncthreads();
        {
            const uint4* gh = (const uint4*)g_Wpq_hi;
            const uint4* gl = (const uint4*)g_Wpq_lo;
#pragma unroll
            for (int it = 0; it < 4; ++it) {
                int idx = tid + it * 512;
                int f = idx >> 4, q = idx & 15;
                *(uint4*)(sma + NB_HI + f * 272 + q * 16) = gh[(nh * 128 + f) * 16 + q];
                *(uint4*)(sma + NB_LO + f * 272 + q * 16) = gl[(nh * 128 + f) * 16 + q];
            }
        }
        __syncthreads();

        float c[2][4][4];
#pragma unroll
        for (int mi = 0; mi < 2; ++mi)
#pragma unroll
            for (int nt = 0; nt < 4; ++nt)
#pragma unroll
                for (int q = 0; q < 4; ++q) c[mi][nt][q] = 0.f;

#pragma unroll
        for (int kb = 0; kb < 128; kb += 16) {
            uint32_t ah[2][4], al[2][4];
#pragma unroll
            for (int mi = 0; mi < 2; ++mi) {
                int arow = wm * 32 + mi * 16 + lrow;
                ldsm_x4(ah[mi][0], ah[mi][1], ah[mi][2], ah[mi][3],
                        sbase + NA_HI + (uint32_t)(arow * 136 + kb + acolh) * 2);
                ldsm_x4(al[mi][0], al[mi][1], al[mi][2], al[mi][3],
                        sbase + NA_LO + (uint32_t)(arow * 136 + kb + acolh) * 2);
            }
#pragma unroll
            for (int nb = 0; nb < 2; ++nb) {
                int brow = wn * 32 + nb * 16 + brlo;
                uint32_t bh[4], bl[4];
                ldsm_x4(bh[0], bh[1], bh[2], bh[3],
                        sbase + NB_HI + (uint32_t)(brow * 136 + kb + bcolh) * 2);
                ldsm_x4(bl[0], bl[1], bl[2], bl[3],
                        sbase + NB_LO + (uint32_t)(brow * 136 + kb + bcolh) * 2);
#pragma unroll
                for (int mi = 0; mi < 2; ++mi) {
                    mma16816(c[mi][nb * 2],     ah[mi], bh);
                    mma16816(c[mi][nb * 2],     ah[mi], bl);
                    mma16816(c[mi][nb * 2],     al[mi], bh);
                    mma16816(c[mi][nb * 2 + 1], ah[mi], bh + 2);
                    mma16816(c[mi][nb * 2 + 1], ah[mi], bl + 2);
                    mma16816(c[mi][nb * 2 + 1], al[mi], bh + 2);
                }
            }
        }
#pragma unroll
        for (int mi = 0; mi < 2; ++mi) {
            int row0 = n0 + wm * 32 + mi * 16;
#pragma unroll
            for (int nt = 0; nt < 4; ++nt) {
                int col = nh * 128 + wn * 32 + nt * 8 + lc;
                if (row0 + lr < NN)
                    *(float2*)&g_PQ[(row0 + lr) * 256 + col] = make_float2(c[mi][nt][0], c[mi][nt][1]);
                if (row0 + 8 + lr < NN)
                    *(float2*)&g_PQ[(row0 + 8 + lr) * 256 + col] = make_float2(c[mi][nt][2], c[mi][nt][3]);
            }
        }
    }
}

// ---------------- edge kernel: 256 thr / 64 edges / 3 CTAs per SM -----------------
#define EO_R    0
#define EO_AHI  33792
#define EO_ALO  38912
#define EO_BHI  44032
#define EO_BLO  54272
#define EO_II   64512
#define EO_JJ   64768
#define E_SMEM  65024

__global__ __launch_bounds__(256, 3)
void edge_kernel(const float* __restrict__ rbf, const int* __restrict__ edge_index,
                 const float* __restrict__ ln_g, const float* __restrict__ ln_b) {
    extern __shared__ char sma[];
    uint32_t sbase = smem_u32(sma);
    float* R = (float*)(sma + EO_R);
    int* ii_s = (int*)(sma + EO_II);
    int* jj_s = (int*)(sma + EO_JJ);

    int tid = threadIdx.x;
    int wid = tid >> 5, lane = tid & 31;
    int tx = tid & 15, ty = tid >> 4;
    int e0 = blockIdx.x * 64;

    if (tid < 64) ii_s[tid] = edge_index[e0 + tid];
    else if (tid < 128) jj_s[tid - 64] = edge_index[EE + e0 + (tid - 64)];

    {
        int e = tid >> 2, ks = (tid & 3) * 8;
        const float4* rbf4 = (const float4*)rbf;
        float4 v0 = rbf4[(e0 + e) * 8 + (tid & 3) * 2];
        float4 v1 = rbf4[(e0 + e) * 8 + (tid & 3) * 2 + 1];
        float vv[8] = {v0.x, v0.y, v0.z, v0.w, v1.x, v1.y, v1.z, v1.w};
        uint32_t hw[4], lw[4];
        split8(vv, hw, lw);
        *(uint4*)(sma + EO_AHI + e * 80 + ks * 2) = make_uint4(hw[0], hw[1], hw[2], hw[3]);
        *(uint4*)(sma + EO_ALO + e * 80 + ks * 2) = make_uint4(lw[0], lw[1], lw[2], lw[3]);
    }
    {
        const uint4* gh = (const uint4*)g_Wrt_hi;
        const uint4* gl = (const uint4*)g_Wrt_lo;
        for (int idx = tid; idx < 512; idx += 256) {
            int f = idx >> 2, q = idx & 3;
            *(uint4*)(sma + EO_BHI + f * 80 + q * 16) = gh[idx];
            *(uint4*)(sma + EO_BLO + f * 80 + q * 16) = gl[idx];
        }
    }
    __syncthreads();

    if (tid < 64) atomicAdd(&g_deg[jj_s[tid]], 1.0f);

    {
        int mrow0 = (wid >> 1) * 16;
        int nhalf = (wid & 1) * 64;
        float c[8][4];
#pragma unroll
        for (int nt = 0; nt < 8; ++nt)
#pragma unroll
            for (int q = 0; q < 4; ++q) c[nt][q] = 0.f;

        int arow = mrow0 + (lane & 15);
        int acolh = (lane >> 4) * 8;
        int brlo = ((lane & 7) | ((lane & 16) >> 1));
        int bcolh = ((lane >> 3) & 1) * 8;

#pragma unroll
        for (int kb = 0; kb < 32; kb += 16) {
            uint32_t ah[4], al[4];
            ldsm_x4(ah[0], ah[1], ah[2], ah[3],
                    sbase + EO_AHI + (uint32_t)(arow * 40 + kb + acolh) * 2);
            ldsm_x4(al[0], al[1], al[2], al[3],
                    sbase + EO_ALO + (uint32_t)(arow * 40 + kb + acolh) * 2);
#pragma unroll
            for (int nb = 0; nb < 4; ++nb) {
                int brow = nhalf + nb * 16 + brlo;
                uint32_t bh[4], bl[4];
                ldsm_x4(bh[0], bh[1], bh[2], bh[3],
                        sbase + EO_BHI + (uint32_t)(brow * 40 + kb + bcolh) * 2);
                ldsm_x4(bl[0], bl[1], bl[2], bl[3],
                        sbase + EO_BLO + (uint32_t)(brow * 40 + kb + bcolh) * 2);
                mma16816(c[nb * 2],     ah, bh);
                mma16816(c[nb * 2],     ah, bl);
                mma16816(c[nb * 2],     al, bh);
                mma16816(c[nb * 2 + 1], ah, bh + 2);
                mma16816(c[nb * 2 + 1], ah, bl + 2);
                mma16816(c[nb * 2 + 1], al, bh + 2);
            }
        }
        int lr = lane >> 2, lc = (lane & 3) * 2;
#pragma unroll
        for (int nt = 0; nt < 8; ++nt) {
            int col = nhalf + nt * 8 + lc;
            *(float2*)&R[(mrow0 + lr) * 132 + col]     = make_float2(c[nt][0], c[nt][1]);
            *(float2*)&R[(mrow0 + 8 + lr) * 132 + col] = make_float2(c[nt][2], c[nt][3]);
        }
    }

    float b1r[8], lg[8], lb[8];
#pragma unroll
    for (int c = 0; c < 8; ++c) {
        int f = tx * 8 + c;
        b1r[c] = g_b1f[f]; lg[c] = ln_g[f]; lb[c] = ln_b[f];
    }
    __syncthreads();

    const float4* pq4 = (const float4*)g_PQ;
#pragma unroll
    for (int r = 0; r < 4; ++r) {
        int e = ty * 4 + r;
        int i = ii_s[e], j = jj_s[e];
        float4 r0 = *(float4*)&R[e * 132 + tx * 8];
        float4 r1 = *(float4*)&R[e * 132 + tx * 8 + 4];
        float4 p0 = pq4[i * 64 + tx * 2];
        float4 p1 = pq4[i * 64 + tx * 2 + 1];
        float4 q0 = pq4[j * 64 + 32 + tx * 2];
        float4 q1 = pq4[j * 64 + 32 + tx * 2 + 1];
        float acc[8];
        acc[0] = b1r[0] + r0.x + p0.x + q0.x; acc[1] = b1r[1] + r0.y + p0.y + q0.y;
        acc[2] = b1r[2] + r0.z + p0.z + q0.z; acc[3] = b1r[3] + r0.w + p0.w + q0.w;
        acc[4] = b1r[4] + r1.x + p1.x + q1.x; acc[5] = b1r[5] + r1.y + p1.y + q1.y;
        acc[6] = b1r[6] + r1.z + p1.z + q1.z; acc[7] = b1r[7] + r1.w + p1.w + q1.w;

        float s = 0.f;
#pragma unroll
        for (int c = 0; c < 8; ++c) s += acc[c];
#pragma unroll
        for (int m = 1; m < 16; m <<= 1) s += __shfl_xor_sync(0xffffffffu, s, m);
        float mu = s * (1.f / FF);
        float v = 0.f;
#pragma unroll
        for (int c = 0; c < 8; ++c) { float d = acc[c] - mu; v += d * d; }
#pragma unroll
        for (int m = 1; m < 16; m <<= 1) v += __shfl_xor_sync(0xffffffffu, v, m);
        float inv = rsqrtf(v * (1.f / FF) + 1e-5f);

        float o[8];
#pragma unroll
        for (int c = 0; c < 8; ++c) {
            float h = (acc[c] - mu) * inv * lg[c] + lb[c];
            o[c] = 0.5f * h * (1.0f + erff(h * 0.70710678118654752f));
        }
        float* dst = &g_G[j * FF + tx * 8];
        atomicAdd((float4*)dst,       make_float4(o[0], o[1], o[2], o[3]));
        atomicAdd((float4*)(dst + 4), make_float4(o[4], o[5], o[6], o[7]));
    }
}

// ---------------- out mma kernel: 512 thr, M=128/CTA, N=256 in 2 halves -----------
#define OO_AHI 0
#define OO_ALO 34816
#define OO_BHI 69632
#define OO_BLO 104448
#define O_SMEM 139264

__global__ __launch_bounds__(512, 1)
void out_kernel(float* __restrict__ out) {
    extern __shared__ char sma[];
    uint32_t sbase = smem_u32(sma);
    int tid = threadIdx.x;
    int wid = tid >> 5, lane = tid & 31;
    int n0 = blockIdx.x * 128;

    int wm = wid >> 2, wn = wid & 3;
    int lrow = lane & 15, acolh = (lane >> 4) * 8;
    int brlo = (lane & 7) | ((lane & 16) >> 1), bcolh = ((lane >> 3) & 1) * 8;
    int lr = lane >> 2, lc = (lane & 3) * 2;

    {
        const float4* g4 = (const float4*)g_G;
#pragma unroll
        for (int it = 0; it < 4; ++it) {
            int idx = tid + it * 512;
            int nl = idx >> 4, q = idx & 15;
            int n = n0 + nl;
            float4 v0 = make_float4(0.f, 0.f, 0.f, 0.f), v1 = v0;
            if (n < NN) {
                v0 = g4[n * 32 + q * 2];
                v1 = g4[n * 32 + q * 2 + 1];
            }
            float vv[8] = {v0.x, v0.y, v0.z, v0.w, v1.x, v1.y, v1.z, v1.w};
            uint32_t hw[4], lw[4];
            split8(vv, hw, lw);
            *(uint4*)(sma + OO_AHI + nl * 272 + q * 16) = make_uint4(hw[0], hw[1], hw[2], hw[3]);
            *(uint4*)(sma + OO_ALO + nl * 272 + q * 16) = make_uint4(lw[0], lw[1], lw[2], lw[3]);
        }
    }

    for (int nh = 0; nh < 2; ++nh) {
        __syncthreads();
        {
            const uint4* gh = (const uint4*)g_Mo_hi;
            const uint4* gl = (const uint4*)g_Mo_lo;
#pragma unroll
            for (int it = 0; it < 4; ++it) {
                int idx = tid + it * 512;
                int f = idx >> 4, q = idx & 15;
                *(uint4*)(sma + OO_BHI + f * 272 + q * 16) = gh[(nh * 128 + f) * 16 + q];
                *(uint4*)(sma + OO_BLO + f * 272 + q * 16) = gl[(nh * 128 + f) * 16 + q];
            }
        }
        __syncthreads();

        float c[2][4][4];
#pragma unroll
        for (int mi = 0; mi < 2; ++mi)
#pragma unroll
            for (int nt = 0; nt < 4; ++nt)
#pragma unroll
                for (int q = 0; q < 4; ++q) c[mi][nt][q] = 0.f;

#pragma unroll
        for (int kb = 0; kb < 128; kb += 16) {
            uint32_t ah[2][4], al[2][4];
#pragma unroll
            for (int mi = 0; mi < 2; ++mi) {
                int arow = wm * 32 + mi * 16 + lrow;
                ldsm_x4(ah[mi][0], ah[mi][1], ah[mi][2], ah[mi][3],
                        sbase + OO_AHI + (uint32_t)(arow * 136 + kb + acolh) * 2);
                ldsm_x4(al[mi][0], al[mi][1], al[mi][2], al[mi][3],
                        sbase + OO_ALO + (uint32_t)(arow * 136 + kb + acolh) * 2);
            }
#pragma unroll
            for (int nb = 0; nb < 2; ++nb) {
                int brow = wn * 32 + nb * 16 + brlo;
                uint32_t bh[4], bl[4];
                ldsm_x4(bh[0], bh[1], bh[2], bh[3],
                        sbase + OO_BHI + (uint32_t)(brow * 136 + kb + bcolh) * 2);
                ldsm_x4(bl[0], bl[1], bl[2], bl[3],
                        sbase + OO_BLO + (uint32_t)(brow * 136 + kb + bcolh) * 2);
#pragma unroll
                for (int mi = 0; mi < 2; ++mi) {
                    mma16816(c[mi][nb * 2],     ah[mi], bh);
                    mma16816(c[mi][nb * 2],     ah[mi], bl);
                    mma16816(c[mi][nb * 2],     al[mi], bh);
                    mma16816(c[mi][nb * 2 + 1], ah[mi], bh + 2);
                    mma16816(c[mi][nb * 2 + 1], ah[mi], bl + 2);
                    mma16816(c[mi][nb * 2 + 1], al[mi], bh + 2);
                }
            }
        }
#pragma unroll
        for (int mi = 0; mi < 2; ++mi) {
            int row0 = n0 + wm * 32 + mi * 16;
            int n1 = row0 + lr, n2 = row0 + 8 + lr;
            float d1 = (n1 < NN) ? g_deg[n1] : 0.f;
            float d2 = (n2 < NN) ? g_deg[n2] : 0.f;
#pragma unroll
            for (int nt = 0; nt < 4; ++nt) {
                int col = nh * 128 + wn * 32 + nt * 8 + lc;
                float2 bv = *(float2*)&g_bm[col];
                if (n1 < NN)
                    *(float2*)&out[n1 * HH + col] = make_float2(c[mi][nt][0] + d1 * bv.x,
                                                                c[mi][nt][1] + d1 * bv.y);
                if (n2 < NN)
                    *(float2*)&out[n2 * HH + col] = make_float2(c[mi][nt][2] + d2 * bv.x,
                                                                c[mi][nt][3] + d2 * bv.y);
            }
        }
    }
}

// ---------------- launch ----------------
extern "C" void kernel_launch(void* const* d_in, const int* in_sizes, int n_in,
                              void* d_out, int out_size) {
    const float* x      = (const float*)d_in[0];
    const float* rbf    = (const float*)d_in[1];
    const int*   eidx   = (const int*)d_in[2];
    const float* ntm_w  = (const float*)d_in[3];
    const float* ntm_b  = (const float*)d_in[4];
    const float* rtm_w  = (const float*)d_in[5];
    const float* rtm_b  = (const float*)d_in[6];
    const float* norm_g = (const float*)d_in[7];
    const float* norm_b = (const float*)d_in[8];
    const float* l1_w   = (const float*)d_in[9];
    const float* l1_b   = (const float*)d_in[10];
    const float* ln_g   = (const float*)d_in[11];
    const float* ln_b   = (const float*)d_in[12];
    const float* l2_w   = (const float*)d_in[13];
    const float* l2_b   = (const float*)d_in[14];
    const float* mtn_w  = (const float*)d_in[15];
    float* out = (float*)d_out;

    cudaFuncSetAttribute(node_kernel, cudaFuncAttributeMaxDynamicSharedMemorySize, N_SMEM);
    cudaFuncSetAttribute(edge_kernel, cudaFuncAttributeMaxDynamicSharedMemorySize, E_SMEM);
    cudaFuncSetAttribute(out_kernel,  cudaFuncAttributeMaxDynamicSharedMemorySize, O_SMEM);

    zero_kernel<<<2048, 256>>>();
    prep_kernel<<<FF, 128>>>(l1_w, l1_b, rtm_w, rtm_b, ntm_w);
    prep2_kernel<<<HH, 128>>>(mtn_w, l2_w, l2_b);
    node_kernel<<<(NN + 127) / 128, 512, N_SMEM>>>(x, ntm_b, norm_g, norm_b);
    edge_kernel<<<EE / 64, 256, E_SMEM>>>(rbf, eidx, ln_g, ln_b);
    out_kernel<<<(NN + 127) / 128, 512, O_SMEM>>>(out);
}

// round 14
// speedup vs baseline: 9.1053x; 1.0207x over previous
#include <cuda_runtime.h>
#include <cuda_bf16.h>
#include <math.h>
#include <stdint.h>

#define NN 50000
#define EE 800000
#define HH 256
#define FF 128
#define RR 32

// ---------------- persistent device scratch ----------------
__device__ float g_PQ[NN * 256];
__device__ float g_G[NN * FF];
__device__ float g_deg[NN];
__device__ float g_b1f[FF];
__device__ float g_bm[HH];
__device__ __nv_bfloat16 g_Wrt_hi[FF * RR];
__device__ __nv_bfloat16 g_Wrt_lo[FF * RR];
__device__ __nv_bfloat16 g_ntm_hi[FF * HH];
__device__ __nv_bfloat16 g_ntm_lo[FF * HH];
__device__ __nv_bfloat16 g_Wpq_hi[256 * FF];
__device__ __nv_bfloat16 g_Wpq_lo[256 * FF];
__device__ __nv_bfloat16 g_Mo_hi[HH * FF];
__device__ __nv_bfloat16 g_Mo_lo[HH * FF];

// ---------------- ptx helpers ----------------
__device__ __forceinline__ uint32_t smem_u32(const void* p) {
    uint32_t a;
    asm("{ .reg .u64 t; cvta.to.shared.u64 t, %1; cvt.u32.u64 %0, t; }" : "=r"(a) : "l"(p));
    return a;
}
__device__ __forceinline__ void ldsm_x4(uint32_t& r0, uint32_t& r1, uint32_t& r2, uint32_t& r3,
                                        uint32_t addr) {
    asm volatile("ldmatrix.sync.aligned.m8n8.x4.shared.b16 {%0,%1,%2,%3}, [%4];"
                 : "=r"(r0), "=r"(r1), "=r"(r2), "=r"(r3) : "r"(addr));
}
__device__ __forceinline__ void mma16816(float* c, const uint32_t* a, const uint32_t* b) {
    asm volatile(
        "mma.sync.aligned.m16n8k16.row.col.f32.bf16.bf16.f32 "
        "{%0,%1,%2,%3}, {%4,%5,%6,%7}, {%8,%9}, {%0,%1,%2,%3};"
        : "+f"(c[0]), "+f"(c[1]), "+f"(c[2]), "+f"(c[3])
        : "r"(a[0]), "r"(a[1]), "r"(a[2]), "r"(a[3]), "r"(b[0]), "r"(b[1]));
}
__device__ __forceinline__ void split8(const float* v, uint32_t* hw, uint32_t* lw) {
#pragma unroll
    for (int c = 0; c < 4; ++c) {
        __nv_bfloat16 h0 = __float2bfloat16_rn(v[c * 2]);
        __nv_bfloat16 h1 = __float2bfloat16_rn(v[c * 2 + 1]);
        __nv_bfloat162 hh = __halves2bfloat162(h0, h1);
        __nv_bfloat162 ll = __halves2bfloat162(
            __float2bfloat16_rn(v[c * 2]     - __bfloat162float(h0)),
            __float2bfloat16_rn(v[c * 2 + 1] - __bfloat162float(h1)));
        hw[c] = *(uint32_t*)&hh;
        lw[c] = *(uint32_t*)&ll;
    }
}

// ---------------- prep ----------------
__global__ void prep_kernel(const float* __restrict__ l1_w, const float* __restrict__ l1_b,
                            const float* __restrict__ rtm_w, const float* __restrict__ rtm_b,
                            const float* __restrict__ ntm_w) {
    int f = blockIdx.x;      // 128
    int t = threadIdx.x;     // 128
#pragma unroll
    for (int kk = 0; kk < 2; ++kk) {
        int k = t + kk * 128;
        float w = ntm_w[f * HH + k];
        __nv_bfloat16 hi = __float2bfloat16_rn(w);
        g_ntm_hi[f * HH + k] = hi;
        g_ntm_lo[f * HH + k] = __float2bfloat16_rn(w - __bfloat162float(hi));
    }
    {
        float wa = l1_w[f * 384 + t];
        __nv_bfloat16 ha = __float2bfloat16_rn(wa);
        g_Wpq_hi[f * FF + t] = ha;
        g_Wpq_lo[f * FF + t] = __float2bfloat16_rn(wa - __bfloat162float(ha));
        float wb = l1_w[f * 384 + 128 + t];
        __nv_bfloat16 hb = __float2bfloat16_rn(wb);
        g_Wpq_hi[(128 + f) * FF + t] = hb;
        g_Wpq_lo[(128 + f) * FF + t] = __float2bfloat16_rn(wb - __bfloat162float(hb));
    }
    if (t < RR) {
        float s = 0.f;
        for (int c = 0; c < FF; ++c)
            s += l1_w[f * 384 + 256 + c] * rtm_w[c * RR + t];
        __nv_bfloat16 hi = __float2bfloat16_rn(s);
        g_Wrt_hi[f * RR + t] = hi;
        g_Wrt_lo[f * RR + t] = __float2bfloat16_rn(s - __bfloat162float(hi));
    } else if (t == RR) {
        float s = l1_b[f];
        for (int c = 0; c < FF; ++c)
            s += l1_w[f * 384 + 256 + c] * rtm_b[c];
        g_b1f[f] = s;
    }
}

__global__ void prep2_kernel(const float* __restrict__ mtn_w, const float* __restrict__ l2_w,
                             const float* __restrict__ l2_b) {
    __shared__ float mrow[FF];
    int h = blockIdx.x;      // 256
    int k = threadIdx.x;     // 128
    mrow[k] = mtn_w[h * FF + k];
    __syncthreads();
    float s = 0.f;
    for (int f = 0; f < FF; ++f)
        s = fmaf(mrow[f], l2_w[f * FF + k], s);
    __nv_bfloat16 hi = __float2bfloat16_rn(s);
    g_Mo_hi[h * FF + k] = hi;
    g_Mo_lo[h * FF + k] = __float2bfloat16_rn(s - __bfloat162float(hi));
    if (k == 0) {
        float b = 0.f;
        for (int f = 0; f < FF; ++f)
            b = fmaf(mrow[f], l2_b[f], b);
        g_bm[h] = b;
    }
}

__global__ void zero_kernel() {
    float4 z = make_float4(0.f, 0.f, 0.f, 0.f);
    float4* p = (float4*)g_G;
    int total = NN * FF / 4;
    for (int i = blockIdx.x * blockDim.x + threadIdx.x; i < total; i += gridDim.x * blockDim.x)
        p[i] = z;
    for (int i = blockIdx.x * blockDim.x + threadIdx.x; i < NN; i += gridDim.x * blockDim.x)
        g_deg[i] = 0.f;
}

// ---------------- fused node kernel ----------------
// phase1: 2 k-chunks of 128 (staging pitch 272B). phase3: full Wpq resident.
// smem: XHI 0, XLO 34816, WHI 69632, WLO 104448 (phase1)
//       R fp32 [128][132] aliases 0..67584
//       NA_HI 0, NA_LO 34816, NB_HI 69632..139264, NB_LO 139264..208896
#define NX_HI  0
#define NX_LO  34816
#define NW_HI  69632
#define NW_LO  104448
#define NA_HI  0
#define NA_LO  34816
#define NB_HI  69632
#define NB_LO  139264
#define N_SMEM 208896

__global__ __launch_bounds__(512, 1)
void node_kernel(const float* __restrict__ x,
                 const float* __restrict__ ntm_b,
                 const float* __restrict__ norm_g, const float* __restrict__ norm_b) {
    extern __shared__ char sma[];
    uint32_t sbase = smem_u32(sma);
    float* R = (float*)sma;

    int tid = threadIdx.x;
    int wid = tid >> 5, lane = tid & 31;
    int n0 = blockIdx.x * 128;

    int wm = wid >> 2, wn = wid & 3;
    int lrow = lane & 15, acolh = (lane >> 4) * 8;
    int brlo = (lane & 7) | ((lane & 16) >> 1), bcolh = ((lane >> 3) & 1) * 8;
    int lr = lane >> 2, lc = (lane & 3) * 2;

    // ================= phase 1: R = x @ ntm^T (2 chunks of K=128) =================
    {
        float c[2][4][4];
#pragma unroll
        for (int mi = 0; mi < 2; ++mi)
#pragma unroll
            for (int nt = 0; nt < 4; ++nt)
#pragma unroll
                for (int q = 0; q < 4; ++q) c[mi][nt][q] = 0.f;

        const float4* x4 = (const float4*)x;

        for (int kc = 0; kc < HH; kc += 128) {
            __syncthreads();
            // X chunk: 128 nodes x 128 k -> bf16 hi/lo, pitch 272 B
#pragma unroll
            for (int it = 0; it < 4; ++it) {
                int idx = tid + it * 512;
                int nl = idx >> 4, kq = idx & 15;
                int n = n0 + nl;
                float4 v0 = make_float4(0.f, 0.f, 0.f, 0.f), v1 = v0;
                if (n < NN) {
                    v0 = x4[n * 64 + kc / 4 + kq * 2];
                    v1 = x4[n * 64 + kc / 4 + kq * 2 + 1];
                }
                float vv[8] = {v0.x, v0.y, v0.z, v0.w, v1.x, v1.y, v1.z, v1.w};
                uint32_t hw[4], lw[4];
                split8(vv, hw, lw);
                *(uint4*)(sma + NX_HI + nl * 272 + kq * 16) = make_uint4(hw[0], hw[1], hw[2], hw[3]);
                *(uint4*)(sma + NX_LO + nl * 272 + kq * 16) = make_uint4(lw[0], lw[1], lw[2], lw[3]);
            }
            // W chunk (pre-split bf16): rows f, cols kc..kc+128
            const uint4* gh = (const uint4*)g_ntm_hi;
            const uint4* gl = (const uint4*)g_ntm_lo;
#pragma unroll
            for (int it = 0; it < 4; ++it) {
                int idx = tid + it * 512;
                int f = idx >> 4, q = idx & 15;
                *(uint4*)(sma + NW_HI + f * 272 + q * 16) = gh[f * 32 + kc / 8 + q];
                *(uint4*)(sma + NW_LO + f * 272 + q * 16) = gl[f * 32 + kc / 8 + q];
            }
            __syncthreads();
#pragma unroll
            for (int kb = 0; kb < 128; kb += 16) {
                uint32_t ah[2][4], al[2][4];
#pragma unroll
                for (int mi = 0; mi < 2; ++mi) {
                    int arow = wm * 32 + mi * 16 + lrow;
                    ldsm_x4(ah[mi][0], ah[mi][1], ah[mi][2], ah[mi][3],
                            sbase + NX_HI + (uint32_t)(arow * 136 + kb + acolh) * 2);
                    ldsm_x4(al[mi][0], al[mi][1], al[mi][2], al[mi][3],
                            sbase + NX_LO + (uint32_t)(arow * 136 + kb + acolh) * 2);
                }
#pragma unroll
                for (int nb = 0; nb < 2; ++nb) {
                    int brow = wn * 32 + nb * 16 + brlo;
                    uint32_t bh[4], bl[4];
                    ldsm_x4(bh[0], bh[1], bh[2], bh[3],
                            sbase + NW_HI + (uint32_t)(brow * 136 + kb + bcolh) * 2);
                    ldsm_x4(bl[0], bl[1], bl[2], bl[3],
                            sbase + NW_LO + (uint32_t)(brow * 136 + kb + bcolh) * 2);
#pragma unroll
                    for (int mi = 0; mi < 2; ++mi) {
                        mma16816(c[mi][nb * 2],     ah[mi], bh);
                        mma16816(c[mi][nb * 2],     ah[mi], bl);
                        mma16816(c[mi][nb * 2],     al[mi], bh);
                        mma16816(c[mi][nb * 2 + 1], ah[mi], bh + 2);
                        mma16816(c[mi][nb * 2 + 1], ah[mi], bl + 2);
                        mma16816(c[mi][nb * 2 + 1], al[mi], bh + 2);
                    }
                }
            }
        }

        __syncthreads();
#pragma unroll
        for (int mi = 0; mi < 2; ++mi) {
            int row0 = wm * 32 + mi * 16;
#pragma unroll
            for (int nt = 0; nt < 4; ++nt) {
                int col = wn * 32 + nt * 8 + lc;
                *(float2*)&R[(row0 + lr) * 132 + col]     = make_float2(c[mi][nt][0], c[mi][nt][1]);
                *(float2*)&R[(row0 + 8 + lr) * 132 + col] = make_float2(c[mi][nt][2], c[mi][nt][3]);
            }
        }
        __syncthreads();
    }

    // ================= phase 2: LN epilogue -> A tiles; load full B ===============
    {
        int tx = tid & 15, ty = tid >> 4;
        float a[4][8];
#pragma unroll
        for (int r = 0; r < 4; ++r) {
            int row = ty * 4 + r;
            float4 a0 = *(float4*)&R[row * 132 + tx * 8];
            float4 a1 = *(float4*)&R[row * 132 + tx * 8 + 4];
            a[r][0] = a0.x; a[r][1] = a0.y; a[r][2] = a0.z; a[r][3] = a0.w;
            a[r][4] = a1.x; a[r][5] = a1.y; a[r][6] = a1.z; a[r][7] = a1.w;
        }
        __syncthreads();   // R reads done before A-tile writes

        // load full Wpq B tiles (non-conflicting region) while doing LN
        {
            const uint4* gh = (const uint4*)g_Wpq_hi;
            const uint4* gl = (const uint4*)g_Wpq_lo;
#pragma unroll
            for (int it = 0; it < 8; ++it) {
                int idx = tid + it * 512;
                int f = idx >> 4, q = idx & 15;
                *(uint4*)(sma + NB_HI + f * 272 + q * 16) = gh[f * 16 + q];
                *(uint4*)(sma + NB_LO + f * 272 + q * 16) = gl[f * 16 + q];
            }
        }

        float bb[8], gg[8], be[8];
#pragma unroll
        for (int cc = 0; cc < 8; ++cc) {
            int f = tx * 8 + cc;
            bb[cc] = ntm_b[f]; gg[cc] = norm_g[f]; be[cc] = norm_b[f];
        }
#pragma unroll
        for (int r = 0; r < 4; ++r) {
            int row = ty * 4 + r;
#pragma unroll
            for (int cc = 0; cc < 8; ++cc) a[r][cc] += bb[cc];

            float s = 0.f;
#pragma unroll
            for (int cc = 0; cc < 8; ++cc) s += a[r][cc];
#pragma unroll
            for (int m = 1; m < 16; m <<= 1) s += __shfl_xor_sync(0xffffffffu, s, m);
            float mu = s * (1.f / FF);
            float v = 0.f;
#pragma unroll
            for (int cc = 0; cc < 8; ++cc) { float d = a[r][cc] - mu; v += d * d; }
#pragma unroll
            for (int m = 1; m < 16; m <<= 1) v += __shfl_xor_sync(0xffffffffu, v, m);
            float inv = rsqrtf(v * (1.f / FF) + 1e-5f);

            float o[8];
#pragma unroll
            for (int cc = 0; cc < 8; ++cc) o[cc] = (a[r][cc] - mu) * inv * gg[cc] + be[cc];
            uint32_t hw[4], lw[4];
            split8(o, hw, lw);
            *(uint4*)(sma + NA_HI + row * 272 + tx * 16) = make_uint4(hw[0], hw[1], hw[2], hw[3]);
            *(uint4*)(sma + NA_LO + row * 272 + tx * 16) = make_uint4(lw[0], lw[1], lw[2], lw[3]);
        }
    }
    __syncthreads();

    // ================= phase 3: PQ = xf @ Wpq^T (both halves, no syncs) ===========
    for (int nh = 0; nh < 2; ++nh) {
        float c[2][4][4];
#pragma unroll
        for (int mi = 0; mi < 2; ++mi)
#pragma unroll
            for (int nt = 0; nt < 4; ++nt)
#pragma unroll
                for (int q = 0; q < 4; ++q) c[mi][nt][q] = 0.f;

#pragma unroll
        for (int kb = 0; kb < 128; kb += 16) {
            uint32_t ah[2][4], al[2][4];
#pragma unroll
            for (int mi = 0; mi < 2; ++mi) {
                int arow = wm * 32 + mi * 16 + lrow;
                ldsm_x4(ah[mi][0], ah[mi][1], ah[mi][2], ah[mi][3],
                        sbase + NA_HI + (uint32_t)(arow * 136 + kb + acolh) * 2);
                ldsm_x4(al[mi][0], al[mi][1], al[mi][2], al[mi][3],
                        sbase + NA_LO + (uint32_t)(arow * 136 + kb + acolh) * 2);
            }
#pragma unroll
            for (int nb = 0; nb < 2; ++nb) {
                int brow = nh * 128 + wn * 32 + nb * 16 + brlo;
                uint32_t bh[4], bl[4];
                ldsm_x4(bh[0], bh[1], bh[2], bh[3],
                        sbase + NB_HI + (uint32_t)(brow * 136 + kb + bcolh) * 2);
                ldsm_x4(bl[0], bl[1], bl[2], bl[3],
                        sbase + NB_LO + (uint32_t)(brow * 136 + kb + bcolh) * 2);
#pragma unroll
                for (int mi = 0; mi < 2; ++mi) {
                    mma16816(c[mi][nb * 2],     ah[mi], bh);
                    mma16816(c[mi][nb * 2],     ah[mi], bl);
                    mma16816(c[mi][nb * 2],     al[mi], bh);
                    mma16816(c[mi][nb * 2 + 1], ah[mi], bh + 2);
                    mma16816(c[mi][nb * 2 + 1], ah[mi], bl + 2);
                    mma16816(c[mi][nb * 2 + 1], al[mi], bh + 2);
                }
            }
        }
#pragma unroll
        for (int mi = 0; mi < 2; ++mi) {
            int row0 = n0 + wm * 32 + mi * 16;
#pragma unroll
            for (int nt = 0; nt < 4; ++nt) {
                int col = nh * 128 + wn * 32 + nt * 8 + lc;
                if (row0 + lr < NN)
                    *(float2*)&g_PQ[(row0 + lr) * 256 + col] = make_float2(c[mi][nt][0], c[mi][nt][1]);
                if (row0 + 8 + lr < NN)
                    *(float2*)&g_PQ[(row0 + 8 + lr) * 256 + col] = make_float2(c[mi][nt][2], c[mi][nt][3]);
            }
        }
    }
}

// ---------------- edge kernel: 256 thr / 64 edges / 3 CTAs per SM -----------------
#define EO_R    0
#define EO_AHI  33792
#define EO_ALO  38912
#define EO_BHI  44032
#define EO_BLO  54272
#define EO_II   64512
#define EO_JJ   64768
#define E_SMEM  65024

__global__ __launch_bounds__(256, 3)
void edge_kernel(const float* __restrict__ rbf, const int* __restrict__ edge_index,
                 const float* __restrict__ ln_g, const float* __restrict__ ln_b) {
    extern __shared__ char sma[];
    uint32_t sbase = smem_u32(sma);
    float* R = (float*)(sma + EO_R);
    int* ii_s = (int*)(sma + EO_II);
    int* jj_s = (int*)(sma + EO_JJ);

    int tid = threadIdx.x;
    int wid = tid >> 5, lane = tid & 31;
    int tx = tid & 15, ty = tid >> 4;
    int e0 = blockIdx.x * 64;

    if (tid < 64) ii_s[tid] = edge_index[e0 + tid];
    else if (tid < 128) jj_s[tid - 64] = edge_index[EE + e0 + (tid - 64)];

    {
        int e = tid >> 2, ks = (tid & 3) * 8;
        const float4* rbf4 = (const float4*)rbf;
        float4 v0 = rbf4[(e0 + e) * 8 + (tid & 3) * 2];
        float4 v1 = rbf4[(e0 + e) * 8 + (tid & 3) * 2 + 1];
        float vv[8] = {v0.x, v0.y, v0.z, v0.w, v1.x, v1.y, v1.z, v1.w};
        uint32_t hw[4], lw[4];
        split8(vv, hw, lw);
        *(uint4*)(sma + EO_AHI + e * 80 + ks * 2) = make_uint4(hw[0], hw[1], hw[2], hw[3]);
        *(uint4*)(sma + EO_ALO + e * 80 + ks * 2) = make_uint4(lw[0], lw[1], lw[2], lw[3]);
    }
    {
        const uint4* gh = (const uint4*)g_Wrt_hi;
        const uint4* gl = (const uint4*)g_Wrt_lo;
        for (int idx = tid; idx < 512; idx += 256) {
            int f = idx >> 2, q = idx & 3;
            *(uint4*)(sma + EO_BHI + f * 80 + q * 16) = gh[idx];
            *(uint4*)(sma + EO_BLO + f * 80 + q * 16) = gl[idx];
        }
    }
    __syncthreads();

    if (tid < 64) atomicAdd(&g_deg[jj_s[tid]], 1.0f);

    {
        int mrow0 = (wid >> 1) * 16;
        int nhalf = (wid & 1) * 64;
        float c[8][4];
#pragma unroll
        for (int nt = 0; nt < 8; ++nt)
#pragma unroll
            for (int q = 0; q < 4; ++q) c[nt][q] = 0.f;

        int arow = mrow0 + (lane & 15);
        int acolh = (lane >> 4) * 8;
        int brlo = ((lane & 7) | ((lane & 16) >> 1));
        int bcolh = ((lane >> 3) & 1) * 8;

#pragma unroll
        for (int kb = 0; kb < 32; kb += 16) {
            uint32_t ah[4], al[4];
            ldsm_x4(ah[0], ah[1], ah[2], ah[3],
                    sbase + EO_AHI + (uint32_t)(arow * 40 + kb + acolh) * 2);
            ldsm_x4(al[0], al[1], al[2], al[3],
                    sbase + EO_ALO + (uint32_t)(arow * 40 + kb + acolh) * 2);
#pragma unroll
            for (int nb = 0; nb < 4; ++nb) {
                int brow = nhalf + nb * 16 + brlo;
                uint32_t bh[4], bl[4];
                ldsm_x4(bh[0], bh[1], bh[2], bh[3],
                        sbase + EO_BHI + (uint32_t)(brow * 40 + kb + bcolh) * 2);
                ldsm_x4(bl[0], bl[1], bl[2], bl[3],
                        sbase + EO_BLO + (uint32_t)(brow * 40 + kb + bcolh) * 2);
                mma16816(c[nb * 2],     ah, bh);
                mma16816(c[nb * 2],     ah, bl);
                mma16816(c[nb * 2],     al, bh);
                mma16816(c[nb * 2 + 1], ah, bh + 2);
                mma16816(c[nb * 2 + 1], ah, bl + 2);
                mma16816(c[nb * 2 + 1], al, bh + 2);
            }
        }
        int lr = lane >> 2, lc = (lane & 3) * 2;
#pragma unroll
        for (int nt = 0; nt < 8; ++nt) {
            int col = nhalf + nt * 8 + lc;
            *(float2*)&R[(mrow0 + lr) * 132 + col]     = make_float2(c[nt][0], c[nt][1]);
            *(float2*)&R[(mrow0 + 8 + lr) * 132 + col] = make_float2(c[nt][2], c[nt][3]);
        }
    }

    float b1r[8], lg[8], lb[8];
#pragma unroll
    for (int c = 0; c < 8; ++c) {
        int f = tx * 8 + c;
        b1r[c] = g_b1f[f]; lg[c] = ln_g[f]; lb[c] = ln_b[f];
    }
    __syncthreads();

    const float4* pq4 = (const float4*)g_PQ;
#pragma unroll
    for (int r = 0; r < 4; ++r) {
        int e = ty * 4 + r;
        int i = ii_s[e], j = jj_s[e];
        float4 r0 = *(float4*)&R[e * 132 + tx * 8];
        float4 r1 = *(float4*)&R[e * 132 + tx * 8 + 4];
        float4 p0 = pq4[i * 64 + tx * 2];
        float4 p1 = pq4[i * 64 + tx * 2 + 1];
        float4 q0 = pq4[j * 64 + 32 + tx * 2];
        float4 q1 = pq4[j * 64 + 32 + tx * 2 + 1];
        float acc[8];
        acc[0] = b1r[0] + r0.x + p0.x + q0.x; acc[1] = b1r[1] + r0.y + p0.y + q0.y;
        acc[2] = b1r[2] + r0.z + p0.z + q0.z; acc[3] = b1r[3] + r0.w + p0.w + q0.w;
        acc[4] = b1r[4] + r1.x + p1.x + q1.x; acc[5] = b1r[5] + r1.y + p1.y + q1.y;
        acc[6] = b1r[6] + r1.z + p1.z + q1.z; acc[7] = b1r[7] + r1.w + p1.w + q1.w;

        float s = 0.f;
#pragma unroll
        for (int c = 0; c < 8; ++c) s += acc[c];
#pragma unroll
        for (int m = 1; m < 16; m <<= 1) s += __shfl_xor_sync(0xffffffffu, s, m);
        float mu = s * (1.f / FF);
        float v = 0.f;
#pragma unroll
        for (int c = 0; c < 8; ++c) { float d = acc[c] - mu; v += d * d; }
#pragma unroll
        for (int m = 1; m < 16; m <<= 1) v += __shfl_xor_sync(0xffffffffu, v, m);
        float inv = rsqrtf(v * (1.f / FF) + 1e-5f);

        float o[8];
#pragma unroll
        for (int c = 0; c < 8; ++c) {
            float h = (acc[c] - mu) * inv * lg[c] + lb[c];
            o[c] = 0.5f * h * (1.0f + erff(h * 0.70710678118654752f));
        }
        float* dst = &g_G[j * FF + tx * 8];
        atomicAdd((float4*)dst,       make_float4(o[0], o[1], o[2], o[3]));
        atomicAdd((float4*)(dst + 4), make_float4(o[4], o[5], o[6], o[7]));
    }
}

// ---------------- out mma kernel: full-B resident, no inner syncs -----------------
#define OO_AHI 0
#define OO_ALO 34816
#define OO_BHI 69632
#define OO_BLO 139264
#define O_SMEM 208896

__global__ __launch_bounds__(512, 1)
void out_kernel(float* __restrict__ out) {
    extern __shared__ char sma[];
    uint32_t sbase = smem_u32(sma);
    int tid = threadIdx.x;
    int wid = tid >> 5, lane = tid & 31;
    int n0 = blockIdx.x * 128;

    int wm = wid >> 2, wn = wid & 3;
    int lrow = lane & 15, acolh = (lane >> 4) * 8;
    int brlo = (lane & 7) | ((lane & 16) >> 1), bcolh = ((lane >> 3) & 1) * 8;
    int lr = lane >> 2, lc = (lane & 3) * 2;

    // A: G tile fp32 -> bf16 hi/lo; B: full Mo
    {
        const float4* g4 = (const float4*)g_G;
#pragma unroll
        for (int it = 0; it < 4; ++it) {
            int idx = tid + it * 512;
            int nl = idx >> 4, q = idx & 15;
            int n = n0 + nl;
            float4 v0 = make_float4(0.f, 0.f, 0.f, 0.f), v1 = v0;
            if (n < NN) {
                v0 = g4[n * 32 + q * 2];
                v1 = g4[n * 32 + q * 2 + 1];
            }
            float vv[8] = {v0.x, v0.y, v0.z, v0.w, v1.x, v1.y, v1.z, v1.w};
            uint32_t hw[4], lw[4];
            split8(vv, hw, lw);
            *(uint4*)(sma + OO_AHI + nl * 272 + q * 16) = make_uint4(hw[0], hw[1], hw[2], hw[3]);
            *(uint4*)(sma + OO_ALO + nl * 272 + q * 16) = make_uint4(lw[0], lw[1], lw[2], lw[3]);
        }
        const uint4* gh = (const uint4*)g_Mo_hi;
        const uint4* gl = (const uint4*)g_Mo_lo;
#pragma unroll
        for (int it = 0; it < 8; ++it) {
            int idx = tid + it * 512;
            int f = idx >> 4, q = idx & 15;
            *(uint4*)(sma + OO_BHI + f * 272 + q * 16) = gh[f * 16 + q];
            *(uint4*)(sma + OO_BLO + f * 272 + q * 16) = gl[f * 16 + q];
        }
    }
    __syncthreads();

    for (int nh = 0; nh < 2; ++nh) {
        float c[2][4][4];
#pragma unroll
        for (int mi = 0; mi < 2; ++mi)
#pragma unroll
            for (int nt = 0; nt < 4; ++nt)
#pragma unroll
                for (int q = 0; q < 4; ++q) c[mi][nt][q] = 0.f;

#pragma unroll
        for (int kb = 0; kb < 128; kb += 16) {
            uint32_t ah[2][4], al[2][4];
#pragma unroll
            for (int mi = 0; mi < 2; ++mi) {
                int arow = wm * 32 + mi * 16 + lrow;
                ldsm_x4(ah[mi][0], ah[mi][1], ah[mi][2], ah[mi][3],
                        sbase + OO_AHI + (uint32_t)(arow * 136 + kb + acolh) * 2);
                ldsm_x4(al[mi][0], al[mi][1], al[mi][2], al[mi][3],
                        sbase + OO_ALO + (uint32_t)(arow * 136 + kb + acolh) * 2);
            }
#pragma unroll
            for (int nb = 0; nb < 2; ++nb) {
                int brow = nh * 128 + wn * 32 + nb * 16 + brlo;
                uint32_t bh[4], bl[4];
                ldsm_x4(bh[0], bh[1], bh[2], bh[3],
                        sbase + OO_BHI + (uint32_t)(brow * 136 + kb + bcolh) * 2);
                ldsm_x4(bl[0], bl[1], bl[2], bl[3],
                        sbase + OO_BLO + (uint32_t)(brow * 136 + kb + bcolh) * 2);
#pragma unroll
                for (int mi = 0; mi < 2; ++mi) {
                    mma16816(c[mi][nb * 2],     ah[mi], bh);
                    mma16816(c[mi][nb * 2],     ah[mi], bl);
                    mma16816(c[mi][nb * 2],     al[mi], bh);
                    mma16816(c[mi][nb * 2 + 1], ah[mi], bh + 2);
                    mma16816(c[mi][nb * 2 + 1], ah[mi], bl + 2);
                    mma16816(c[mi][nb * 2 + 1], al[mi], bh + 2);
                }
            }
        }
#pragma unroll
        for (int mi = 0; mi < 2; ++mi) {
            int row0 = n0 + wm * 32 + mi * 16;
            int n1 = row0 + lr, n2 = row0 + 8 + lr;
            float d1 = (n1 < NN) ? g_deg[n1] : 0.f;
            float d2 = (n2 < NN) ? g_deg[n2] : 0.f;
#pragma unroll
            for (int nt = 0; nt < 4; ++nt) {
                int col = nh * 128 + wn * 32 + nt * 8 + lc;
                float2 bv = *(float2*)&g_bm[col];
                if (n1 < NN)
                    *(float2*)&out[n1 * HH + col] = make_float2(c[mi][nt][0] + d1 * bv.x,
                                                                c[mi][nt][1] + d1 * bv.y);
                if (n2 < NN)
                    *(float2*)&out[n2 * HH + col] = make_float2(c[mi][nt][2] + d2 * bv.x,
                                                                c[mi][nt][3] + d2 * bv.y);
            }
        }
    }
}

// ---------------- launch ----------------
extern "C" void kernel_launch(void* const* d_in, const int* in_sizes, int n_in,
                              void* d_out, int out_size) {
    const float* x      = (const float*)d_in[0];
    const float* rbf    = (const float*)d_in[1];
    const int*   eidx   = (const int*)d_in[2];
    const float* ntm_w  = (const float*)d_in[3];
    const float* ntm_b  = (const float*)d_in[4];
    const float* rtm_w  = (const float*)d_in[5];
    const float* rtm_b  = (const float*)d_in[6];
    const float* norm_g = (const float*)d_in[7];
    const float* norm_b = (const float*)d_in[8];
    const float* l1_w   = (const float*)d_in[9];
    const float* l1_b   = (const float*)d_in[10];
    const float* ln_g   = (const float*)d_in[11];
    const float* ln_b   = (const float*)d_in[12];
    const float* l2_w   = (const float*)d_in[13];
    const float* l2_b   = (const float*)d_in[14];
    const float* mtn_w  = (const float*)d_in[15];
    float* out = (float*)d_out;

    cudaFuncSetAttribute(node_kernel, cudaFuncAttributeMaxDynamicSharedMemorySize, N_SMEM);
    cudaFuncSetAttribute(edge_kernel, cudaFuncAttributeMaxDynamicSharedMemorySize, E_SMEM);
    cudaFuncSetAttribute(out_kernel,  cudaFuncAttributeMaxDynamicSharedMemorySize, O_SMEM);

    zero_kernel<<<2048, 256>>>();
    prep_kernel<<<FF, 128>>>(l1_w, l1_b, rtm_w, rtm_b, ntm_w);
    prep2_kernel<<<HH, 128>>>(mtn_w, l2_w, l2_b);
    node_kernel<<<(NN + 127) / 128, 512, N_SMEM>>>(x, ntm_b, norm_g, norm_b);
    edge_kernel<<<EE / 64, 256, E_SMEM>>>(rbf, eidx, ln_g, ln_b);
    out_kernel<<<(NN + 127) / 128, 512, O_SMEM>>>(out);
}